// round 5
// baseline (speedup 1.0000x reference)
#include <cuda_runtime.h>
#include <cstdint>
#include <math.h>

#define BATCH  2
#define TSEQ   2048
#define BT     (BATCH*TSEQ)   // 4096
#define DMODEL 1024
#define NHEAD  16
#define DHEAD  64
#define VOCAB  32000

typedef unsigned long long u64;

// ---------------- scratch (device globals; referenced ONLY from device code) ----
__device__ __align__(16) int   g_cnt[VOCAB];
__device__ __align__(16) float g_m[3][DMODEL];   // 0: r-mix, 1: k-mix, 2: v-mix
__device__ __align__(16) float g_r[BT*DMODEL];
__device__ __align__(16) float g_k[BT*DMODEL];
__device__ __align__(16) float g_v[BT*DMODEL];
__device__ __align__(16) float g_o[BT*DMODEL];

// ---------------- packed f32x2 helpers (validated on this target in R4) --------
#define FMA2(d, a, b, c) asm("fma.rn.f32x2 %0, %1, %2, %3;" : "=l"(d) : "l"(a), "l"(b), "l"(c))
#define MUL2(d, a, b)    asm("mul.rn.f32x2 %0, %1, %2;"     : "=l"(d) : "l"(a), "l"(b))
#define ADD2(d, a, b)    asm("add.rn.f32x2 %0, %1, %2;"     : "=l"(d) : "l"(a), "l"(b))
#define DUP2(d, s)       asm("mov.b64 %0, {%1, %1};"        : "=l"(d) : "r"(__float_as_uint(s)))

// ---------------- kWTA: histogram + top-5 + gains ----------------
__global__ void zero_cnt_kernel() {
    int i = blockIdx.x * blockDim.x + threadIdx.x;
    if (i < VOCAB) g_cnt[i] = 0;
}
__global__ void hist_kernel(const int* __restrict__ tok) {
    int i = blockIdx.x * blockDim.x + threadIdx.x;
    atomicAdd(&g_cnt[tok[i]], 1);
}
__global__ void topk_gains_kernel(const float* __restrict__ tmr,
                                  const float* __restrict__ tmk,
                                  const float* __restrict__ tmv) {
    __shared__ long long skey[256];
    __shared__ int sel[5];
    int tid = threadIdx.x;
    for (int it = 0; it < 5; it++) {
        long long best = -1;
        for (int i = tid; i < VOCAB; i += 256) {
            bool ex = false;
            for (int j = 0; j < it; j++) if (sel[j] == i) ex = true;
            if (ex) continue;
            long long key = (((long long)g_cnt[i]) << 16) | (long long)(VOCAB - 1 - i);
            if (key > best) best = key;
        }
        skey[tid] = best;
        __syncthreads();
        for (int s = 128; s > 0; s >>= 1) {
            if (tid < s && skey[tid + s] > skey[tid]) skey[tid] = skey[tid + s];
            __syncthreads();
        }
        if (tid == 0) sel[it] = VOCAB - 1 - (int)(skey[0] & 0xFFFFLL);
        __syncthreads();
    }
    for (int d = tid; d < DMODEL; d += 256) {
        float g = (g_cnt[d] > 0) ? 0.6f : 1.0f;
        #pragma unroll
        for (int j = 0; j < 5; j++) if (sel[j] == d) g = 1.5f;
        g_m[0][d] = tmr[d] * g;
        g_m[1][d] = tmk[d] * g;
        g_m[2][d] = tmv[d] * g;
    }
}

// ---------------- SIMT fp32 GEMM with packed FFMA2 inner product ---------------
// C[4096,1024] = A @ W^T. CTA 128x128, 256 threads, 8x8 per-thread tile,
// accumulators packed as f32x2 pairs along N. Exact fp32.
// MODE 0/1/2: A = m*x+(1-m)*prev_x -> g_r/g_k/g_v (MODE1 epilogue: spike >0.5)
// MODE 3:     A = sigmoid(g_r)*g_o -> Cout (+bias)
template<int MODE>
__global__ __launch_bounds__(256, 2)
void gemm_f2(const float* __restrict__ X, const float* __restrict__ W,
             const float* __restrict__ bias, float* __restrict__ Cout)
{
    float* C;
    if      (MODE == 0) C = g_r;
    else if (MODE == 1) C = g_k;
    else if (MODE == 2) C = g_v;
    else                C = Cout;

    __shared__ __align__(16) float As[8][128];
    __shared__ __align__(16) float Ws[8][128];
    const int bm = blockIdx.y * 128;
    const int bn = blockIdx.x * 128;
    const int tid = threadIdx.x;
    const int lr  = tid >> 1;           // 0..127 (tile row to load)
    const int lc  = (tid & 1) * 4;      // 0 or 4 (k offset, float4)
    const int tx  = tid & 15;
    const int ty  = tid >> 4;

    u64 acc2[8][4];                      // [m][n-pair] packed f32x2
    #pragma unroll
    for (int i = 0; i < 8; i++)
        #pragma unroll
        for (int j = 0; j < 4; j++) acc2[i][j] = 0ull;

    for (int k0 = 0; k0 < DMODEL; k0 += 8) {
        {
            int t = bm + lr;
            int d = k0 + lc;
            float4 a;
            if (MODE < 3) {
                float4 xv = *(const float4*)(X + (size_t)t * DMODEL + d);
                float4 pv = make_float4(0.f, 0.f, 0.f, 0.f);
                if ((t & (TSEQ - 1)) != 0)
                    pv = *(const float4*)(X + (size_t)(t - 1) * DMODEL + d);
                float4 mv = *(const float4*)(&g_m[MODE][d]);
                a.x = mv.x * xv.x + (1.f - mv.x) * pv.x;
                a.y = mv.y * xv.y + (1.f - mv.y) * pv.y;
                a.z = mv.z * xv.z + (1.f - mv.z) * pv.z;
                a.w = mv.w * xv.w + (1.f - mv.w) * pv.w;
            } else {
                float4 rv = *(const float4*)(g_r + (size_t)t * DMODEL + d);
                float4 ov = *(const float4*)(g_o + (size_t)t * DMODEL + d);
                a.x = ov.x / (1.f + __expf(-rv.x));
                a.y = ov.y / (1.f + __expf(-rv.y));
                a.z = ov.z / (1.f + __expf(-rv.z));
                a.w = ov.w / (1.f + __expf(-rv.w));
            }
            As[lc + 0][lr] = a.x; As[lc + 1][lr] = a.y;
            As[lc + 2][lr] = a.z; As[lc + 3][lr] = a.w;

            float4 w = *(const float4*)(W + (size_t)(bn + lr) * DMODEL + k0 + lc);
            Ws[lc + 0][lr] = w.x; Ws[lc + 1][lr] = w.y;
            Ws[lc + 2][lr] = w.z; Ws[lc + 3][lr] = w.w;
        }
        __syncthreads();
        #pragma unroll
        for (int kk = 0; kk < 8; kk++) {
            float4 a0 = *(const float4*)&As[kk][ty * 8];
            float4 a1 = *(const float4*)&As[kk][ty * 8 + 4];
            ulonglong2 w0 = *(const ulonglong2*)&Ws[kk][tx * 8];      // (n0,n1),(n2,n3)
            ulonglong2 w1 = *(const ulonglong2*)&Ws[kk][tx * 8 + 4];  // (n4,n5),(n6,n7)
            const float ar[8] = {a0.x, a0.y, a0.z, a0.w, a1.x, a1.y, a1.z, a1.w};
            #pragma unroll
            for (int i = 0; i < 8; i++) {
                u64 ad; DUP2(ad, ar[i]);
                FMA2(acc2[i][0], ad, w0.x, acc2[i][0]);
                FMA2(acc2[i][1], ad, w0.y, acc2[i][1]);
                FMA2(acc2[i][2], ad, w1.x, acc2[i][2]);
                FMA2(acc2[i][3], ad, w1.y, acc2[i][3]);
            }
        }
        __syncthreads();
    }
    #pragma unroll
    for (int i = 0; i < 8; i++) {
        const int row = bm + ty * 8 + i;
        const int col = bn + tx * 8;
        float v[8];
        #pragma unroll
        for (int j = 0; j < 4; j++) {
            uint32_t lo, hi;
            asm("mov.b64 {%0, %1}, %2;" : "=r"(lo), "=r"(hi) : "l"(acc2[i][j]));
            v[2 * j]     = __uint_as_float(lo);
            v[2 * j + 1] = __uint_as_float(hi);
        }
        #pragma unroll
        for (int j = 0; j < 8; j++) {
            if (MODE == 1) v[j] = (v[j] > 0.5f) ? 1.f : 0.f;
            if (MODE == 3) v[j] += bias[col + j];
        }
        *(float4*)(C + (size_t)row * DMODEL + col)     = make_float4(v[0], v[1], v[2], v[3]);
        *(float4*)(C + (size_t)row * DMODEL + col + 4) = make_float4(v[4], v[5], v[6], v[7]);
    }
}

// ---------------- non-causal flash attention (packed f32x2 math) ----------------
// grid (T/128, H, B); 128 threads; thread = one query row; online softmax.
#define TK 16
__global__ __launch_bounds__(128)
void attn_kernel()
{
    __shared__ __align__(16) ulonglong2 Ks[TK * 16];   // 16 rows x 64 f32
    __shared__ __align__(16) ulonglong2 Vs[TK * 16];
    const int tid = threadIdx.x;
    const int b = blockIdx.z, h = blockIdx.y;
    const int q = blockIdx.x * 128 + tid;

    const float* qptr = g_r + ((size_t)(b * TSEQ + q) * DMODEL) + h * DHEAD;
    u64 q2[32];
    {
        const ulonglong2* qp = (const ulonglong2*)qptr;
        #pragma unroll
        for (int i = 0; i < 16; i++) { ulonglong2 t = qp[i]; q2[2*i] = t.x; q2[2*i+1] = t.y; }
    }
    u64 ov2[32];
    #pragma unroll
    for (int i = 0; i < 32; i++) ov2[i] = 0ull;
    float mval = -1e30f, l = 0.f;

    for (int kt = 0; kt < TSEQ; kt += TK) {
        #pragma unroll
        for (int e = 0; e < 2; e++) {
            int i  = tid * 2 + e;
            int kk = i >> 4, d4 = i & 15;
            size_t base = (size_t)(b * TSEQ + kt + kk) * DMODEL + h * DHEAD + d4 * 4;
            Ks[i] = *(const ulonglong2*)(g_k + base);
            Vs[i] = *(const ulonglong2*)(g_v + base);
        }
        __syncthreads();

        float s[TK];
        float smax = mval;
        #pragma unroll
        for (int kk = 0; kk < TK; kk++) {
            u64 a0 = 0ull, a1 = 0ull;
            #pragma unroll
            for (int j = 0; j < 16; j++) {
                ulonglong2 kv = Ks[kk * 16 + j];
                FMA2(a0, q2[2*j],     kv.x, a0);
                FMA2(a1, q2[2*j + 1], kv.y, a1);
            }
            ADD2(a0, a0, a1);
            uint32_t lo, hi;
            asm("mov.b64 {%0, %1}, %2;" : "=r"(lo), "=r"(hi) : "l"(a0));
            s[kk] = (__uint_as_float(lo) + __uint_as_float(hi)) * 0.125f;
            smax = fmaxf(smax, s[kk]);
        }
        float corr = __expf(mval - smax);
        l *= corr;
        u64 corr2; DUP2(corr2, corr);
        #pragma unroll
        for (int i = 0; i < 32; i++) MUL2(ov2[i], ov2[i], corr2);
        #pragma unroll
        for (int kk = 0; kk < TK; kk++) {
            float p = __expf(s[kk] - smax);
            l += p;
            u64 p2; DUP2(p2, p);
            #pragma unroll
            for (int j = 0; j < 16; j++) {
                ulonglong2 vv = Vs[kk * 16 + j];
                FMA2(ov2[2*j],     p2, vv.x, ov2[2*j]);
                FMA2(ov2[2*j + 1], p2, vv.y, ov2[2*j + 1]);
            }
        }
        mval = smax;
        __syncthreads();
    }
    float inv = 1.f / l;
    u64 inv2; DUP2(inv2, inv);
    float* optr = g_o + ((size_t)(b * TSEQ + q) * DMODEL) + h * DHEAD;
    #pragma unroll
    for (int j = 0; j < 16; j++) {
        MUL2(ov2[2*j],     ov2[2*j],     inv2);
        MUL2(ov2[2*j + 1], ov2[2*j + 1], inv2);
        ulonglong2 st; st.x = ov2[2*j]; st.y = ov2[2*j + 1];
        *(ulonglong2*)(optr + j * 4) = st;
    }
}

// ---------------- launch (only harness pointers cross the boundary) ----------
extern "C" void kernel_launch(void* const* d_in, const int* in_sizes, int n_in,
                              void* d_out, int out_size)
{
    const float* x   = (const float*)d_in[0];
    const int*   tok = (const int*)  d_in[1];
    const float* Wr  = (const float*)d_in[2];
    const float* Wk  = (const float*)d_in[3];
    const float* Wv  = (const float*)d_in[4];
    const float* Wo  = (const float*)d_in[5];
    const float* bo  = (const float*)d_in[6];
    const float* tmk = (const float*)d_in[7];
    const float* tmv = (const float*)d_in[8];
    const float* tmr = (const float*)d_in[9];
    float* out = (float*)d_out;

    zero_cnt_kernel<<<(VOCAB + 255) / 256, 256>>>();
    hist_kernel<<<BT / 256, 256>>>(tok);
    topk_gains_kernel<<<1, 256>>>(tmr, tmk, tmv);

    dim3 gg(DMODEL / 128, BT / 128);   // (8, 32)
    gemm_f2<0><<<gg, 256>>>(x, Wr, nullptr, nullptr);
    gemm_f2<1><<<gg, 256>>>(x, Wk, nullptr, nullptr);
    gemm_f2<2><<<gg, 256>>>(x, Wv, nullptr, nullptr);

    attn_kernel<<<dim3(TSEQ / 128, NHEAD, BATCH), 128>>>();

    gemm_f2<3><<<gg, 256>>>(nullptr, Wo, bo, out);
}

// round 6
// speedup vs baseline: 1.5666x; 1.5666x over previous
#include <cuda_runtime.h>
#include <cstdint>
#include <math.h>

#define BATCH  2
#define TSEQ   2048
#define BT     (BATCH*TSEQ)   // 4096
#define DMODEL 1024
#define NHEAD  16
#define DHEAD  64
#define VOCAB  32000

typedef unsigned long long u64;

// ---------------- scratch (device globals; referenced ONLY from device code) ----
__device__ __align__(16) int   g_cnt[VOCAB];
__device__ __align__(16) float g_m[3][DMODEL];   // 0: r-mix, 1: k-mix, 2: v-mix
__device__ __align__(16) float g_r[BT*DMODEL];
__device__ __align__(16) float g_k[BT*DMODEL];
__device__ __align__(16) float g_v[BT*DMODEL];
__device__ __align__(16) float g_o[BT*DMODEL];

// ---------------- helpers ----------------
__device__ __forceinline__ uint32_t tf32_hi(float x) {
    uint32_t u;
    asm("cvt.rna.tf32.f32 %0, %1;" : "=r"(u) : "f"(x));
    return u;
}
__device__ __forceinline__ void tf32_split(float x, uint32_t& hi, uint32_t& lo) {
    hi = tf32_hi(x);
    lo = tf32_hi(x - __uint_as_float(hi));
}

#define MMA_TF32(c, a0, a1, a2, a3, b0, b1)                                     \
    asm volatile(                                                               \
        "mma.sync.aligned.m16n8k8.row.col.f32.tf32.tf32.f32 "                   \
        "{%0,%1,%2,%3}, {%4,%5,%6,%7}, {%8,%9}, {%0,%1,%2,%3};"                 \
        : "+f"((c)[0]), "+f"((c)[1]), "+f"((c)[2]), "+f"((c)[3])                \
        : "r"(a0), "r"(a1), "r"(a2), "r"(a3), "r"(b0), "r"(b1))

// ---------------- kWTA: histogram + top-5 + gains ----------------
__global__ void zero_cnt_kernel() {
    int i = blockIdx.x * blockDim.x + threadIdx.x;
    if (i < VOCAB) g_cnt[i] = 0;
}
__global__ void hist_kernel(const int* __restrict__ tok) {
    int i = blockIdx.x * blockDim.x + threadIdx.x;
    atomicAdd(&g_cnt[tok[i]], 1);
}
__global__ void topk_gains_kernel(const float* __restrict__ tmr,
                                  const float* __restrict__ tmk,
                                  const float* __restrict__ tmv) {
    __shared__ long long skey[256];
    __shared__ int sel[5];
    int tid = threadIdx.x;
    for (int it = 0; it < 5; it++) {
        long long best = -1;
        for (int i = tid; i < VOCAB; i += 256) {
            bool ex = false;
            for (int j = 0; j < it; j++) if (sel[j] == i) ex = true;
            if (ex) continue;
            long long key = (((long long)g_cnt[i]) << 16) | (long long)(VOCAB - 1 - i);
            if (key > best) best = key;
        }
        skey[tid] = best;
        __syncthreads();
        for (int s = 128; s > 0; s >>= 1) {
            if (tid < s && skey[tid + s] > skey[tid]) skey[tid] = skey[tid + s];
            __syncthreads();
        }
        if (tid == 0) sel[it] = VOCAB - 1 - (int)(skey[0] & 0xFFFFLL);
        __syncthreads();
    }
    for (int d = tid; d < DMODEL; d += 256) {
        float g = (g_cnt[d] > 0) ? 0.6f : 1.0f;
        #pragma unroll
        for (int j = 0; j < 5; j++) if (sel[j] == d) g = 1.5f;
        g_m[0][d] = tmr[d] * g;
        g_m[1][d] = tmk[d] * g;
        g_m[2][d] = tmv[d] * g;
    }
}

// ---------------- 3xTF32 tensor-core GEMM: C[4096,1024] = A @ W^T ---------------
// CTA 128x128, 8 warps (warp tile 64x32), K chunked by 16. Inputs split into
// tf32 hi+lo; acc += a_lo*w_hi + a_hi*w_lo + a_hi*w_hi  (fp32-accurate).
// MODE 0/1/2: A = m*x+(1-m)*prev_x -> g_r/g_k/g_v (MODE1 epilogue: spike >0.5)
// MODE 3:     A = sigmoid(g_r)*g_o -> Cout (+bias)
#define SROW 20
template<int MODE>
__global__ __launch_bounds__(256)
void gemm_tc3(const float* __restrict__ X, const float* __restrict__ W,
              const float* __restrict__ bias, float* __restrict__ Cout)
{
    float* C;
    if      (MODE == 0) C = g_r;
    else if (MODE == 1) C = g_k;
    else if (MODE == 2) C = g_v;
    else                C = Cout;

    __shared__ __align__(16) uint32_t sAh[128 * SROW];
    __shared__ __align__(16) uint32_t sAl[128 * SROW];
    __shared__ __align__(16) uint32_t sWh[128 * SROW];
    __shared__ __align__(16) uint32_t sWl[128 * SROW];

    const int tid  = threadIdx.x;
    const int wid  = tid >> 5, lane = tid & 31;
    const int wr   = wid & 1,  wc   = wid >> 1;
    const int qrow = lane >> 2, qcol = lane & 3;
    const int bm = blockIdx.y * 128, bn = blockIdx.x * 128;

    const int lr  = tid >> 1;            // 0..127 row to load
    const int lc8 = (tid & 1) * 8;       // 0 or 8 col offset

    float acc[4][4][4];
    #pragma unroll
    for (int mi = 0; mi < 4; mi++)
        #pragma unroll
        for (int ni = 0; ni < 4; ni++)
            #pragma unroll
            for (int e = 0; e < 4; e++) acc[mi][ni][e] = 0.f;

    for (int c = 0; c < 64; c++) {               // K chunks of 16
        const int kc = c * 16 + lc8;
        // ---- fused prologue: 8 A elems + 8 W elems per thread ----
        float a[8], w[8];
        if (MODE < 3) {
            const int t = bm + lr;
            float4 x0 = *(const float4*)(X + (size_t)t * DMODEL + kc);
            float4 x1 = *(const float4*)(X + (size_t)t * DMODEL + kc + 4);
            float4 p0 = make_float4(0.f, 0.f, 0.f, 0.f), p1 = p0;
            if ((t & (TSEQ - 1)) != 0) {
                p0 = *(const float4*)(X + (size_t)(t - 1) * DMODEL + kc);
                p1 = *(const float4*)(X + (size_t)(t - 1) * DMODEL + kc + 4);
            }
            float4 m0 = *(const float4*)(&g_m[MODE][kc]);
            float4 m1 = *(const float4*)(&g_m[MODE][kc + 4]);
            a[0] = m0.x * x0.x + (1.f - m0.x) * p0.x;
            a[1] = m0.y * x0.y + (1.f - m0.y) * p0.y;
            a[2] = m0.z * x0.z + (1.f - m0.z) * p0.z;
            a[3] = m0.w * x0.w + (1.f - m0.w) * p0.w;
            a[4] = m1.x * x1.x + (1.f - m1.x) * p1.x;
            a[5] = m1.y * x1.y + (1.f - m1.y) * p1.y;
            a[6] = m1.z * x1.z + (1.f - m1.z) * p1.z;
            a[7] = m1.w * x1.w + (1.f - m1.w) * p1.w;
        } else {
            const int t = bm + lr;
            float4 r0 = *(const float4*)(g_r + (size_t)t * DMODEL + kc);
            float4 r1 = *(const float4*)(g_r + (size_t)t * DMODEL + kc + 4);
            float4 o0 = *(const float4*)(g_o + (size_t)t * DMODEL + kc);
            float4 o1 = *(const float4*)(g_o + (size_t)t * DMODEL + kc + 4);
            a[0] = o0.x / (1.f + __expf(-r0.x));
            a[1] = o0.y / (1.f + __expf(-r0.y));
            a[2] = o0.z / (1.f + __expf(-r0.z));
            a[3] = o0.w / (1.f + __expf(-r0.w));
            a[4] = o1.x / (1.f + __expf(-r1.x));
            a[5] = o1.y / (1.f + __expf(-r1.y));
            a[6] = o1.z / (1.f + __expf(-r1.z));
            a[7] = o1.w / (1.f + __expf(-r1.w));
        }
        {
            float4 w0 = *(const float4*)(W + (size_t)(bn + lr) * DMODEL + kc);
            float4 w1 = *(const float4*)(W + (size_t)(bn + lr) * DMODEL + kc + 4);
            w[0] = w0.x; w[1] = w0.y; w[2] = w0.z; w[3] = w0.w;
            w[4] = w1.x; w[5] = w1.y; w[6] = w1.z; w[7] = w1.w;
        }
        uint32_t ah[8], al[8], wh[8], wl[8];
        #pragma unroll
        for (int e = 0; e < 8; e++) {
            tf32_split(a[e], ah[e], al[e]);
            tf32_split(w[e], wh[e], wl[e]);
        }
        const int sbase = lr * SROW + lc8;
        *(uint4*)(sAh + sbase)     = make_uint4(ah[0], ah[1], ah[2], ah[3]);
        *(uint4*)(sAh + sbase + 4) = make_uint4(ah[4], ah[5], ah[6], ah[7]);
        *(uint4*)(sAl + sbase)     = make_uint4(al[0], al[1], al[2], al[3]);
        *(uint4*)(sAl + sbase + 4) = make_uint4(al[4], al[5], al[6], al[7]);
        *(uint4*)(sWh + sbase)     = make_uint4(wh[0], wh[1], wh[2], wh[3]);
        *(uint4*)(sWh + sbase + 4) = make_uint4(wh[4], wh[5], wh[6], wh[7]);
        *(uint4*)(sWl + sbase)     = make_uint4(wl[0], wl[1], wl[2], wl[3]);
        *(uint4*)(sWl + sbase + 4) = make_uint4(wl[4], wl[5], wl[6], wl[7]);
        __syncthreads();

        #pragma unroll
        for (int ks = 0; ks < 2; ks++) {
            const int k0 = ks * 8;
            uint32_t afh[4][4], afl[4][4], bfh[4][2], bfl[4][2];
            #pragma unroll
            for (int mi = 0; mi < 4; mi++) {
                const int off = (wr * 64 + mi * 16 + qrow) * SROW + k0 + qcol;
                afh[mi][0] = sAh[off];            afh[mi][1] = sAh[off + 8 * SROW];
                afh[mi][2] = sAh[off + 4];        afh[mi][3] = sAh[off + 8 * SROW + 4];
                afl[mi][0] = sAl[off];            afl[mi][1] = sAl[off + 8 * SROW];
                afl[mi][2] = sAl[off + 4];        afl[mi][3] = sAl[off + 8 * SROW + 4];
            }
            #pragma unroll
            for (int ni = 0; ni < 4; ni++) {
                const int off = (wc * 32 + ni * 8 + qrow) * SROW + k0 + qcol;
                bfh[ni][0] = sWh[off];  bfh[ni][1] = sWh[off + 4];
                bfl[ni][0] = sWl[off];  bfl[ni][1] = sWl[off + 4];
            }
            #pragma unroll
            for (int mi = 0; mi < 4; mi++)
                #pragma unroll
                for (int ni = 0; ni < 4; ni++) {
                    MMA_TF32(acc[mi][ni], afl[mi][0], afl[mi][1], afl[mi][2], afl[mi][3],
                             bfh[ni][0], bfh[ni][1]);
                    MMA_TF32(acc[mi][ni], afh[mi][0], afh[mi][1], afh[mi][2], afh[mi][3],
                             bfl[ni][0], bfl[ni][1]);
                    MMA_TF32(acc[mi][ni], afh[mi][0], afh[mi][1], afh[mi][2], afh[mi][3],
                             bfh[ni][0], bfh[ni][1]);
                }
        }
        __syncthreads();
    }

    #pragma unroll
    for (int mi = 0; mi < 4; mi++) {
        const int row = bm + wr * 64 + mi * 16 + qrow;
        #pragma unroll
        for (int ni = 0; ni < 4; ni++) {
            const int col = bn + wc * 32 + ni * 8 + qcol * 2;
            float d0 = acc[mi][ni][0], d1 = acc[mi][ni][1];
            float d2 = acc[mi][ni][2], d3 = acc[mi][ni][3];
            if (MODE == 1) {
                d0 = (d0 > 0.5f) ? 1.f : 0.f; d1 = (d1 > 0.5f) ? 1.f : 0.f;
                d2 = (d2 > 0.5f) ? 1.f : 0.f; d3 = (d3 > 0.5f) ? 1.f : 0.f;
            }
            if (MODE == 3) {
                float b0 = bias[col], b1 = bias[col + 1];
                d0 += b0; d1 += b1; d2 += b0; d3 += b1;
            }
            *(float2*)(C + (size_t)row * DMODEL + col)       = make_float2(d0, d1);
            *(float2*)(C + (size_t)(row + 8) * DMODEL + col) = make_float2(d2, d3);
        }
    }
}

// ---------------- flash attention on tensor cores -------------------------------
// Block: 256 thr (8 warps), 128 q-rows per block, one (b,h). K/V tiles of 32 keys.
// QK: q split hi/lo (2 MMAs; k binary = exact tf32). PV: 3-term split (3 MMAs).
// Softmax fp32 in C-fragments with quad shuffles; P goes through per-warp smem.
#define ATK  32
#define KVS  68          // K/V smem row stride (floats)
#define PST  34          // P smem row stride (floats)
__global__ __launch_bounds__(256)
void attn_mma()
{
    __shared__ __align__(16) float sK[ATK * KVS];
    __shared__ __align__(16) float sV[ATK * KVS];
    __shared__ __align__(16) float sP[8][16 * PST];

    const int tid = threadIdx.x, warp = tid >> 5, lane = tid & 31;
    const int qr = lane >> 2, qc = lane & 3;
    const int b = blockIdx.z, h = blockIdx.y;
    const int q0 = blockIdx.x * 128;
    const int qb = q0 + warp * 16;       // warp's first q row

    // ---- Q fragments (resident, hi/lo) ----
    uint32_t qh[8][4], ql[8][4];
    {
        const float* Q = g_r + ((size_t)(b * TSEQ + qb) * DMODEL) + h * DHEAD;
        #pragma unroll
        for (int kc = 0; kc < 8; kc++) {
            const int cc = kc * 8 + qc;
            float f0 = Q[(size_t)qr * DMODEL + cc];
            float f1 = Q[(size_t)(qr + 8) * DMODEL + cc];
            float f2 = Q[(size_t)qr * DMODEL + cc + 4];
            float f3 = Q[(size_t)(qr + 8) * DMODEL + cc + 4];
            tf32_split(f0, qh[kc][0], ql[kc][0]);
            tf32_split(f1, qh[kc][1], ql[kc][1]);
            tf32_split(f2, qh[kc][2], ql[kc][2]);
            tf32_split(f3, qh[kc][3], ql[kc][3]);
        }
    }

    float o[8][4];
    #pragma unroll
    for (int nd = 0; nd < 8; nd++)
        #pragma unroll
        for (int e = 0; e < 4; e++) o[nd][e] = 0.f;
    float m0 = -1e30f, m1 = -1e30f, l0 = 0.f, l1 = 0.f;

    for (int kt = 0; kt < TSEQ; kt += ATK) {
        // ---- cooperative K/V tile load (32 keys x 64 d) ----
        #pragma unroll
        for (int e = 0; e < 2; e++) {
            int j = tid * 2 + e;
            int key = j >> 4, dd = (j & 15) * 4;
            size_t gbase = (size_t)(b * TSEQ + kt + key) * DMODEL + h * DHEAD + dd;
            *(float4*)(sK + key * KVS + dd) = *(const float4*)(g_k + gbase);
            *(float4*)(sV + key * KVS + dd) = *(const float4*)(g_v + gbase);
        }
        __syncthreads();

        // ---- S = Q K^T (2 MMAs per chunk; k exact in tf32) ----
        float s[4][4];
        #pragma unroll
        for (int nt = 0; nt < 4; nt++) {
            #pragma unroll
            for (int e = 0; e < 4; e++) s[nt][e] = 0.f;
            #pragma unroll
            for (int kc = 0; kc < 8; kc++) {
                uint32_t b0 = __float_as_uint(sK[(nt * 8 + qr) * KVS + kc * 8 + qc]);
                uint32_t b1 = __float_as_uint(sK[(nt * 8 + qr) * KVS + kc * 8 + qc + 4]);
                MMA_TF32(s[nt], ql[kc][0], ql[kc][1], ql[kc][2], ql[kc][3], b0, b1);
                MMA_TF32(s[nt], qh[kc][0], qh[kc][1], qh[kc][2], qh[kc][3], b0, b1);
            }
            #pragma unroll
            for (int e = 0; e < 4; e++) s[nt][e] *= 0.125f;
        }

        // ---- online softmax (rows qr and qr+8) ----
        float t0 = -1e30f, t1 = -1e30f;
        #pragma unroll
        for (int nt = 0; nt < 4; nt++) {
            t0 = fmaxf(t0, fmaxf(s[nt][0], s[nt][1]));
            t1 = fmaxf(t1, fmaxf(s[nt][2], s[nt][3]));
        }
        t0 = fmaxf(t0, __shfl_xor_sync(0xffffffffu, t0, 1));
        t0 = fmaxf(t0, __shfl_xor_sync(0xffffffffu, t0, 2));
        t1 = fmaxf(t1, __shfl_xor_sync(0xffffffffu, t1, 1));
        t1 = fmaxf(t1, __shfl_xor_sync(0xffffffffu, t1, 2));
        float mn0 = fmaxf(m0, t0), mn1 = fmaxf(m1, t1);
        float corr0 = __expf(m0 - mn0), corr1 = __expf(m1 - mn1);
        float sum0 = 0.f, sum1 = 0.f;
        #pragma unroll
        for (int nt = 0; nt < 4; nt++) {
            s[nt][0] = __expf(s[nt][0] - mn0);
            s[nt][1] = __expf(s[nt][1] - mn0);
            s[nt][2] = __expf(s[nt][2] - mn1);
            s[nt][3] = __expf(s[nt][3] - mn1);
            sum0 += s[nt][0] + s[nt][1];
            sum1 += s[nt][2] + s[nt][3];
        }
        sum0 += __shfl_xor_sync(0xffffffffu, sum0, 1);
        sum0 += __shfl_xor_sync(0xffffffffu, sum0, 2);
        sum1 += __shfl_xor_sync(0xffffffffu, sum1, 1);
        sum1 += __shfl_xor_sync(0xffffffffu, sum1, 2);
        l0 = l0 * corr0 + sum0;
        l1 = l1 * corr1 + sum1;
        m0 = mn0; m1 = mn1;
        #pragma unroll
        for (int nd = 0; nd < 8; nd++) {
            o[nd][0] *= corr0; o[nd][1] *= corr0;
            o[nd][2] *= corr1; o[nd][3] *= corr1;
        }

        // ---- P to per-warp smem (C-frag -> A-frag relayout) ----
        float* Pw = sP[warp];
        #pragma unroll
        for (int nt = 0; nt < 4; nt++) {
            *(float2*)(Pw + qr * PST + nt * 8 + 2 * qc)       = make_float2(s[nt][0], s[nt][1]);
            *(float2*)(Pw + (qr + 8) * PST + nt * 8 + 2 * qc) = make_float2(s[nt][2], s[nt][3]);
        }
        __syncwarp();

        // ---- O += P V (3-term split) ----
        #pragma unroll
        for (int kc = 0; kc < 4; kc++) {
            uint32_t ph[4], pl[4];
            tf32_split(Pw[qr * PST + kc * 8 + qc],           ph[0], pl[0]);
            tf32_split(Pw[(qr + 8) * PST + kc * 8 + qc],     ph[1], pl[1]);
            tf32_split(Pw[qr * PST + kc * 8 + qc + 4],       ph[2], pl[2]);
            tf32_split(Pw[(qr + 8) * PST + kc * 8 + qc + 4], ph[3], pl[3]);
            #pragma unroll
            for (int nd = 0; nd < 8; nd++) {
                uint32_t vh0, vl0, vh1, vl1;
                tf32_split(sV[(kc * 8 + qc) * KVS + nd * 8 + qr],     vh0, vl0);
                tf32_split(sV[(kc * 8 + qc + 4) * KVS + nd * 8 + qr], vh1, vl1);
                MMA_TF32(o[nd], pl[0], pl[1], pl[2], pl[3], vh0, vh1);
                MMA_TF32(o[nd], ph[0], ph[1], ph[2], ph[3], vl0, vl1);
                MMA_TF32(o[nd], ph[0], ph[1], ph[2], ph[3], vh0, vh1);
            }
        }
        __syncthreads();
    }

    // ---- epilogue ----
    const float inv0 = 1.f / l0, inv1 = 1.f / l1;
    float* O = g_o + ((size_t)(b * TSEQ + qb) * DMODEL) + h * DHEAD;
    #pragma unroll
    for (int nd = 0; nd < 8; nd++) {
        const int cc = nd * 8 + 2 * qc;
        *(float2*)(O + (size_t)qr * DMODEL + cc) =
            make_float2(o[nd][0] * inv0, o[nd][1] * inv0);
        *(float2*)(O + (size_t)(qr + 8) * DMODEL + cc) =
            make_float2(o[nd][2] * inv1, o[nd][3] * inv1);
    }
}

// ---------------- launch (only harness pointers cross the boundary) ----------
extern "C" void kernel_launch(void* const* d_in, const int* in_sizes, int n_in,
                              void* d_out, int out_size)
{
    const float* x   = (const float*)d_in[0];
    const int*   tok = (const int*)  d_in[1];
    const float* Wr  = (const float*)d_in[2];
    const float* Wk  = (const float*)d_in[3];
    const float* Wv  = (const float*)d_in[4];
    const float* Wo  = (const float*)d_in[5];
    const float* bo  = (const float*)d_in[6];
    const float* tmk = (const float*)d_in[7];
    const float* tmv = (const float*)d_in[8];
    const float* tmr = (const float*)d_in[9];
    float* out = (float*)d_out;

    zero_cnt_kernel<<<(VOCAB + 255) / 256, 256>>>();
    hist_kernel<<<BT / 256, 256>>>(tok);
    topk_gains_kernel<<<1, 256>>>(tmr, tmk, tmv);

    dim3 gg(DMODEL / 128, BT / 128);   // (8, 32)
    gemm_tc3<0><<<gg, 256>>>(x, Wr, nullptr, nullptr);
    gemm_tc3<1><<<gg, 256>>>(x, Wk, nullptr, nullptr);
    gemm_tc3<2><<<gg, 256>>>(x, Wv, nullptr, nullptr);

    attn_mma<<<dim3(TSEQ / 128, NHEAD, BATCH), 256>>>();

    gemm_tc3<3><<<gg, 256>>>(nullptr, Wo, bo, out);
}

// round 7
// speedup vs baseline: 2.7949x; 1.7841x over previous
#include <cuda_runtime.h>
#include <cuda_bf16.h>
#include <cstdint>
#include <math.h>

#define BATCH  2
#define TSEQ   2048
#define BT     (BATCH*TSEQ)   // 4096
#define DMODEL 1024
#define NHEAD  16
#define DHEAD  64
#define VOCAB  32000

// ---------------- scratch (device globals; referenced ONLY from device code) ----
__device__ __align__(16) int   g_cnt[VOCAB];
__device__ __align__(16) float g_m[3][DMODEL];        // per-mode mix coeffs
__device__ __align__(16) float g_r[BT*DMODEL];        // r (fp32, for sigmoid gate)
__device__ __align__(16) float g_o[BT*DMODEL];        // attention output (fp32)
__device__ __align__(16) __nv_bfloat16 g_ah[BT*DMODEL],     g_al[BT*DMODEL];      // A hi/lo
__device__ __align__(16) __nv_bfloat16 g_wh[DMODEL*DMODEL], g_wl[DMODEL*DMODEL];  // W hi/lo
__device__ __align__(16) __nv_bfloat16 g_qh[BT*DMODEL],     g_ql[BT*DMODEL];      // q hi/lo
__device__ __align__(16) __nv_bfloat16 g_kb[BT*DMODEL];                           // k (binary)
__device__ __align__(16) __nv_bfloat16 g_vh[BATCH*NHEAD*DHEAD*TSEQ];              // V^T hi
__device__ __align__(16) __nv_bfloat16 g_vl[BATCH*NHEAD*DHEAD*TSEQ];              // V^T lo

// ---------------- helpers ----------------
__device__ __forceinline__ void bf_split(float x, __nv_bfloat16& h, __nv_bfloat16& l) {
    h = __float2bfloat16(x);
    l = __float2bfloat16(x - __bfloat162float(h));
}
#define U32(p) (*reinterpret_cast<const uint32_t*>(p))

#define MMA_BF(c, a0, a1, a2, a3, b0, b1)                                       \
    asm volatile(                                                               \
        "mma.sync.aligned.m16n8k16.row.col.f32.bf16.bf16.f32 "                  \
        "{%0,%1,%2,%3}, {%4,%5,%6,%7}, {%8,%9}, {%0,%1,%2,%3};"                 \
        : "+f"((c)[0]), "+f"((c)[1]), "+f"((c)[2]), "+f"((c)[3])                \
        : "r"(a0), "r"(a1), "r"(a2), "r"(a3), "r"(b0), "r"(b1))

// ---------------- kWTA: histogram + top-5 + gains ----------------
__global__ void zero_cnt_kernel() {
    int i = blockIdx.x * blockDim.x + threadIdx.x;
    if (i < VOCAB) g_cnt[i] = 0;
}
__global__ void hist_kernel(const int* __restrict__ tok) {
    int i = blockIdx.x * blockDim.x + threadIdx.x;
    atomicAdd(&g_cnt[tok[i]], 1);
}
__global__ void topk_gains_kernel(const float* __restrict__ tmr,
                                  const float* __restrict__ tmk,
                                  const float* __restrict__ tmv) {
    __shared__ long long skey[256];
    __shared__ int sel[5];
    int tid = threadIdx.x;
    for (int it = 0; it < 5; it++) {
        long long best = -1;
        for (int i = tid; i < VOCAB; i += 256) {
            bool ex = false;
            for (int j = 0; j < it; j++) if (sel[j] == i) ex = true;
            if (ex) continue;
            long long key = (((long long)g_cnt[i]) << 16) | (long long)(VOCAB - 1 - i);
            if (key > best) best = key;
        }
        skey[tid] = best;
        __syncthreads();
        for (int s = 128; s > 0; s >>= 1) {
            if (tid < s && skey[tid + s] > skey[tid]) skey[tid] = skey[tid + s];
            __syncthreads();
        }
        if (tid == 0) sel[it] = VOCAB - 1 - (int)(skey[0] & 0xFFFFLL);
        __syncthreads();
    }
    for (int d = tid; d < DMODEL; d += 256) {
        float g = (g_cnt[d] > 0) ? 0.6f : 1.0f;
        #pragma unroll
        for (int j = 0; j < 5; j++) if (sel[j] == d) g = 1.5f;
        g_m[0][d] = tmr[d] * g;
        g_m[1][d] = tmk[d] * g;
        g_m[2][d] = tmv[d] * g;
    }
}

// ---------------- prep: split W and A into bf16 hi/lo ----------------
__global__ void split_w_kernel(const float* __restrict__ W) {
    int i = blockIdx.x * 256 + threadIdx.x;    // grid covers DMODEL*DMODEL
    __nv_bfloat16 h, l;
    bf_split(W[i], h, l);
    g_wh[i] = h; g_wl[i] = l;
}

// MODE 0/1/2: A = m*x + (1-m)*prev_x ; MODE 3: A = sigmoid(g_r)*g_o
template<int MODE>
__global__ void prep_a_kernel(const float* __restrict__ X) {
    int i = blockIdx.x * 256 + threadIdx.x;    // grid covers BT*DMODEL
    int t = i >> 10, d = i & (DMODEL - 1);
    float a;
    if (MODE < 3) {
        float xv = X[i];
        float pv = ((t & (TSEQ - 1)) != 0) ? X[i - DMODEL] : 0.f;
        float m  = g_m[MODE][d];
        a = m * xv + (1.f - m) * pv;
    } else {
        a = g_o[i] / (1.f + __expf(-g_r[i]));
    }
    __nv_bfloat16 h, l;
    bf_split(a, h, l);
    g_ah[i] = h; g_al[i] = l;
}

// ---------------- bf16 3-term tensor-core GEMM: C = A @ W^T -------------------
// CTA 128x128, 8 warps (warp tile 64x32), K chunk 32 (2 x k16 steps).
// acc += a_lo*w_hi + a_hi*w_lo + a_hi*w_hi (drops l*l ~ 2^-16).
// Epilogues: 0 -> g_r fp32 + g_qh/g_ql ; 1 -> spike -> g_kb ;
//            2 -> g_vh/g_vl (TRANSPOSED [b][h][d][t]) ; 3 -> Cout + bias.
#define SBF 40
template<int MODE>
__global__ __launch_bounds__(256)
void gemm_bf(const float* __restrict__ bias, float* __restrict__ Cout)
{
    __shared__ __align__(16) __nv_bfloat16 sAh[128 * SBF], sAl[128 * SBF];
    __shared__ __align__(16) __nv_bfloat16 sWh[128 * SBF], sWl[128 * SBF];

    const int tid  = threadIdx.x;
    const int wid  = tid >> 5, lane = tid & 31;
    const int wr   = wid & 1,  wc   = wid >> 1;
    const int qrow = lane >> 2, qc = lane & 3;
    const int bm = blockIdx.y * 128, bn = blockIdx.x * 128;
    const int lr = tid >> 1, cg = (tid & 1) * 16;

    float acc[4][4][4];
    #pragma unroll
    for (int mi = 0; mi < 4; mi++)
        #pragma unroll
        for (int ni = 0; ni < 4; ni++)
            #pragma unroll
            for (int e = 0; e < 4; e++) acc[mi][ni][e] = 0.f;

    for (int c = 0; c < 32; c++) {
        const size_t ka = (size_t)(bm + lr) * DMODEL + c * 32 + cg;
        const size_t kw = (size_t)(bn + lr) * DMODEL + c * 32 + cg;
        *(uint4*)(sAh + lr * SBF + cg)     = *(const uint4*)(g_ah + ka);
        *(uint4*)(sAh + lr * SBF + cg + 8) = *(const uint4*)(g_ah + ka + 8);
        *(uint4*)(sAl + lr * SBF + cg)     = *(const uint4*)(g_al + ka);
        *(uint4*)(sAl + lr * SBF + cg + 8) = *(const uint4*)(g_al + ka + 8);
        *(uint4*)(sWh + lr * SBF + cg)     = *(const uint4*)(g_wh + kw);
        *(uint4*)(sWh + lr * SBF + cg + 8) = *(const uint4*)(g_wh + kw + 8);
        *(uint4*)(sWl + lr * SBF + cg)     = *(const uint4*)(g_wl + kw);
        *(uint4*)(sWl + lr * SBF + cg + 8) = *(const uint4*)(g_wl + kw + 8);
        __syncthreads();

        #pragma unroll
        for (int ks = 0; ks < 2; ks++) {
            const int k0 = ks * 16 + 2 * qc;
            uint32_t bh[4][2], bl[4][2];
            #pragma unroll
            for (int ni = 0; ni < 4; ni++) {
                const int off = (wc * 32 + ni * 8 + qrow) * SBF + k0;
                bh[ni][0] = U32(sWh + off); bh[ni][1] = U32(sWh + off + 8);
                bl[ni][0] = U32(sWl + off); bl[ni][1] = U32(sWl + off + 8);
            }
            #pragma unroll
            for (int mi = 0; mi < 4; mi++) {
                const int off = (wr * 64 + mi * 16 + qrow) * SBF + k0;
                uint32_t ah0 = U32(sAh + off),               ah1 = U32(sAh + off + 8 * SBF);
                uint32_t ah2 = U32(sAh + off + 8),           ah3 = U32(sAh + off + 8 * SBF + 8);
                uint32_t al0 = U32(sAl + off),               al1 = U32(sAl + off + 8 * SBF);
                uint32_t al2 = U32(sAl + off + 8),           al3 = U32(sAl + off + 8 * SBF + 8);
                #pragma unroll
                for (int ni = 0; ni < 4; ni++) {
                    MMA_BF(acc[mi][ni], al0, al1, al2, al3, bh[ni][0], bh[ni][1]);
                    MMA_BF(acc[mi][ni], ah0, ah1, ah2, ah3, bl[ni][0], bl[ni][1]);
                    MMA_BF(acc[mi][ni], ah0, ah1, ah2, ah3, bh[ni][0], bh[ni][1]);
                }
            }
        }
        __syncthreads();
    }

    #pragma unroll
    for (int mi = 0; mi < 4; mi++) {
        const int row0 = bm + wr * 64 + mi * 16 + qrow;
        #pragma unroll
        for (int ni = 0; ni < 4; ni++) {
            const int col = bn + wc * 32 + ni * 8 + 2 * qc;
            float d0 = acc[mi][ni][0], d1 = acc[mi][ni][1];
            float d2 = acc[mi][ni][2], d3 = acc[mi][ni][3];
            if (MODE == 0) {
                *(float2*)(g_r + (size_t)row0 * DMODEL + col)       = make_float2(d0, d1);
                *(float2*)(g_r + (size_t)(row0 + 8) * DMODEL + col) = make_float2(d2, d3);
                __nv_bfloat162 hh, ll;
                bf_split(d0, hh.x, ll.x); bf_split(d1, hh.y, ll.y);
                *(__nv_bfloat162*)(g_qh + (size_t)row0 * DMODEL + col) = hh;
                *(__nv_bfloat162*)(g_ql + (size_t)row0 * DMODEL + col) = ll;
                bf_split(d2, hh.x, ll.x); bf_split(d3, hh.y, ll.y);
                *(__nv_bfloat162*)(g_qh + (size_t)(row0 + 8) * DMODEL + col) = hh;
                *(__nv_bfloat162*)(g_ql + (size_t)(row0 + 8) * DMODEL + col) = ll;
            } else if (MODE == 1) {
                __nv_bfloat162 s;
                s.x = __float2bfloat16((d0 > 0.5f) ? 1.f : 0.f);
                s.y = __float2bfloat16((d1 > 0.5f) ? 1.f : 0.f);
                *(__nv_bfloat162*)(g_kb + (size_t)row0 * DMODEL + col) = s;
                s.x = __float2bfloat16((d2 > 0.5f) ? 1.f : 0.f);
                s.y = __float2bfloat16((d3 > 0.5f) ? 1.f : 0.f);
                *(__nv_bfloat162*)(g_kb + (size_t)(row0 + 8) * DMODEL + col) = s;
            } else if (MODE == 2) {
                const int b  = row0 >> 11, tl = row0 & (TSEQ - 1);
                const int hh = col >> 6,  dd = col & (DHEAD - 1);
                const size_t base = ((size_t)(b * NHEAD + hh)) * DHEAD;
                __nv_bfloat16 h, l;
                bf_split(d0, h, l);
                g_vh[(base + dd) * TSEQ + tl] = h;     g_vl[(base + dd) * TSEQ + tl] = l;
                bf_split(d1, h, l);
                g_vh[(base + dd + 1) * TSEQ + tl] = h; g_vl[(base + dd + 1) * TSEQ + tl] = l;
                bf_split(d2, h, l);
                g_vh[(base + dd) * TSEQ + tl + 8] = h;     g_vl[(base + dd) * TSEQ + tl + 8] = l;
                bf_split(d3, h, l);
                g_vh[(base + dd + 1) * TSEQ + tl + 8] = h; g_vl[(base + dd + 1) * TSEQ + tl + 8] = l;
            } else {
                float b0 = bias[col], b1 = bias[col + 1];
                *(float2*)(Cout + (size_t)row0 * DMODEL + col)       = make_float2(d0 + b0, d1 + b1);
                *(float2*)(Cout + (size_t)(row0 + 8) * DMODEL + col) = make_float2(d2 + b0, d3 + b1);
            }
        }
    }
}

// ---------------- flash attention, bf16 tensor cores --------------------------
// 256 thr / 8 warps, 128 q rows per block (16 per warp), one (b,h).
// K tiles of 32 keys. QK: 2 MMAs (q hi/lo; k binary = exact). PV: 3-term.
// Q fragments live in registers (loaded once from gmem bf16 splits).
#define KS 72
#define VS 40
#define PS 40
__global__ __launch_bounds__(256)
void attn_bf()
{
    __shared__ __align__(16) __nv_bfloat16 sKb[32 * KS];
    __shared__ __align__(16) __nv_bfloat16 sVh[64 * VS], sVl[64 * VS];
    __shared__ __align__(16) __nv_bfloat16 sPh[8][16 * PS], sPl[8][16 * PS];

    const int tid = threadIdx.x, warp = tid >> 5, lane = tid & 31;
    const int qr = lane >> 2, qc = lane & 3;
    const int b = blockIdx.z, h = blockIdx.y;
    const int qb = blockIdx.x * 128 + warp * 16;

    // ---- resident Q fragments (hi/lo) ----
    uint32_t qh[4][4], ql[4][4];
    {
        const size_t r0 = (size_t)(b * TSEQ + qb + qr) * DMODEL + h * DHEAD;
        const size_t r1 = r0 + (size_t)8 * DMODEL;
        #pragma unroll
        for (int kc = 0; kc < 4; kc++) {
            const int cc = kc * 16 + 2 * qc;
            qh[kc][0] = U32(g_qh + r0 + cc);     qh[kc][1] = U32(g_qh + r1 + cc);
            qh[kc][2] = U32(g_qh + r0 + cc + 8); qh[kc][3] = U32(g_qh + r1 + cc + 8);
            ql[kc][0] = U32(g_ql + r0 + cc);     ql[kc][1] = U32(g_ql + r1 + cc);
            ql[kc][2] = U32(g_ql + r0 + cc + 8); ql[kc][3] = U32(g_ql + r1 + cc + 8);
        }
    }

    float o[8][4];
    #pragma unroll
    for (int nd = 0; nd < 8; nd++)
        #pragma unroll
        for (int e = 0; e < 4; e++) o[nd][e] = 0.f;
    float m0 = -1e30f, m1 = -1e30f, l0 = 0.f, l1 = 0.f;

    const size_t vbase = ((size_t)(b * NHEAD + h)) * DHEAD * TSEQ;

    for (int kt = 0; kt < TSEQ; kt += 32) {
        // ---- stage K (32 keys x 64 d) and V^T (64 d x 32 keys, hi+lo) ----
        {
            const int key = tid >> 3, dg = (tid & 7) * 8;
            *(uint4*)(sKb + key * KS + dg) =
                *(const uint4*)(g_kb + (size_t)(b * TSEQ + kt + key) * DMODEL + h * DHEAD + dg);
            const int d = tid >> 2, kg = (tid & 3) * 8;
            *(uint4*)(sVh + d * VS + kg) = *(const uint4*)(g_vh + vbase + (size_t)d * TSEQ + kt + kg);
            *(uint4*)(sVl + d * VS + kg) = *(const uint4*)(g_vl + vbase + (size_t)d * TSEQ + kt + kg);
        }
        __syncthreads();

        // ---- S = Q K^T ----
        float s[4][4];
        #pragma unroll
        for (int nt = 0; nt < 4; nt++) {
            #pragma unroll
            for (int e = 0; e < 4; e++) s[nt][e] = 0.f;
            #pragma unroll
            for (int kc = 0; kc < 4; kc++) {
                const int off = (nt * 8 + qr) * KS + kc * 16 + 2 * qc;
                uint32_t b0 = U32(sKb + off), b1 = U32(sKb + off + 8);
                MMA_BF(s[nt], ql[kc][0], ql[kc][1], ql[kc][2], ql[kc][3], b0, b1);
                MMA_BF(s[nt], qh[kc][0], qh[kc][1], qh[kc][2], qh[kc][3], b0, b1);
            }
            #pragma unroll
            for (int e = 0; e < 4; e++) s[nt][e] *= 0.125f;
        }

        // ---- online softmax ----
        float t0 = -1e30f, t1 = -1e30f;
        #pragma unroll
        for (int nt = 0; nt < 4; nt++) {
            t0 = fmaxf(t0, fmaxf(s[nt][0], s[nt][1]));
            t1 = fmaxf(t1, fmaxf(s[nt][2], s[nt][3]));
        }
        t0 = fmaxf(t0, __shfl_xor_sync(0xffffffffu, t0, 1));
        t0 = fmaxf(t0, __shfl_xor_sync(0xffffffffu, t0, 2));
        t1 = fmaxf(t1, __shfl_xor_sync(0xffffffffu, t1, 1));
        t1 = fmaxf(t1, __shfl_xor_sync(0xffffffffu, t1, 2));
        float mn0 = fmaxf(m0, t0), mn1 = fmaxf(m1, t1);
        float corr0 = __expf(m0 - mn0), corr1 = __expf(m1 - mn1);
        float sum0 = 0.f, sum1 = 0.f;
        #pragma unroll
        for (int nt = 0; nt < 4; nt++) {
            s[nt][0] = __expf(s[nt][0] - mn0);
            s[nt][1] = __expf(s[nt][1] - mn0);
            s[nt][2] = __expf(s[nt][2] - mn1);
            s[nt][3] = __expf(s[nt][3] - mn1);
            sum0 += s[nt][0] + s[nt][1];
            sum1 += s[nt][2] + s[nt][3];
        }
        sum0 += __shfl_xor_sync(0xffffffffu, sum0, 1);
        sum0 += __shfl_xor_sync(0xffffffffu, sum0, 2);
        sum1 += __shfl_xor_sync(0xffffffffu, sum1, 1);
        sum1 += __shfl_xor_sync(0xffffffffu, sum1, 2);
        l0 = l0 * corr0 + sum0;
        l1 = l1 * corr1 + sum1;
        m0 = mn0; m1 = mn1;
        #pragma unroll
        for (int nd = 0; nd < 8; nd++) {
            o[nd][0] *= corr0; o[nd][1] *= corr0;
            o[nd][2] *= corr1; o[nd][3] *= corr1;
        }

        // ---- P (bf16 hi/lo) -> per-warp smem, packed pairs ----
        __nv_bfloat16* Ph = sPh[warp];
        __nv_bfloat16* Pl = sPl[warp];
        #pragma unroll
        for (int nt = 0; nt < 4; nt++) {
            __nv_bfloat162 hh, ll;
            bf_split(s[nt][0], hh.x, ll.x); bf_split(s[nt][1], hh.y, ll.y);
            *(__nv_bfloat162*)(Ph + qr * PS + nt * 8 + 2 * qc) = hh;
            *(__nv_bfloat162*)(Pl + qr * PS + nt * 8 + 2 * qc) = ll;
            bf_split(s[nt][2], hh.x, ll.x); bf_split(s[nt][3], hh.y, ll.y);
            *(__nv_bfloat162*)(Ph + (qr + 8) * PS + nt * 8 + 2 * qc) = hh;
            *(__nv_bfloat162*)(Pl + (qr + 8) * PS + nt * 8 + 2 * qc) = ll;
        }
        __syncwarp();

        // ---- O += P V (3-term) ----
        #pragma unroll
        for (int kc = 0; kc < 2; kc++) {
            const int k0 = kc * 16 + 2 * qc;
            uint32_t ah0 = U32(Ph + qr * PS + k0),       ah1 = U32(Ph + (qr + 8) * PS + k0);
            uint32_t ah2 = U32(Ph + qr * PS + k0 + 8),   ah3 = U32(Ph + (qr + 8) * PS + k0 + 8);
            uint32_t al0 = U32(Pl + qr * PS + k0),       al1 = U32(Pl + (qr + 8) * PS + k0);
            uint32_t al2 = U32(Pl + qr * PS + k0 + 8),   al3 = U32(Pl + (qr + 8) * PS + k0 + 8);
            #pragma unroll
            for (int nd = 0; nd < 8; nd++) {
                const int off = (nd * 8 + qr) * VS + k0;
                uint32_t bh0 = U32(sVh + off), bh1 = U32(sVh + off + 8);
                uint32_t bl0 = U32(sVl + off), bl1 = U32(sVl + off + 8);
                MMA_BF(o[nd], al0, al1, al2, al3, bh0, bh1);
                MMA_BF(o[nd], ah0, ah1, ah2, ah3, bl0, bl1);
                MMA_BF(o[nd], ah0, ah1, ah2, ah3, bh0, bh1);
            }
        }
        __syncthreads();
    }

    // ---- epilogue ----
    const float inv0 = 1.f / l0, inv1 = 1.f / l1;
    float* O = g_o + ((size_t)(b * TSEQ + qb) * DMODEL) + h * DHEAD;
    #pragma unroll
    for (int nd = 0; nd < 8; nd++) {
        const int cc = nd * 8 + 2 * qc;
        *(float2*)(O + (size_t)qr * DMODEL + cc) =
            make_float2(o[nd][0] * inv0, o[nd][1] * inv0);
        *(float2*)(O + (size_t)(qr + 8) * DMODEL + cc) =
            make_float2(o[nd][2] * inv1, o[nd][3] * inv1);
    }
}

// ---------------- launch (only harness pointers cross the boundary) ----------
extern "C" void kernel_launch(void* const* d_in, const int* in_sizes, int n_in,
                              void* d_out, int out_size)
{
    const float* x   = (const float*)d_in[0];
    const int*   tok = (const int*)  d_in[1];
    const float* Wr  = (const float*)d_in[2];
    const float* Wk  = (const float*)d_in[3];
    const float* Wv  = (const float*)d_in[4];
    const float* Wo  = (const float*)d_in[5];
    const float* bo  = (const float*)d_in[6];
    const float* tmk = (const float*)d_in[7];
    const float* tmv = (const float*)d_in[8];
    const float* tmr = (const float*)d_in[9];
    float* out = (float*)d_out;

    zero_cnt_kernel<<<(VOCAB + 255) / 256, 256>>>();
    hist_kernel<<<BT / 256, 256>>>(tok);
    topk_gains_kernel<<<1, 256>>>(tmr, tmk, tmv);

    const int GW = (DMODEL * DMODEL) / 256;   // split_w grid
    const int GA = (BT * DMODEL) / 256;       // prep_a grid
    dim3 gg(DMODEL / 128, BT / 128);          // (8, 32)

    split_w_kernel<<<GW, 256>>>(Wr);
    prep_a_kernel<0><<<GA, 256>>>(x);
    gemm_bf<0><<<gg, 256>>>(nullptr, nullptr);

    split_w_kernel<<<GW, 256>>>(Wk);
    prep_a_kernel<1><<<GA, 256>>>(x);
    gemm_bf<1><<<gg, 256>>>(nullptr, nullptr);

    split_w_kernel<<<GW, 256>>>(Wv);
    prep_a_kernel<2><<<GA, 256>>>(x);
    gemm_bf<2><<<gg, 256>>>(nullptr, nullptr);

    attn_bf<<<dim3(TSEQ / 128, NHEAD, BATCH), 256>>>();

    split_w_kernel<<<GW, 256>>>(Wo);
    prep_a_kernel<3><<<GA, 256>>>(nullptr);
    gemm_bf<3><<<gg, 256>>>(bo, out);
}

// round 8
// speedup vs baseline: 3.0071x; 1.0759x over previous
#include <cuda_runtime.h>
#include <cuda_bf16.h>
#include <cstdint>
#include <math.h>

#define BATCH  2
#define TSEQ   2048
#define BT     (BATCH*TSEQ)   // 4096
#define DMODEL 1024
#define NHEAD  16
#define DHEAD  64
#define VOCAB  32000

// ---------------- scratch (device globals; referenced ONLY from device code) ----
__device__ __align__(16) int   g_cnt[VOCAB];
__device__ __align__(16) float g_m[3][DMODEL];
__device__ __align__(16) float g_r[BT*DMODEL];
__device__ __align__(16) float g_o[BT*DMODEL];
__device__ __align__(16) __nv_bfloat16 g_ah[3][BT*DMODEL], g_al[3][BT*DMODEL];        // A hi/lo (mode3 reuses [0])
__device__ __align__(16) __nv_bfloat16 g_wh[4][DMODEL*DMODEL], g_wl[4][DMODEL*DMODEL];// W hi/lo
__device__ __align__(16) __nv_bfloat16 g_qh[BT*DMODEL], g_ql[BT*DMODEL];              // q hi/lo
__device__ __align__(16) __nv_bfloat16 g_kb[BT*DMODEL];                               // k (binary)
__device__ __align__(16) __nv_bfloat16 g_vh[BATCH*NHEAD*DHEAD*TSEQ];                  // V^T hi
__device__ __align__(16) __nv_bfloat16 g_vl[BATCH*NHEAD*DHEAD*TSEQ];                  // V^T lo

// ---------------- helpers ----------------
__device__ __forceinline__ void bf_split(float x, __nv_bfloat16& h, __nv_bfloat16& l) {
    h = __float2bfloat16(x);
    l = __float2bfloat16(x - __bfloat162float(h));
}
__device__ __forceinline__ void split2(float x, float y, uint32_t& h, uint32_t& l) {
    __nv_bfloat162 hh, ll;
    hh.x = __float2bfloat16(x); hh.y = __float2bfloat16(y);
    ll.x = __float2bfloat16(x - __bfloat162float(hh.x));
    ll.y = __float2bfloat16(y - __bfloat162float(hh.y));
    h = *(uint32_t*)&hh; l = *(uint32_t*)&ll;
}
__device__ __forceinline__ uint32_t smem_u32(const void* p) {
    uint32_t a;
    asm("{ .reg .u64 t; cvta.to.shared.u64 t, %1; cvt.u32.u64 %0, t; }" : "=r"(a) : "l"(p));
    return a;
}
#define U32(p) (*reinterpret_cast<const uint32_t*>(p))
#define CP16(dst, src) asm volatile("cp.async.cg.shared.global [%0], [%1], 16;" :: "r"(dst), "l"(src))
#define CPCOMMIT()     asm volatile("cp.async.commit_group;")
#define CPWAIT0()      asm volatile("cp.async.wait_group 0;")

#define MMA_BF(c, a0, a1, a2, a3, b0, b1)                                       \
    asm volatile(                                                               \
        "mma.sync.aligned.m16n8k16.row.col.f32.bf16.bf16.f32 "                  \
        "{%0,%1,%2,%3}, {%4,%5,%6,%7}, {%8,%9}, {%0,%1,%2,%3};"                 \
        : "+f"((c)[0]), "+f"((c)[1]), "+f"((c)[2]), "+f"((c)[3])                \
        : "r"(a0), "r"(a1), "r"(a2), "r"(a3), "r"(b0), "r"(b1))

// ---------------- kWTA: histogram + top-5 + gains ----------------
__global__ void zero_cnt_kernel() {
    int i = blockIdx.x * blockDim.x + threadIdx.x;
    if (i < VOCAB) g_cnt[i] = 0;
}
__global__ void hist_kernel(const int* __restrict__ tok) {
    int i = blockIdx.x * blockDim.x + threadIdx.x;
    atomicAdd(&g_cnt[tok[i]], 1);
}
__global__ void topk_gains_kernel(const float* __restrict__ tmr,
                                  const float* __restrict__ tmk,
                                  const float* __restrict__ tmv) {
    __shared__ long long skey[256];
    __shared__ int sel[5];
    int tid = threadIdx.x;
    for (int it = 0; it < 5; it++) {
        long long best = -1;
        for (int i = tid; i < VOCAB; i += 256) {
            bool ex = false;
            for (int j = 0; j < it; j++) if (sel[j] == i) ex = true;
            if (ex) continue;
            long long key = (((long long)g_cnt[i]) << 16) | (long long)(VOCAB - 1 - i);
            if (key > best) best = key;
        }
        skey[tid] = best;
        __syncthreads();
        for (int s = 128; s > 0; s >>= 1) {
            if (tid < s && skey[tid + s] > skey[tid]) skey[tid] = skey[tid + s];
            __syncthreads();
        }
        if (tid == 0) sel[it] = VOCAB - 1 - (int)(skey[0] & 0xFFFFLL);
        __syncthreads();
    }
    for (int d = tid; d < DMODEL; d += 256) {
        float g = (g_cnt[d] > 0) ? 0.6f : 1.0f;
        #pragma unroll
        for (int j = 0; j < 5; j++) if (sel[j] == d) g = 1.5f;
        g_m[0][d] = tmr[d] * g;
        g_m[1][d] = tmk[d] * g;
        g_m[2][d] = tmv[d] * g;
    }
}

// ---------------- prep: all 4 W splits in one pass ----------------
__global__ void split_w_all(const float* __restrict__ W0, const float* __restrict__ W1,
                            const float* __restrict__ W2, const float* __restrict__ W3) {
    int i = blockIdx.x * 256 + threadIdx.x;   // covers DMODEL*DMODEL
    const float* Ws[4] = {W0, W1, W2, W3};
    #pragma unroll
    for (int m = 0; m < 4; m++) {
        __nv_bfloat16 h, l;
        bf_split(Ws[m][i], h, l);
        g_wh[m][i] = h; g_wl[m][i] = l;
    }
}

// ---------------- prep: 3 mixed inputs in one pass (x read once) --------------
__global__ void prep_x012(const float* __restrict__ X) {
    int i = blockIdx.x * 256 + threadIdx.x;   // covers BT*DMODEL
    int t = i >> 10, d = i & (DMODEL - 1);
    float xv = X[i];
    float pv = ((t & (TSEQ - 1)) != 0) ? X[i - DMODEL] : 0.f;
    #pragma unroll
    for (int m = 0; m < 3; m++) {
        float mm = g_m[m][d];
        float a = mm * xv + (1.f - mm) * pv;
        __nv_bfloat16 h, l;
        bf_split(a, h, l);
        g_ah[m][i] = h; g_al[m][i] = l;
    }
}

// ---------------- prep: gated attention output -> A (mode 3, into slot 0) ------
__global__ void prep_a3() {
    int i = blockIdx.x * 256 + threadIdx.x;
    float a = g_o[i] / (1.f + __expf(-g_r[i]));
    __nv_bfloat16 h, l;
    bf_split(a, h, l);
    g_ah[0][i] = h; g_al[0][i] = l;
}

// ---------------- bf16 3-term tensor-core GEMM (modes via blockIdx.z) ----------
// CTA 128x128, 8 warps (warp tile 64x32), K chunk 32 (2 x k16).
// mode = mode_base + blockIdx.z. Epilogues:
//  0 -> g_r fp32 + g_qh/g_ql ; 1 -> spike -> g_kb ; 2 -> g_vh/g_vl transposed ;
//  3 -> Cout + bias.
#define SBF 40
__global__ __launch_bounds__(256)
void gemm_all(int mode_base, const float* __restrict__ bias, float* __restrict__ Cout)
{
    const int mode = mode_base + blockIdx.z;
    const __nv_bfloat16* __restrict__ Ah = g_ah[mode == 3 ? 0 : mode];
    const __nv_bfloat16* __restrict__ Al = g_al[mode == 3 ? 0 : mode];
    const __nv_bfloat16* __restrict__ Wh = g_wh[mode];
    const __nv_bfloat16* __restrict__ Wl = g_wl[mode];

    __shared__ __align__(16) __nv_bfloat16 sAh[128 * SBF], sAl[128 * SBF];
    __shared__ __align__(16) __nv_bfloat16 sWh[128 * SBF], sWl[128 * SBF];

    const int tid  = threadIdx.x;
    const int wid  = tid >> 5, lane = tid & 31;
    const int wr   = wid & 1,  wc   = wid >> 1;
    const int qrow = lane >> 2, qc = lane & 3;
    const int bm = blockIdx.y * 128, bn = blockIdx.x * 128;
    const int lr = tid >> 1, cg = (tid & 1) * 16;

    float acc[4][4][4];
    #pragma unroll
    for (int mi = 0; mi < 4; mi++)
        #pragma unroll
        for (int ni = 0; ni < 4; ni++)
            #pragma unroll
            for (int e = 0; e < 4; e++) acc[mi][ni][e] = 0.f;

    for (int c = 0; c < 32; c++) {
        const size_t ka = (size_t)(bm + lr) * DMODEL + c * 32 + cg;
        const size_t kw = (size_t)(bn + lr) * DMODEL + c * 32 + cg;
        *(uint4*)(sAh + lr * SBF + cg)     = *(const uint4*)(Ah + ka);
        *(uint4*)(sAh + lr * SBF + cg + 8) = *(const uint4*)(Ah + ka + 8);
        *(uint4*)(sAl + lr * SBF + cg)     = *(const uint4*)(Al + ka);
        *(uint4*)(sAl + lr * SBF + cg + 8) = *(const uint4*)(Al + ka + 8);
        *(uint4*)(sWh + lr * SBF + cg)     = *(const uint4*)(Wh + kw);
        *(uint4*)(sWh + lr * SBF + cg + 8) = *(const uint4*)(Wh + kw + 8);
        *(uint4*)(sWl + lr * SBF + cg)     = *(const uint4*)(Wl + kw);
        *(uint4*)(sWl + lr * SBF + cg + 8) = *(const uint4*)(Wl + kw + 8);
        __syncthreads();

        #pragma unroll
        for (int ks = 0; ks < 2; ks++) {
            const int k0 = ks * 16 + 2 * qc;
            uint32_t bh[4][2], bl[4][2];
            #pragma unroll
            for (int ni = 0; ni < 4; ni++) {
                const int off = (wc * 32 + ni * 8 + qrow) * SBF + k0;
                bh[ni][0] = U32(sWh + off); bh[ni][1] = U32(sWh + off + 8);
                bl[ni][0] = U32(sWl + off); bl[ni][1] = U32(sWl + off + 8);
            }
            #pragma unroll
            for (int mi = 0; mi < 4; mi++) {
                const int off = (wr * 64 + mi * 16 + qrow) * SBF + k0;
                uint32_t ah0 = U32(sAh + off),     ah1 = U32(sAh + off + 8 * SBF);
                uint32_t ah2 = U32(sAh + off + 8), ah3 = U32(sAh + off + 8 * SBF + 8);
                uint32_t al0 = U32(sAl + off),     al1 = U32(sAl + off + 8 * SBF);
                uint32_t al2 = U32(sAl + off + 8), al3 = U32(sAl + off + 8 * SBF + 8);
                #pragma unroll
                for (int ni = 0; ni < 4; ni++) {
                    MMA_BF(acc[mi][ni], al0, al1, al2, al3, bh[ni][0], bh[ni][1]);
                    MMA_BF(acc[mi][ni], ah0, ah1, ah2, ah3, bl[ni][0], bl[ni][1]);
                    MMA_BF(acc[mi][ni], ah0, ah1, ah2, ah3, bh[ni][0], bh[ni][1]);
                }
            }
        }
        __syncthreads();
    }

    #pragma unroll
    for (int mi = 0; mi < 4; mi++) {
        const int row0 = bm + wr * 64 + mi * 16 + qrow;
        #pragma unroll
        for (int ni = 0; ni < 4; ni++) {
            const int col = bn + wc * 32 + ni * 8 + 2 * qc;
            float d0 = acc[mi][ni][0], d1 = acc[mi][ni][1];
            float d2 = acc[mi][ni][2], d3 = acc[mi][ni][3];
            if (mode == 0) {
                *(float2*)(g_r + (size_t)row0 * DMODEL + col)       = make_float2(d0, d1);
                *(float2*)(g_r + (size_t)(row0 + 8) * DMODEL + col) = make_float2(d2, d3);
                uint32_t h, l;
                split2(d0, d1, h, l);
                *(uint32_t*)(g_qh + (size_t)row0 * DMODEL + col) = h;
                *(uint32_t*)(g_ql + (size_t)row0 * DMODEL + col) = l;
                split2(d2, d3, h, l);
                *(uint32_t*)(g_qh + (size_t)(row0 + 8) * DMODEL + col) = h;
                *(uint32_t*)(g_ql + (size_t)(row0 + 8) * DMODEL + col) = l;
            } else if (mode == 1) {
                __nv_bfloat162 s;
                s.x = __float2bfloat16((d0 > 0.5f) ? 1.f : 0.f);
                s.y = __float2bfloat16((d1 > 0.5f) ? 1.f : 0.f);
                *(__nv_bfloat162*)(g_kb + (size_t)row0 * DMODEL + col) = s;
                s.x = __float2bfloat16((d2 > 0.5f) ? 1.f : 0.f);
                s.y = __float2bfloat16((d3 > 0.5f) ? 1.f : 0.f);
                *(__nv_bfloat162*)(g_kb + (size_t)(row0 + 8) * DMODEL + col) = s;
            } else if (mode == 2) {
                const int b  = row0 >> 11, tl = row0 & (TSEQ - 1);
                const int hh = col >> 6,  dd = col & (DHEAD - 1);
                const size_t base = ((size_t)(b * NHEAD + hh)) * DHEAD;
                __nv_bfloat16 h, l;
                bf_split(d0, h, l);
                g_vh[(base + dd) * TSEQ + tl] = h;         g_vl[(base + dd) * TSEQ + tl] = l;
                bf_split(d1, h, l);
                g_vh[(base + dd + 1) * TSEQ + tl] = h;     g_vl[(base + dd + 1) * TSEQ + tl] = l;
                bf_split(d2, h, l);
                g_vh[(base + dd) * TSEQ + tl + 8] = h;     g_vl[(base + dd) * TSEQ + tl + 8] = l;
                bf_split(d3, h, l);
                g_vh[(base + dd + 1) * TSEQ + tl + 8] = h; g_vl[(base + dd + 1) * TSEQ + tl + 8] = l;
            } else {
                float b0 = bias[col], b1 = bias[col + 1];
                *(float2*)(Cout + (size_t)row0 * DMODEL + col)       = make_float2(d0 + b0, d1 + b1);
                *(float2*)(Cout + (size_t)(row0 + 8) * DMODEL + col) = make_float2(d2 + b0, d3 + b1);
            }
        }
    }
}

// ---------------- flash attention: register P-reuse + cp.async double buffer ---
// 256 thr / 8 warps, 128 q rows/block, one (b,h), 32-key tiles.
// QK C-fragment == PV A-fragment layout -> P never touches smem.
#define KS 72
#define VS 40
__global__ __launch_bounds__(256)
void attn_bf()
{
    __shared__ __align__(16) __nv_bfloat16 sKb[2][32 * KS];
    __shared__ __align__(16) __nv_bfloat16 sVh[2][64 * VS], sVl[2][64 * VS];

    const int tid = threadIdx.x, warp = tid >> 5, lane = tid & 31;
    const int qr = lane >> 2, qc = lane & 3;
    const int b = blockIdx.z, h = blockIdx.y;
    const int qb = blockIdx.x * 128 + warp * 16;

    // per-thread cp.async source/dest coordinates
    const int kkey = tid >> 3, kdg = (tid & 7) * 8;          // K: 32 keys x 64 d
    const int vd = tid >> 2,   vkg = (tid & 3) * 8;          // V^T: 64 d x 32 keys
    const size_t vbase = ((size_t)(b * NHEAD + h)) * DHEAD * TSEQ;
    const __nv_bfloat16* gK = g_kb + (size_t)(b * TSEQ + kkey) * DMODEL + h * DHEAD + kdg;
    const __nv_bfloat16* gVh = g_vh + vbase + (size_t)vd * TSEQ + vkg;
    const __nv_bfloat16* gVl = g_vl + vbase + (size_t)vd * TSEQ + vkg;
    const uint32_t sKa = smem_u32(sKb) + (kkey * KS + kdg) * 2;
    const uint32_t sVha = smem_u32(sVh) + (vd * VS + vkg) * 2;
    const uint32_t sVla = smem_u32(sVl) + (vd * VS + vkg) * 2;
    const uint32_t KBUF = 32 * KS * 2, VBUF = 64 * VS * 2;

    // ---- resident Q fragments (hi/lo) ----
    uint32_t qh[4][4], ql[4][4];
    {
        const size_t r0 = (size_t)(b * TSEQ + qb + qr) * DMODEL + h * DHEAD;
        const size_t r1 = r0 + (size_t)8 * DMODEL;
        #pragma unroll
        for (int kc = 0; kc < 4; kc++) {
            const int cc = kc * 16 + 2 * qc;
            qh[kc][0] = U32(g_qh + r0 + cc);     qh[kc][1] = U32(g_qh + r1 + cc);
            qh[kc][2] = U32(g_qh + r0 + cc + 8); qh[kc][3] = U32(g_qh + r1 + cc + 8);
            ql[kc][0] = U32(g_ql + r0 + cc);     ql[kc][1] = U32(g_ql + r1 + cc);
            ql[kc][2] = U32(g_ql + r0 + cc + 8); ql[kc][3] = U32(g_ql + r1 + cc + 8);
        }
    }

    float o[8][4];
    #pragma unroll
    for (int nd = 0; nd < 8; nd++)
        #pragma unroll
        for (int e = 0; e < 4; e++) o[nd][e] = 0.f;
    float m0 = -1e30f, m1 = -1e30f, l0 = 0.f, l1 = 0.f;

    // prologue prefetch (tile 0 -> buf 0)
    CP16(sKa, gK);
    CP16(sVha, gVh);
    CP16(sVla, gVl);
    CPCOMMIT();

    int buf = 0;
    for (int kt = 0; kt < TSEQ; kt += 32) {
        CPWAIT0();
        __syncthreads();
        if (kt + 32 < TSEQ) {           // prefetch next tile into other buffer
            const int nb = buf ^ 1;
            CP16(sKa + nb * KBUF, gK + (kt + 32) * DMODEL);
            CP16(sVha + nb * VBUF, gVh + kt + 32);
            CP16(sVla + nb * VBUF, gVl + kt + 32);
            CPCOMMIT();
        }
        const __nv_bfloat16* Kb = sKb[buf];
        const __nv_bfloat16* Vh = sVh[buf];
        const __nv_bfloat16* Vl = sVl[buf];

        // ---- S = Q K^T (k binary -> exact; q hi+lo) ----
        float s[4][4];
        #pragma unroll
        for (int nt = 0; nt < 4; nt++) {
            #pragma unroll
            for (int e = 0; e < 4; e++) s[nt][e] = 0.f;
            #pragma unroll
            for (int kc = 0; kc < 4; kc++) {
                const int off = (nt * 8 + qr) * KS + kc * 16 + 2 * qc;
                uint32_t b0 = U32(Kb + off), b1 = U32(Kb + off + 8);
                MMA_BF(s[nt], ql[kc][0], ql[kc][1], ql[kc][2], ql[kc][3], b0, b1);
                MMA_BF(s[nt], qh[kc][0], qh[kc][1], qh[kc][2], qh[kc][3], b0, b1);
            }
            #pragma unroll
            for (int e = 0; e < 4; e++) s[nt][e] *= 0.125f;
        }

        // ---- online softmax (rows qr, qr+8) ----
        float t0 = -1e30f, t1 = -1e30f;
        #pragma unroll
        for (int nt = 0; nt < 4; nt++) {
            t0 = fmaxf(t0, fmaxf(s[nt][0], s[nt][1]));
            t1 = fmaxf(t1, fmaxf(s[nt][2], s[nt][3]));
        }
        t0 = fmaxf(t0, __shfl_xor_sync(0xffffffffu, t0, 1));
        t0 = fmaxf(t0, __shfl_xor_sync(0xffffffffu, t0, 2));
        t1 = fmaxf(t1, __shfl_xor_sync(0xffffffffu, t1, 1));
        t1 = fmaxf(t1, __shfl_xor_sync(0xffffffffu, t1, 2));
        float mn0 = fmaxf(m0, t0), mn1 = fmaxf(m1, t1);
        float corr0 = __expf(m0 - mn0), corr1 = __expf(m1 - mn1);
        float sum0 = 0.f, sum1 = 0.f;
        #pragma unroll
        for (int nt = 0; nt < 4; nt++) {
            s[nt][0] = __expf(s[nt][0] - mn0);
            s[nt][1] = __expf(s[nt][1] - mn0);
            s[nt][2] = __expf(s[nt][2] - mn1);
            s[nt][3] = __expf(s[nt][3] - mn1);
            sum0 += s[nt][0] + s[nt][1];
            sum1 += s[nt][2] + s[nt][3];
        }
        sum0 += __shfl_xor_sync(0xffffffffu, sum0, 1);
        sum0 += __shfl_xor_sync(0xffffffffu, sum0, 2);
        sum1 += __shfl_xor_sync(0xffffffffu, sum1, 1);
        sum1 += __shfl_xor_sync(0xffffffffu, sum1, 2);
        l0 = l0 * corr0 + sum0;
        l1 = l1 * corr1 + sum1;
        m0 = mn0; m1 = mn1;
        #pragma unroll
        for (int nd = 0; nd < 8; nd++) {
            o[nd][0] *= corr0; o[nd][1] *= corr0;
            o[nd][2] *= corr1; o[nd][3] *= corr1;
        }

        // ---- O += P V : C-frag == A-frag, split in registers, zero smem ----
        #pragma unroll
        for (int kc = 0; kc < 2; kc++) {
            uint32_t ah0, al0, ah1, al1, ah2, al2, ah3, al3;
            split2(s[2*kc][0],     s[2*kc][1],     ah0, al0);
            split2(s[2*kc][2],     s[2*kc][3],     ah1, al1);
            split2(s[2*kc + 1][0], s[2*kc + 1][1], ah2, al2);
            split2(s[2*kc + 1][2], s[2*kc + 1][3], ah3, al3);
            const int k0 = kc * 16 + 2 * qc;
            #pragma unroll
            for (int nd = 0; nd < 8; nd++) {
                const int off = (nd * 8 + qr) * VS + k0;
                uint32_t bh0 = U32(Vh + off), bh1 = U32(Vh + off + 8);
                uint32_t bl0 = U32(Vl + off), bl1 = U32(Vl + off + 8);
                MMA_BF(o[nd], al0, al1, al2, al3, bh0, bh1);
                MMA_BF(o[nd], ah0, ah1, ah2, ah3, bl0, bl1);
                MMA_BF(o[nd], ah0, ah1, ah2, ah3, bh0, bh1);
            }
        }
        buf ^= 1;
    }

    // ---- epilogue ----
    const float inv0 = 1.f / l0, inv1 = 1.f / l1;
    float* O = g_o + ((size_t)(b * TSEQ + qb) * DMODEL) + h * DHEAD;
    #pragma unroll
    for (int nd = 0; nd < 8; nd++) {
        const int cc = nd * 8 + 2 * qc;
        *(float2*)(O + (size_t)qr * DMODEL + cc) =
            make_float2(o[nd][0] * inv0, o[nd][1] * inv0);
        *(float2*)(O + (size_t)(qr + 8) * DMODEL + cc) =
            make_float2(o[nd][2] * inv1, o[nd][3] * inv1);
    }
}

// ---------------- launch (only harness pointers cross the boundary) ----------
extern "C" void kernel_launch(void* const* d_in, const int* in_sizes, int n_in,
                              void* d_out, int out_size)
{
    const float* x   = (const float*)d_in[0];
    const int*   tok = (const int*)  d_in[1];
    const float* Wr  = (const float*)d_in[2];
    const float* Wk  = (const float*)d_in[3];
    const float* Wv  = (const float*)d_in[4];
    const float* Wo  = (const float*)d_in[5];
    const float* bo  = (const float*)d_in[6];
    const float* tmk = (const float*)d_in[7];
    const float* tmv = (const float*)d_in[8];
    const float* tmr = (const float*)d_in[9];
    float* out = (float*)d_out;

    zero_cnt_kernel<<<(VOCAB + 255) / 256, 256>>>();
    hist_kernel<<<BT / 256, 256>>>(tok);
    topk_gains_kernel<<<1, 256>>>(tmr, tmk, tmv);

    split_w_all<<<(DMODEL * DMODEL) / 256, 256>>>(Wr, Wk, Wv, Wo);
    prep_x012<<<(BT * DMODEL) / 256, 256>>>(x);

    gemm_all<<<dim3(DMODEL / 128, BT / 128, 3), 256>>>(0, nullptr, nullptr);

    attn_bf<<<dim3(TSEQ / 128, NHEAD, BATCH), 256>>>();

    prep_a3<<<(BT * DMODEL) / 256, 256>>>();
    gemm_all<<<dim3(DMODEL / 128, BT / 128, 1), 256>>>(3, bo, out);
}

// round 9
// speedup vs baseline: 3.0603x; 1.0177x over previous
#include <cuda_runtime.h>
#include <cuda_bf16.h>
#include <cstdint>
#include <math.h>

#define BATCH  2
#define TSEQ   2048
#define BT     (BATCH*TSEQ)   // 4096
#define DMODEL 1024
#define NHEAD  16
#define DHEAD  64
#define VOCAB  32000

// ---------------- scratch (device globals; referenced ONLY from device code) ----
__device__ __align__(16) int   g_cnt[VOCAB];
__device__ __align__(16) float g_m[3][DMODEL];
__device__ __align__(16) float g_gate[BT*DMODEL];                                      // sigmoid(r)
__device__ __align__(16) __nv_bfloat16 g_ah[3][BT*DMODEL], g_al[3][BT*DMODEL];         // A hi/lo (mode3 reuses [0])
__device__ __align__(16) __nv_bfloat16 g_wh[4][DMODEL*DMODEL], g_wl[4][DMODEL*DMODEL]; // W hi/lo
__device__ __align__(16) __nv_bfloat16 g_qh[BT*DMODEL], g_ql[BT*DMODEL];               // q hi/lo
__device__ __align__(16) __nv_bfloat16 g_kb[BT*DMODEL];                                // k (binary)
__device__ __align__(16) __nv_bfloat16 g_vh[BATCH*NHEAD*DHEAD*TSEQ];                   // V^T hi
__device__ __align__(16) __nv_bfloat16 g_vl[BATCH*NHEAD*DHEAD*TSEQ];                   // V^T lo

// ---------------- helpers ----------------
__device__ __forceinline__ void bf_split(float x, __nv_bfloat16& h, __nv_bfloat16& l) {
    h = __float2bfloat16(x);
    l = __float2bfloat16(x - __bfloat162float(h));
}
__device__ __forceinline__ void split2(float x, float y, uint32_t& h, uint32_t& l) {
    __nv_bfloat162 hh, ll;
    hh.x = __float2bfloat16(x); hh.y = __float2bfloat16(y);
    ll.x = __float2bfloat16(x - __bfloat162float(hh.x));
    ll.y = __float2bfloat16(y - __bfloat162float(hh.y));
    h = *(uint32_t*)&hh; l = *(uint32_t*)&ll;
}
__device__ __forceinline__ uint32_t smem_u32(const void* p) {
    uint32_t a;
    asm("{ .reg .u64 t; cvta.to.shared.u64 t, %1; cvt.u32.u64 %0, t; }" : "=r"(a) : "l"(p));
    return a;
}
#define U32(p) (*reinterpret_cast<const uint32_t*>(p))
#define CP16(dst, src) asm volatile("cp.async.cg.shared.global [%0], [%1], 16;" :: "r"(dst), "l"(src))
#define CPCOMMIT()     asm volatile("cp.async.commit_group;")
#define CPWAIT0()      asm volatile("cp.async.wait_group 0;")

#define MMA_BF(c, a0, a1, a2, a3, b0, b1)                                       \
    asm volatile(                                                               \
        "mma.sync.aligned.m16n8k16.row.col.f32.bf16.bf16.f32 "                  \
        "{%0,%1,%2,%3}, {%4,%5,%6,%7}, {%8,%9}, {%0,%1,%2,%3};"                 \
        : "+f"((c)[0]), "+f"((c)[1]), "+f"((c)[2]), "+f"((c)[3])                \
        : "r"(a0), "r"(a1), "r"(a2), "r"(a3), "r"(b0), "r"(b1))

// ---------------- kWTA: histogram + top-5 + gains ----------------
__global__ void zero_cnt_kernel() {
    int i = blockIdx.x * blockDim.x + threadIdx.x;
    if (i < VOCAB) g_cnt[i] = 0;
}
__global__ void hist_kernel(const int* __restrict__ tok) {
    int i = blockIdx.x * blockDim.x + threadIdx.x;
    atomicAdd(&g_cnt[tok[i]], 1);
}
__global__ void topk_gains_kernel(const float* __restrict__ tmr,
                                  const float* __restrict__ tmk,
                                  const float* __restrict__ tmv) {
    __shared__ long long skey[256];
    __shared__ int sel[5];
    int tid = threadIdx.x;
    for (int it = 0; it < 5; it++) {
        long long best = -1;
        for (int i = tid; i < VOCAB; i += 256) {
            bool ex = false;
            for (int j = 0; j < it; j++) if (sel[j] == i) ex = true;
            if (ex) continue;
            long long key = (((long long)g_cnt[i]) << 16) | (long long)(VOCAB - 1 - i);
            if (key > best) best = key;
        }
        skey[tid] = best;
        __syncthreads();
        for (int s = 128; s > 0; s >>= 1) {
            if (tid < s && skey[tid + s] > skey[tid]) skey[tid] = skey[tid + s];
            __syncthreads();
        }
        if (tid == 0) sel[it] = VOCAB - 1 - (int)(skey[0] & 0xFFFFLL);
        __syncthreads();
    }
    for (int d = tid; d < DMODEL; d += 256) {
        float g = (g_cnt[d] > 0) ? 0.6f : 1.0f;
        #pragma unroll
        for (int j = 0; j < 5; j++) if (sel[j] == d) g = 1.5f;
        g_m[0][d] = tmr[d] * g;
        g_m[1][d] = tmk[d] * g;
        g_m[2][d] = tmv[d] * g;
    }
}

// ---------------- prep: all 4 W splits in one pass ----------------
__global__ void split_w_all(const float* __restrict__ W0, const float* __restrict__ W1,
                            const float* __restrict__ W2, const float* __restrict__ W3) {
    int i = blockIdx.x * 256 + threadIdx.x;
    const float* Ws[4] = {W0, W1, W2, W3};
    #pragma unroll
    for (int m = 0; m < 4; m++) {
        __nv_bfloat16 h, l;
        bf_split(Ws[m][i], h, l);
        g_wh[m][i] = h; g_wl[m][i] = l;
    }
}

// ---------------- prep: 3 mixed inputs in one pass (x read once) --------------
__global__ void prep_x012(const float* __restrict__ X) {
    int i = blockIdx.x * 256 + threadIdx.x;
    int t = i >> 10, d = i & (DMODEL - 1);
    float xv = X[i];
    float pv = ((t & (TSEQ - 1)) != 0) ? X[i - DMODEL] : 0.f;
    #pragma unroll
    for (int m = 0; m < 3; m++) {
        float mm = g_m[m][d];
        float a = mm * xv + (1.f - mm) * pv;
        __nv_bfloat16 h, l;
        bf_split(a, h, l);
        g_ah[m][i] = h; g_al[m][i] = l;
    }
}

// ---------------- bf16 3-term GEMM, 2-stage cp.async pipeline ------------------
// CTA 128x128, 8 warps (warp tile 64x32), K chunk 16, double-buffered smem.
// Row stride 24 bf16 (48B): cp.async dsts 16B-aligned, fragment LDS conflict-free.
// Epilogues: 0 -> g_gate=sigmoid(r) + g_qh/g_ql ; 1 -> spike -> g_kb ;
//            2 -> g_vh/g_vl transposed ; 3 -> Cout + bias.
#define CH  16
#define SBF 24
#define STG (128 * SBF * 2)   // stage size in bytes
__global__ __launch_bounds__(256)
void gemm_all(int mode_base, const float* __restrict__ bias, float* __restrict__ Cout)
{
    const int mode = mode_base + blockIdx.z;
    const __nv_bfloat16* __restrict__ Ah = g_ah[mode == 3 ? 0 : mode];
    const __nv_bfloat16* __restrict__ Al = g_al[mode == 3 ? 0 : mode];
    const __nv_bfloat16* __restrict__ Wh = g_wh[mode];
    const __nv_bfloat16* __restrict__ Wl = g_wl[mode];

    __shared__ __align__(16) __nv_bfloat16 sAh[2][128 * SBF], sAl[2][128 * SBF];
    __shared__ __align__(16) __nv_bfloat16 sWh[2][128 * SBF], sWl[2][128 * SBF];

    const int tid  = threadIdx.x;
    const int wid  = tid >> 5, lane = tid & 31;
    const int wr   = wid & 1,  wc   = wid >> 1;
    const int qrow = lane >> 2, qc = lane & 3;
    const int bm = blockIdx.y * 128, bn = blockIdx.x * 128;
    const int lr = tid >> 1, cg = (tid & 1) * 8;

    const __nv_bfloat16* pAh = Ah + (size_t)(bm + lr) * DMODEL + cg;
    const __nv_bfloat16* pAl = Al + (size_t)(bm + lr) * DMODEL + cg;
    const __nv_bfloat16* pWh = Wh + (size_t)(bn + lr) * DMODEL + cg;
    const __nv_bfloat16* pWl = Wl + (size_t)(bn + lr) * DMODEL + cg;
    const uint32_t dAh = smem_u32(sAh) + (lr * SBF + cg) * 2;
    const uint32_t dAl = smem_u32(sAl) + (lr * SBF + cg) * 2;
    const uint32_t dWh = smem_u32(sWh) + (lr * SBF + cg) * 2;
    const uint32_t dWl = smem_u32(sWl) + (lr * SBF + cg) * 2;

    float acc[4][4][4];
    #pragma unroll
    for (int mi = 0; mi < 4; mi++)
        #pragma unroll
        for (int ni = 0; ni < 4; ni++)
            #pragma unroll
            for (int e = 0; e < 4; e++) acc[mi][ni][e] = 0.f;

    // prologue: prefetch chunk 0 into stage 0
    CP16(dAh, pAh); CP16(dAl, pAl); CP16(dWh, pWh); CP16(dWl, pWl);
    CPCOMMIT();

    for (int c = 0; c < DMODEL / CH; c++) {
        CPWAIT0();
        __syncthreads();
        if (c + 1 < DMODEL / CH) {
            const uint32_t so = ((c + 1) & 1) * STG;
            const int go = (c + 1) * CH;
            CP16(dAh + so, pAh + go); CP16(dAl + so, pAl + go);
            CP16(dWh + so, pWh + go); CP16(dWl + so, pWl + go);
            CPCOMMIT();
        }
        const __nv_bfloat16* cAh = sAh[c & 1];
        const __nv_bfloat16* cAl = sAl[c & 1];
        const __nv_bfloat16* cWh = sWh[c & 1];
        const __nv_bfloat16* cWl = sWl[c & 1];

        const int k0 = 2 * qc;
        uint32_t bh[4][2], bl[4][2];
        #pragma unroll
        for (int ni = 0; ni < 4; ni++) {
            const int off = (wc * 32 + ni * 8 + qrow) * SBF + k0;
            bh[ni][0] = U32(cWh + off); bh[ni][1] = U32(cWh + off + 8);
            bl[ni][0] = U32(cWl + off); bl[ni][1] = U32(cWl + off + 8);
        }
        #pragma unroll
        for (int mi = 0; mi < 4; mi++) {
            const int off = (wr * 64 + mi * 16 + qrow) * SBF + k0;
            uint32_t ah0 = U32(cAh + off),     ah1 = U32(cAh + off + 8 * SBF);
            uint32_t ah2 = U32(cAh + off + 8), ah3 = U32(cAh + off + 8 * SBF + 8);
            uint32_t al0 = U32(cAl + off),     al1 = U32(cAl + off + 8 * SBF);
            uint32_t al2 = U32(cAl + off + 8), al3 = U32(cAl + off + 8 * SBF + 8);
            #pragma unroll
            for (int ni = 0; ni < 4; ni++) {
                MMA_BF(acc[mi][ni], al0, al1, al2, al3, bh[ni][0], bh[ni][1]);
                MMA_BF(acc[mi][ni], ah0, ah1, ah2, ah3, bl[ni][0], bl[ni][1]);
                MMA_BF(acc[mi][ni], ah0, ah1, ah2, ah3, bh[ni][0], bh[ni][1]);
            }
        }
    }

    #pragma unroll
    for (int mi = 0; mi < 4; mi++) {
        const int row0 = bm + wr * 64 + mi * 16 + qrow;
        #pragma unroll
        for (int ni = 0; ni < 4; ni++) {
            const int col = bn + wc * 32 + ni * 8 + 2 * qc;
            float d0 = acc[mi][ni][0], d1 = acc[mi][ni][1];
            float d2 = acc[mi][ni][2], d3 = acc[mi][ni][3];
            if (mode == 0) {
                // gate = sigmoid(r); q = r (bf16 hi/lo)
                *(float2*)(g_gate + (size_t)row0 * DMODEL + col) =
                    make_float2(1.f / (1.f + __expf(-d0)), 1.f / (1.f + __expf(-d1)));
                *(float2*)(g_gate + (size_t)(row0 + 8) * DMODEL + col) =
                    make_float2(1.f / (1.f + __expf(-d2)), 1.f / (1.f + __expf(-d3)));
                uint32_t h, l;
                split2(d0, d1, h, l);
                *(uint32_t*)(g_qh + (size_t)row0 * DMODEL + col) = h;
                *(uint32_t*)(g_ql + (size_t)row0 * DMODEL + col) = l;
                split2(d2, d3, h, l);
                *(uint32_t*)(g_qh + (size_t)(row0 + 8) * DMODEL + col) = h;
                *(uint32_t*)(g_ql + (size_t)(row0 + 8) * DMODEL + col) = l;
            } else if (mode == 1) {
                __nv_bfloat162 s;
                s.x = __float2bfloat16((d0 > 0.5f) ? 1.f : 0.f);
                s.y = __float2bfloat16((d1 > 0.5f) ? 1.f : 0.f);
                *(__nv_bfloat162*)(g_kb + (size_t)row0 * DMODEL + col) = s;
                s.x = __float2bfloat16((d2 > 0.5f) ? 1.f : 0.f);
                s.y = __float2bfloat16((d3 > 0.5f) ? 1.f : 0.f);
                *(__nv_bfloat162*)(g_kb + (size_t)(row0 + 8) * DMODEL + col) = s;
            } else if (mode == 2) {
                const int b  = row0 >> 11, tl = row0 & (TSEQ - 1);
                const int hh = col >> 6,  dd = col & (DHEAD - 1);
                const size_t base = ((size_t)(b * NHEAD + hh)) * DHEAD;
                __nv_bfloat16 h, l;
                bf_split(d0, h, l);
                g_vh[(base + dd) * TSEQ + tl] = h;         g_vl[(base + dd) * TSEQ + tl] = l;
                bf_split(d1, h, l);
                g_vh[(base + dd + 1) * TSEQ + tl] = h;     g_vl[(base + dd + 1) * TSEQ + tl] = l;
                bf_split(d2, h, l);
                g_vh[(base + dd) * TSEQ + tl + 8] = h;     g_vl[(base + dd) * TSEQ + tl + 8] = l;
                bf_split(d3, h, l);
                g_vh[(base + dd + 1) * TSEQ + tl + 8] = h; g_vl[(base + dd + 1) * TSEQ + tl + 8] = l;
            } else {
                float b0 = bias[col], b1 = bias[col + 1];
                *(float2*)(Cout + (size_t)row0 * DMODEL + col)       = make_float2(d0 + b0, d1 + b1);
                *(float2*)(Cout + (size_t)(row0 + 8) * DMODEL + col) = make_float2(d2 + b0, d3 + b1);
            }
        }
    }
}

// ---------------- flash attention: register P-reuse + cp.async double buffer ---
// 256 thr / 8 warps, 128 q rows/block, one (b,h), 32-key tiles.
// Epilogue fuses receptance gating and writes the final GEMM's bf16 A operand.
#define KS 72
#define VS 40
__global__ __launch_bounds__(256)
void attn_bf()
{
    __shared__ __align__(16) __nv_bfloat16 sKb[2][32 * KS];
    __shared__ __align__(16) __nv_bfloat16 sVh[2][64 * VS], sVl[2][64 * VS];

    const int tid = threadIdx.x, warp = tid >> 5, lane = tid & 31;
    const int qr = lane >> 2, qc = lane & 3;
    const int b = blockIdx.z, h = blockIdx.y;
    const int qb = blockIdx.x * 128 + warp * 16;

    const int kkey = tid >> 3, kdg = (tid & 7) * 8;
    const int vd = tid >> 2,   vkg = (tid & 3) * 8;
    const size_t vbase = ((size_t)(b * NHEAD + h)) * DHEAD * TSEQ;
    const __nv_bfloat16* gK  = g_kb + (size_t)(b * TSEQ + kkey) * DMODEL + h * DHEAD + kdg;
    const __nv_bfloat16* gVh = g_vh + vbase + (size_t)vd * TSEQ + vkg;
    const __nv_bfloat16* gVl = g_vl + vbase + (size_t)vd * TSEQ + vkg;
    const uint32_t sKa  = smem_u32(sKb) + (kkey * KS + kdg) * 2;
    const uint32_t sVha = smem_u32(sVh) + (vd * VS + vkg) * 2;
    const uint32_t sVla = smem_u32(sVl) + (vd * VS + vkg) * 2;
    const uint32_t KBUF = 32 * KS * 2, VBUF = 64 * VS * 2;

    uint32_t qh[4][4], ql[4][4];
    {
        const size_t r0 = (size_t)(b * TSEQ + qb + qr) * DMODEL + h * DHEAD;
        const size_t r1 = r0 + (size_t)8 * DMODEL;
        #pragma unroll
        for (int kc = 0; kc < 4; kc++) {
            const int cc = kc * 16 + 2 * qc;
            qh[kc][0] = U32(g_qh + r0 + cc);     qh[kc][1] = U32(g_qh + r1 + cc);
            qh[kc][2] = U32(g_qh + r0 + cc + 8); qh[kc][3] = U32(g_qh + r1 + cc + 8);
            ql[kc][0] = U32(g_ql + r0 + cc);     ql[kc][1] = U32(g_ql + r1 + cc);
            ql[kc][2] = U32(g_ql + r0 + cc + 8); ql[kc][3] = U32(g_ql + r1 + cc + 8);
        }
    }

    float o[8][4];
    #pragma unroll
    for (int nd = 0; nd < 8; nd++)
        #pragma unroll
        for (int e = 0; e < 4; e++) o[nd][e] = 0.f;
    float m0 = -1e30f, m1 = -1e30f, l0 = 0.f, l1 = 0.f;

    CP16(sKa, gK);
    CP16(sVha, gVh);
    CP16(sVla, gVl);
    CPCOMMIT();

    int buf = 0;
    for (int kt = 0; kt < TSEQ; kt += 32) {
        CPWAIT0();
        __syncthreads();
        if (kt + 32 < TSEQ) {
            const int nb = buf ^ 1;
            CP16(sKa + nb * KBUF, gK + (kt + 32) * DMODEL);
            CP16(sVha + nb * VBUF, gVh + kt + 32);
            CP16(sVla + nb * VBUF, gVl + kt + 32);
            CPCOMMIT();
        }
        const __nv_bfloat16* Kb = sKb[buf];
        const __nv_bfloat16* Vh = sVh[buf];
        const __nv_bfloat16* Vl = sVl[buf];

        float s[4][4];
        #pragma unroll
        for (int nt = 0; nt < 4; nt++) {
            #pragma unroll
            for (int e = 0; e < 4; e++) s[nt][e] = 0.f;
            #pragma unroll
            for (int kc = 0; kc < 4; kc++) {
                const int off = (nt * 8 + qr) * KS + kc * 16 + 2 * qc;
                uint32_t b0 = U32(Kb + off), b1 = U32(Kb + off + 8);
                MMA_BF(s[nt], ql[kc][0], ql[kc][1], ql[kc][2], ql[kc][3], b0, b1);
                MMA_BF(s[nt], qh[kc][0], qh[kc][1], qh[kc][2], qh[kc][3], b0, b1);
            }
            #pragma unroll
            for (int e = 0; e < 4; e++) s[nt][e] *= 0.125f;
        }

        float t0 = -1e30f, t1 = -1e30f;
        #pragma unroll
        for (int nt = 0; nt < 4; nt++) {
            t0 = fmaxf(t0, fmaxf(s[nt][0], s[nt][1]));
            t1 = fmaxf(t1, fmaxf(s[nt][2], s[nt][3]));
        }
        t0 = fmaxf(t0, __shfl_xor_sync(0xffffffffu, t0, 1));
        t0 = fmaxf(t0, __shfl_xor_sync(0xffffffffu, t0, 2));
        t1 = fmaxf(t1, __shfl_xor_sync(0xffffffffu, t1, 1));
        t1 = fmaxf(t1, __shfl_xor_sync(0xffffffffu, t1, 2));
        float mn0 = fmaxf(m0, t0), mn1 = fmaxf(m1, t1);
        float corr0 = __expf(m0 - mn0), corr1 = __expf(m1 - mn1);
        float sum0 = 0.f, sum1 = 0.f;
        #pragma unroll
        for (int nt = 0; nt < 4; nt++) {
            s[nt][0] = __expf(s[nt][0] - mn0);
            s[nt][1] = __expf(s[nt][1] - mn0);
            s[nt][2] = __expf(s[nt][2] - mn1);
            s[nt][3] = __expf(s[nt][3] - mn1);
            sum0 += s[nt][0] + s[nt][1];
            sum1 += s[nt][2] + s[nt][3];
        }
        sum0 += __shfl_xor_sync(0xffffffffu, sum0, 1);
        sum0 += __shfl_xor_sync(0xffffffffu, sum0, 2);
        sum1 += __shfl_xor_sync(0xffffffffu, sum1, 1);
        sum1 += __shfl_xor_sync(0xffffffffu, sum1, 2);
        l0 = l0 * corr0 + sum0;
        l1 = l1 * corr1 + sum1;
        m0 = mn0; m1 = mn1;
        #pragma unroll
        for (int nd = 0; nd < 8; nd++) {
            o[nd][0] *= corr0; o[nd][1] *= corr0;
            o[nd][2] *= corr1; o[nd][3] *= corr1;
        }

        #pragma unroll
        for (int kc = 0; kc < 2; kc++) {
            uint32_t ah0, al0, ah1, al1, ah2, al2, ah3, al3;
            split2(s[2*kc][0],     s[2*kc][1],     ah0, al0);
            split2(s[2*kc][2],     s[2*kc][3],     ah1, al1);
            split2(s[2*kc + 1][0], s[2*kc + 1][1], ah2, al2);
            split2(s[2*kc + 1][2], s[2*kc + 1][3], ah3, al3);
            const int k0 = kc * 16 + 2 * qc;
            #pragma unroll
            for (int nd = 0; nd < 8; nd++) {
                const int off = (nd * 8 + qr) * VS + k0;
                uint32_t bh0 = U32(Vh + off), bh1 = U32(Vh + off + 8);
                uint32_t bl0 = U32(Vl + off), bl1 = U32(Vl + off + 8);
                MMA_BF(o[nd], al0, al1, al2, al3, bh0, bh1);
                MMA_BF(o[nd], ah0, ah1, ah2, ah3, bl0, bl1);
                MMA_BF(o[nd], ah0, ah1, ah2, ah3, bh0, bh1);
            }
        }
        buf ^= 1;
    }

    // ---- epilogue: normalize, gate, split -> final GEMM A operand ----
    const float inv0 = 1.f / l0, inv1 = 1.f / l1;
    const size_t r0 = (size_t)(b * TSEQ + qb + qr) * DMODEL + h * DHEAD;
    const size_t r1 = r0 + (size_t)8 * DMODEL;
    #pragma unroll
    for (int nd = 0; nd < 8; nd++) {
        const int cc = nd * 8 + 2 * qc;
        float2 gt0 = *(const float2*)(g_gate + r0 + cc);
        float2 gt1 = *(const float2*)(g_gate + r1 + cc);
        float a0 = o[nd][0] * inv0 * gt0.x, a1 = o[nd][1] * inv0 * gt0.y;
        float a2 = o[nd][2] * inv1 * gt1.x, a3 = o[nd][3] * inv1 * gt1.y;
        uint32_t h2, l2;
        split2(a0, a1, h2, l2);
        *(uint32_t*)(g_ah[0] + r0 + cc) = h2;
        *(uint32_t*)(g_al[0] + r0 + cc) = l2;
        split2(a2, a3, h2, l2);
        *(uint32_t*)(g_ah[0] + r1 + cc) = h2;
        *(uint32_t*)(g_al[0] + r1 + cc) = l2;
    }
}

// ---------------- launch (only harness pointers cross the boundary) ----------
extern "C" void kernel_launch(void* const* d_in, const int* in_sizes, int n_in,
                              void* d_out, int out_size)
{
    const float* x   = (const float*)d_in[0];
    const int*   tok = (const int*)  d_in[1];
    const float* Wr  = (const float*)d_in[2];
    const float* Wk  = (const float*)d_in[3];
    const float* Wv  = (const float*)d_in[4];
    const float* Wo  = (const float*)d_in[5];
    const float* bo  = (const float*)d_in[6];
    const float* tmk = (const float*)d_in[7];
    const float* tmv = (const float*)d_in[8];
    const float* tmr = (const float*)d_in[9];
    float* out = (float*)d_out;

    zero_cnt_kernel<<<(VOCAB + 255) / 256, 256>>>();
    hist_kernel<<<BT / 256, 256>>>(tok);
    topk_gains_kernel<<<1, 256>>>(tmr, tmk, tmv);

    split_w_all<<<(DMODEL * DMODEL) / 256, 256>>>(Wr, Wk, Wv, Wo);
    prep_x012<<<(BT * DMODEL) / 256, 256>>>(x);

    gemm_all<<<dim3(DMODEL / 128, BT / 128, 3), 256>>>(0, nullptr, nullptr);

    attn_bf<<<dim3(TSEQ / 128, NHEAD, BATCH), 256>>>();

    gemm_all<<<dim3(DMODEL / 128, BT / 128, 1), 256>>>(3, bo, out);
}

// round 10
// speedup vs baseline: 3.6530x; 1.1937x over previous
#include <cuda_runtime.h>
#include <cuda_fp16.h>
#include <cstdint>
#include <math.h>

#define BATCH  2
#define TSEQ   2048
#define BT     (BATCH*TSEQ)   // 4096
#define DMODEL 1024
#define NHEAD  16
#define DHEAD  64
#define VOCAB  32000

// ---------------- scratch (device globals; referenced ONLY from device code) ----
__device__ __align__(16) int   g_cnt[VOCAB];
__device__ __align__(16) float g_m[3][DMODEL];
__device__ __align__(16) float g_gate[BT*DMODEL];                             // sigmoid(r)
__device__ __align__(16) __half g_ah[3][BT*DMODEL], g_al[3][BT*DMODEL];       // A hi/lo (mode3 reuses [0])
__device__ __align__(16) __half g_wh[4][DMODEL*DMODEL];                       // W hi (all 4)
__device__ __align__(16) __half g_wl[DMODEL*DMODEL];                          // W lo (k-GEMM only)
__device__ __align__(16) __half g_qh[BT*DMODEL], g_ql[BT*DMODEL];             // q hi/lo
__device__ __align__(16) __half g_kb[BT*DMODEL];                              // k (binary)
__device__ __align__(16) __half g_vf[BATCH*NHEAD*DHEAD*TSEQ];                 // V^T (single fp16)

// ---------------- helpers ----------------
__device__ __forceinline__ void h_split(float x, __half& h, __half& l) {
    h = __float2half_rn(x);
    l = __float2half_rn(x - __half2float(h));
}
__device__ __forceinline__ void split2h(float x, float y, uint32_t& h, uint32_t& l) {
    __half2 hh = __floats2half2_rn(x, y);
    float2 hf = __half22float2(hh);
    __half2 ll = __floats2half2_rn(x - hf.x, y - hf.y);
    h = *(uint32_t*)&hh; l = *(uint32_t*)&ll;
}
__device__ __forceinline__ uint32_t smem_u32(const void* p) {
    uint32_t a;
    asm("{ .reg .u64 t; cvta.to.shared.u64 t, %1; cvt.u32.u64 %0, t; }" : "=r"(a) : "l"(p));
    return a;
}
#define U32(p) (*reinterpret_cast<const uint32_t*>(p))
#define CP16(dst, src) asm volatile("cp.async.cg.shared.global [%0], [%1], 16;" :: "r"(dst), "l"(src))
#define CPCOMMIT()     asm volatile("cp.async.commit_group;")
#define CPWAIT0()      asm volatile("cp.async.wait_group 0;")

#define MMA_F16(c, a0, a1, a2, a3, b0, b1)                                      \
    asm volatile(                                                               \
        "mma.sync.aligned.m16n8k16.row.col.f32.f16.f16.f32 "                    \
        "{%0,%1,%2,%3}, {%4,%5,%6,%7}, {%8,%9}, {%0,%1,%2,%3};"                 \
        : "+f"((c)[0]), "+f"((c)[1]), "+f"((c)[2]), "+f"((c)[3])                \
        : "r"(a0), "r"(a1), "r"(a2), "r"(a3), "r"(b0), "r"(b1))

// ---------------- kWTA: histogram + top-5 + gains ----------------
__global__ void zero_cnt_kernel() {
    int i = blockIdx.x * blockDim.x + threadIdx.x;
    if (i < VOCAB) g_cnt[i] = 0;
}
__global__ void hist_kernel(const int* __restrict__ tok) {
    int i = blockIdx.x * blockDim.x + threadIdx.x;
    atomicAdd(&g_cnt[tok[i]], 1);
}
__global__ void topk_gains_kernel(const float* __restrict__ tmr,
                                  const float* __restrict__ tmk,
                                  const float* __restrict__ tmv) {
    __shared__ long long skey[256];
    __shared__ int sel[5];
    int tid = threadIdx.x;
    for (int it = 0; it < 5; it++) {
        long long best = -1;
        for (int i = tid; i < VOCAB; i += 256) {
            bool ex = false;
            for (int j = 0; j < it; j++) if (sel[j] == i) ex = true;
            if (ex) continue;
            long long key = (((long long)g_cnt[i]) << 16) | (long long)(VOCAB - 1 - i);
            if (key > best) best = key;
        }
        skey[tid] = best;
        __syncthreads();
        for (int s = 128; s > 0; s >>= 1) {
            if (tid < s && skey[tid + s] > skey[tid]) skey[tid] = skey[tid + s];
            __syncthreads();
        }
        if (tid == 0) sel[it] = VOCAB - 1 - (int)(skey[0] & 0xFFFFLL);
        __syncthreads();
    }
    for (int d = tid; d < DMODEL; d += 256) {
        float g = (g_cnt[d] > 0) ? 0.6f : 1.0f;
        #pragma unroll
        for (int j = 0; j < 5; j++) if (sel[j] == d) g = 1.5f;
        g_m[0][d] = tmr[d] * g;
        g_m[1][d] = tmk[d] * g;
        g_m[2][d] = tmv[d] * g;
    }
}

// ---------------- prep: W splits (hi x4; lo only for Wk) ----------------
__global__ void split_w_all(const float* __restrict__ W0, const float* __restrict__ W1,
                            const float* __restrict__ W2, const float* __restrict__ W3) {
    int i = blockIdx.x * 256 + threadIdx.x;
    const float* Ws[4] = {W0, W1, W2, W3};
    #pragma unroll
    for (int m = 0; m < 4; m++) {
        __half h, l;
        h_split(Ws[m][i], h, l);
        g_wh[m][i] = h;
        if (m == 1) g_wl[i] = l;
    }
}

// ---------------- prep: 3 mixed inputs in one pass (x read once) --------------
__global__ void prep_x012(const float* __restrict__ X) {
    int i = blockIdx.x * 256 + threadIdx.x;
    int t = i >> 10, d = i & (DMODEL - 1);
    float xv = X[i];
    float pv = ((t & (TSEQ - 1)) != 0) ? X[i - DMODEL] : 0.f;
    #pragma unroll
    for (int m = 0; m < 3; m++) {
        float mm = g_m[m][d];
        float a = mm * xv + (1.f - mm) * pv;
        __half h, l;
        h_split(a, h, l);
        g_ah[m][i] = h; g_al[m][i] = l;
    }
}

// ---------------- fp16 tensor-core GEMM, 2-stage cp.async pipeline -------------
// CTA 128x128, 8 warps (warp tile 64x32), K chunk 16, double-buffered smem.
// Terms: acc += al*wh + ah*wh (modes 0,2,3: error ~2^-12 rms from dropped a*wl)
//        + ah*wl (mode 1 only: near-exact for spike threshold).
// Epilogues: 0 -> g_gate=sigmoid(r) + g_qh/g_ql ; 1 -> spike -> g_kb ;
//            2 -> g_vf transposed (single fp16) ; 3 -> Cout + bias.
#define CH  16
#define SBF 24
#define STG (128 * SBF * 2)   // stage size in bytes
__global__ __launch_bounds__(256)
void gemm_all(int mode_base, const float* __restrict__ bias, float* __restrict__ Cout)
{
    const int mode = mode_base + blockIdx.z;
    const bool t3 = (mode == 1);
    const __half* __restrict__ Ah = g_ah[mode == 3 ? 0 : mode];
    const __half* __restrict__ Al = g_al[mode == 3 ? 0 : mode];
    const __half* __restrict__ Wh = g_wh[mode];
    const __half* __restrict__ Wl = g_wl;

    __shared__ __align__(16) __half sAh[2][128 * SBF], sAl[2][128 * SBF];
    __shared__ __align__(16) __half sWh[2][128 * SBF], sWl[2][128 * SBF];

    const int tid  = threadIdx.x;
    const int wid  = tid >> 5, lane = tid & 31;
    const int wr   = wid & 1,  wc   = wid >> 1;
    const int qrow = lane >> 2, qc = lane & 3;
    const int bm = blockIdx.y * 128, bn = blockIdx.x * 128;
    const int lr = tid >> 1, cg = (tid & 1) * 8;

    const __half* pAh = Ah + (size_t)(bm + lr) * DMODEL + cg;
    const __half* pAl = Al + (size_t)(bm + lr) * DMODEL + cg;
    const __half* pWh = Wh + (size_t)(bn + lr) * DMODEL + cg;
    const __half* pWl = Wl + (size_t)(bn + lr) * DMODEL + cg;
    const uint32_t dAh = smem_u32(sAh) + (lr * SBF + cg) * 2;
    const uint32_t dAl = smem_u32(sAl) + (lr * SBF + cg) * 2;
    const uint32_t dWh = smem_u32(sWh) + (lr * SBF + cg) * 2;
    const uint32_t dWl = smem_u32(sWl) + (lr * SBF + cg) * 2;

    float acc[4][4][4];
    #pragma unroll
    for (int mi = 0; mi < 4; mi++)
        #pragma unroll
        for (int ni = 0; ni < 4; ni++)
            #pragma unroll
            for (int e = 0; e < 4; e++) acc[mi][ni][e] = 0.f;

    CP16(dAh, pAh); CP16(dAl, pAl); CP16(dWh, pWh);
    if (t3) CP16(dWl, pWl);
    CPCOMMIT();

    for (int c = 0; c < DMODEL / CH; c++) {
        CPWAIT0();
        __syncthreads();
        if (c + 1 < DMODEL / CH) {
            const uint32_t so = ((c + 1) & 1) * STG;
            const int go = (c + 1) * CH;
            CP16(dAh + so, pAh + go); CP16(dAl + so, pAl + go);
            CP16(dWh + so, pWh + go);
            if (t3) CP16(dWl + so, pWl + go);
            CPCOMMIT();
        }
        const __half* cAh = sAh[c & 1];
        const __half* cAl = sAl[c & 1];
        const __half* cWh = sWh[c & 1];
        const __half* cWl = sWl[c & 1];

        const int k0 = 2 * qc;
        uint32_t bh[4][2], bl[4][2];
        #pragma unroll
        for (int ni = 0; ni < 4; ni++) {
            const int off = (wc * 32 + ni * 8 + qrow) * SBF + k0;
            bh[ni][0] = U32(cWh + off); bh[ni][1] = U32(cWh + off + 8);
            if (t3) { bl[ni][0] = U32(cWl + off); bl[ni][1] = U32(cWl + off + 8); }
        }
        #pragma unroll
        for (int mi = 0; mi < 4; mi++) {
            const int off = (wr * 64 + mi * 16 + qrow) * SBF + k0;
            uint32_t ah0 = U32(cAh + off),     ah1 = U32(cAh + off + 8 * SBF);
            uint32_t ah2 = U32(cAh + off + 8), ah3 = U32(cAh + off + 8 * SBF + 8);
            uint32_t al0 = U32(cAl + off),     al1 = U32(cAl + off + 8 * SBF);
            uint32_t al2 = U32(cAl + off + 8), al3 = U32(cAl + off + 8 * SBF + 8);
            #pragma unroll
            for (int ni = 0; ni < 4; ni++) {
                MMA_F16(acc[mi][ni], al0, al1, al2, al3, bh[ni][0], bh[ni][1]);
                MMA_F16(acc[mi][ni], ah0, ah1, ah2, ah3, bh[ni][0], bh[ni][1]);
                if (t3)
                    MMA_F16(acc[mi][ni], ah0, ah1, ah2, ah3, bl[ni][0], bl[ni][1]);
            }
        }
    }

    #pragma unroll
    for (int mi = 0; mi < 4; mi++) {
        const int row0 = bm + wr * 64 + mi * 16 + qrow;
        #pragma unroll
        for (int ni = 0; ni < 4; ni++) {
            const int col = bn + wc * 32 + ni * 8 + 2 * qc;
            float d0 = acc[mi][ni][0], d1 = acc[mi][ni][1];
            float d2 = acc[mi][ni][2], d3 = acc[mi][ni][3];
            if (mode == 0) {
                *(float2*)(g_gate + (size_t)row0 * DMODEL + col) =
                    make_float2(1.f / (1.f + __expf(-d0)), 1.f / (1.f + __expf(-d1)));
                *(float2*)(g_gate + (size_t)(row0 + 8) * DMODEL + col) =
                    make_float2(1.f / (1.f + __expf(-d2)), 1.f / (1.f + __expf(-d3)));
                uint32_t h, l;
                split2h(d0, d1, h, l);
                *(uint32_t*)(g_qh + (size_t)row0 * DMODEL + col) = h;
                *(uint32_t*)(g_ql + (size_t)row0 * DMODEL + col) = l;
                split2h(d2, d3, h, l);
                *(uint32_t*)(g_qh + (size_t)(row0 + 8) * DMODEL + col) = h;
                *(uint32_t*)(g_ql + (size_t)(row0 + 8) * DMODEL + col) = l;
            } else if (mode == 1) {
                __half2 s;
                s.x = __float2half((d0 > 0.5f) ? 1.f : 0.f);
                s.y = __float2half((d1 > 0.5f) ? 1.f : 0.f);
                *(__half2*)(g_kb + (size_t)row0 * DMODEL + col) = s;
                s.x = __float2half((d2 > 0.5f) ? 1.f : 0.f);
                s.y = __float2half((d3 > 0.5f) ? 1.f : 0.f);
                *(__half2*)(g_kb + (size_t)(row0 + 8) * DMODEL + col) = s;
            } else if (mode == 2) {
                const int b  = row0 >> 11, tl = row0 & (TSEQ - 1);
                const int hh = col >> 6,  dd = col & (DHEAD - 1);
                const size_t base = ((size_t)(b * NHEAD + hh)) * DHEAD;
                g_vf[(base + dd) * TSEQ + tl]         = __float2half(d0);
                g_vf[(base + dd + 1) * TSEQ + tl]     = __float2half(d1);
                g_vf[(base + dd) * TSEQ + tl + 8]     = __float2half(d2);
                g_vf[(base + dd + 1) * TSEQ + tl + 8] = __float2half(d3);
            } else {
                float b0 = bias[col], b1 = bias[col + 1];
                *(float2*)(Cout + (size_t)row0 * DMODEL + col)       = make_float2(d0 + b0, d1 + b1);
                *(float2*)(Cout + (size_t)(row0 + 8) * DMODEL + col) = make_float2(d2 + b0, d3 + b1);
            }
        }
    }
}

// ---------------- flash attention: fp16, register P-reuse, cp.async ------------
// 256 thr / 8 warps, 128 q rows/block, one (b,h), 32-key tiles.
// QK: 2 MMAs (q hi/lo fp16; k binary = exact). PV: 2 MMAs ((Ph+Pl) x Vf).
// Epilogue fuses receptance gating and writes the final GEMM's fp16 A operand.
#define KS 72
#define VS 40
__global__ __launch_bounds__(256)
void attn_f16()
{
    __shared__ __align__(16) __half sKb[2][32 * KS];
    __shared__ __align__(16) __half sVf[2][64 * VS];

    const int tid = threadIdx.x, warp = tid >> 5, lane = tid & 31;
    const int qr = lane >> 2, qc = lane & 3;
    const int b = blockIdx.z, h = blockIdx.y;
    const int qb = blockIdx.x * 128 + warp * 16;

    const int kkey = tid >> 3, kdg = (tid & 7) * 8;
    const int vd = tid >> 2,   vkg = (tid & 3) * 8;
    const size_t vbase = ((size_t)(b * NHEAD + h)) * DHEAD * TSEQ;
    const __half* gK  = g_kb + (size_t)(b * TSEQ + kkey) * DMODEL + h * DHEAD + kdg;
    const __half* gVf = g_vf + vbase + (size_t)vd * TSEQ + vkg;
    const uint32_t sKa  = smem_u32(sKb) + (kkey * KS + kdg) * 2;
    const uint32_t sVfa = smem_u32(sVf) + (vd * VS + vkg) * 2;
    const uint32_t KBUF = 32 * KS * 2, VBUF = 64 * VS * 2;

    uint32_t qh[4][4], ql[4][4];
    {
        const size_t r0 = (size_t)(b * TSEQ + qb + qr) * DMODEL + h * DHEAD;
        const size_t r1 = r0 + (size_t)8 * DMODEL;
        #pragma unroll
        for (int kc = 0; kc < 4; kc++) {
            const int cc = kc * 16 + 2 * qc;
            qh[kc][0] = U32(g_qh + r0 + cc);     qh[kc][1] = U32(g_qh + r1 + cc);
            qh[kc][2] = U32(g_qh + r0 + cc + 8); qh[kc][3] = U32(g_qh + r1 + cc + 8);
            ql[kc][0] = U32(g_ql + r0 + cc);     ql[kc][1] = U32(g_ql + r1 + cc);
            ql[kc][2] = U32(g_ql + r0 + cc + 8); ql[kc][3] = U32(g_ql + r1 + cc + 8);
        }
    }

    float o[8][4];
    #pragma unroll
    for (int nd = 0; nd < 8; nd++)
        #pragma unroll
        for (int e = 0; e < 4; e++) o[nd][e] = 0.f;
    float m0 = -1e30f, m1 = -1e30f, l0 = 0.f, l1 = 0.f;

    CP16(sKa, gK);
    CP16(sVfa, gVf);
    CPCOMMIT();

    int buf = 0;
    for (int kt = 0; kt < TSEQ; kt += 32) {
        CPWAIT0();
        __syncthreads();
        if (kt + 32 < TSEQ) {
            const int nb = buf ^ 1;
            CP16(sKa + nb * KBUF, gK + (kt + 32) * DMODEL);
            CP16(sVfa + nb * VBUF, gVf + kt + 32);
            CPCOMMIT();
        }
        const __half* Kb = sKb[buf];
        const __half* Vf = sVf[buf];

        float s[4][4];
        #pragma unroll
        for (int nt = 0; nt < 4; nt++) {
            #pragma unroll
            for (int e = 0; e < 4; e++) s[nt][e] = 0.f;
            #pragma unroll
            for (int kc = 0; kc < 4; kc++) {
                const int off = (nt * 8 + qr) * KS + kc * 16 + 2 * qc;
                uint32_t b0 = U32(Kb + off), b1 = U32(Kb + off + 8);
                MMA_F16(s[nt], ql[kc][0], ql[kc][1], ql[kc][2], ql[kc][3], b0, b1);
                MMA_F16(s[nt], qh[kc][0], qh[kc][1], qh[kc][2], qh[kc][3], b0, b1);
            }
            #pragma unroll
            for (int e = 0; e < 4; e++) s[nt][e] *= 0.125f;
        }

        float t0 = -1e30f, t1 = -1e30f;
        #pragma unroll
        for (int nt = 0; nt < 4; nt++) {
            t0 = fmaxf(t0, fmaxf(s[nt][0], s[nt][1]));
            t1 = fmaxf(t1, fmaxf(s[nt][2], s[nt][3]));
        }
        t0 = fmaxf(t0, __shfl_xor_sync(0xffffffffu, t0, 1));
        t0 = fmaxf(t0, __shfl_xor_sync(0xffffffffu, t0, 2));
        t1 = fmaxf(t1, __shfl_xor_sync(0xffffffffu, t1, 1));
        t1 = fmaxf(t1, __shfl_xor_sync(0xffffffffu, t1, 2));
        float mn0 = fmaxf(m0, t0), mn1 = fmaxf(m1, t1);
        float corr0 = __expf(m0 - mn0), corr1 = __expf(m1 - mn1);
        float sum0 = 0.f, sum1 = 0.f;
        #pragma unroll
        for (int nt = 0; nt < 4; nt++) {
            s[nt][0] = __expf(s[nt][0] - mn0);
            s[nt][1] = __expf(s[nt][1] - mn0);
            s[nt][2] = __expf(s[nt][2] - mn1);
            s[nt][3] = __expf(s[nt][3] - mn1);
            sum0 += s[nt][0] + s[nt][1];
            sum1 += s[nt][2] + s[nt][3];
        }
        sum0 += __shfl_xor_sync(0xffffffffu, sum0, 1);
        sum0 += __shfl_xor_sync(0xffffffffu, sum0, 2);
        sum1 += __shfl_xor_sync(0xffffffffu, sum1, 1);
        sum1 += __shfl_xor_sync(0xffffffffu, sum1, 2);
        l0 = l0 * corr0 + sum0;
        l1 = l1 * corr1 + sum1;
        m0 = mn0; m1 = mn1;
        #pragma unroll
        for (int nd = 0; nd < 8; nd++) {
            o[nd][0] *= corr0; o[nd][1] *= corr0;
            o[nd][2] *= corr1; o[nd][3] *= corr1;
        }

        #pragma unroll
        for (int kc = 0; kc < 2; kc++) {
            uint32_t ah0, al0, ah1, al1, ah2, al2, ah3, al3;
            split2h(s[2*kc][0],     s[2*kc][1],     ah0, al0);
            split2h(s[2*kc][2],     s[2*kc][3],     ah1, al1);
            split2h(s[2*kc + 1][0], s[2*kc + 1][1], ah2, al2);
            split2h(s[2*kc + 1][2], s[2*kc + 1][3], ah3, al3);
            const int k0 = kc * 16 + 2 * qc;
            #pragma unroll
            for (int nd = 0; nd < 8; nd++) {
                const int off = (nd * 8 + qr) * VS + k0;
                uint32_t bh0 = U32(Vf + off), bh1 = U32(Vf + off + 8);
                MMA_F16(o[nd], al0, al1, al2, al3, bh0, bh1);
                MMA_F16(o[nd], ah0, ah1, ah2, ah3, bh0, bh1);
            }
        }
        buf ^= 1;
    }

    // ---- epilogue: normalize, gate, split -> final GEMM A operand ----
    const float inv0 = 1.f / l0, inv1 = 1.f / l1;
    const size_t r0 = (size_t)(b * TSEQ + qb + qr) * DMODEL + h * DHEAD;
    const size_t r1 = r0 + (size_t)8 * DMODEL;
    #pragma unroll
    for (int nd = 0; nd < 8; nd++) {
        const int cc = nd * 8 + 2 * qc;
        float2 gt0 = *(const float2*)(g_gate + r0 + cc);
        float2 gt1 = *(const float2*)(g_gate + r1 + cc);
        float a0 = o[nd][0] * inv0 * gt0.x, a1 = o[nd][1] * inv0 * gt0.y;
        float a2 = o[nd][2] * inv1 * gt1.x, a3 = o[nd][3] * inv1 * gt1.y;
        uint32_t h2, l2;
        split2h(a0, a1, h2, l2);
        *(uint32_t*)(g_ah[0] + r0 + cc) = h2;
        *(uint32_t*)(g_al[0] + r0 + cc) = l2;
        split2h(a2, a3, h2, l2);
        *(uint32_t*)(g_ah[0] + r1 + cc) = h2;
        *(uint32_t*)(g_al[0] + r1 + cc) = l2;
    }
}

// ---------------- launch (only harness pointers cross the boundary) ----------
extern "C" void kernel_launch(void* const* d_in, const int* in_sizes, int n_in,
                              void* d_out, int out_size)
{
    const float* x   = (const float*)d_in[0];
    const int*   tok = (const int*)  d_in[1];
    const float* Wr  = (const float*)d_in[2];
    const float* Wk  = (const float*)d_in[3];
    const float* Wv  = (const float*)d_in[4];
    const float* Wo  = (const float*)d_in[5];
    const float* bo  = (const float*)d_in[6];
    const float* tmk = (const float*)d_in[7];
    const float* tmv = (const float*)d_in[8];
    const float* tmr = (const float*)d_in[9];
    float* out = (float*)d_out;

    zero_cnt_kernel<<<(VOCAB + 255) / 256, 256>>>();
    hist_kernel<<<BT / 256, 256>>>(tok);
    topk_gains_kernel<<<1, 256>>>(tmr, tmk, tmv);

    split_w_all<<<(DMODEL * DMODEL) / 256, 256>>>(Wr, Wk, Wv, Wo);
    prep_x012<<<(BT * DMODEL) / 256, 256>>>(x);

    gemm_all<<<dim3(DMODEL / 128, BT / 128, 3), 256>>>(0, nullptr, nullptr);

    attn_f16<<<dim3(TSEQ / 128, NHEAD, BATCH), 256>>>();

    gemm_all<<<dim3(DMODEL / 128, BT / 128, 1), 256>>>(3, bo, out);
}

// round 11
// speedup vs baseline: 3.8676x; 1.0588x over previous
#include <cuda_runtime.h>
#include <cuda_fp16.h>
#include <cstdint>
#include <math.h>

#define BATCH  2
#define TSEQ   2048
#define BT     (BATCH*TSEQ)   // 4096
#define DMODEL 1024
#define NHEAD  16
#define DHEAD  64
#define VOCAB  32000

// ---------------- scratch (device globals; referenced ONLY from device code) ----
__device__ __align__(16) int   g_cnt[VOCAB];
__device__ __align__(16) float g_m[3][DMODEL];
__device__ __align__(16) float g_gate[BT*DMODEL];                       // sigmoid(r)
__device__ __align__(16) __half g_ah[3][BT*DMODEL];                     // A hi (mode3 reuses [0])
__device__ __align__(16) __half g_al1[BT*DMODEL];                       // A lo (k-GEMM only)
__device__ __align__(16) __half g_wh[4][DMODEL*DMODEL];                 // W hi (all 4)
__device__ __align__(16) __half g_wl[DMODEL*DMODEL];                    // W lo (k-GEMM only)
__device__ __align__(16) __half g_qh[BT*DMODEL], g_ql[BT*DMODEL];       // q hi/lo
__device__ __align__(16) __half g_kb[BT*DMODEL];                        // k (binary)
__device__ __align__(16) __half g_vf[BATCH*NHEAD*DHEAD*TSEQ];           // V^T (single fp16)

// ---------------- helpers ----------------
__device__ __forceinline__ void h_split(float x, __half& h, __half& l) {
    h = __float2half_rn(x);
    l = __float2half_rn(x - __half2float(h));
}
__device__ __forceinline__ void split2h(float x, float y, uint32_t& h, uint32_t& l) {
    __half2 hh = __floats2half2_rn(x, y);
    float2 hf = __half22float2(hh);
    __half2 ll = __floats2half2_rn(x - hf.x, y - hf.y);
    h = *(uint32_t*)&hh; l = *(uint32_t*)&ll;
}
__device__ __forceinline__ uint32_t pack2h(float x, float y) {
    __half2 hh = __floats2half2_rn(x, y);
    return *(uint32_t*)&hh;
}
__device__ __forceinline__ uint32_t smem_u32(const void* p) {
    uint32_t a;
    asm("{ .reg .u64 t; cvta.to.shared.u64 t, %1; cvt.u32.u64 %0, t; }" : "=r"(a) : "l"(p));
    return a;
}
#define U32(p) (*reinterpret_cast<const uint32_t*>(p))
#define CP16(dst, src) asm volatile("cp.async.cg.shared.global [%0], [%1], 16;" :: "r"(dst), "l"(src))
#define CPCOMMIT()     asm volatile("cp.async.commit_group;")
#define CPWAIT0()      asm volatile("cp.async.wait_group 0;")

#define MMA_F16(c, a0, a1, a2, a3, b0, b1)                                      \
    asm volatile(                                                               \
        "mma.sync.aligned.m16n8k16.row.col.f32.f16.f16.f32 "                    \
        "{%0,%1,%2,%3}, {%4,%5,%6,%7}, {%8,%9}, {%0,%1,%2,%3};"                 \
        : "+f"((c)[0]), "+f"((c)[1]), "+f"((c)[2]), "+f"((c)[3])                \
        : "r"(a0), "r"(a1), "r"(a2), "r"(a3), "r"(b0), "r"(b1))

// ---------------- kWTA: histogram + top-5 + gains ----------------
__global__ void zero_cnt_kernel() {
    int i = blockIdx.x * blockDim.x + threadIdx.x;
    if (i < VOCAB) g_cnt[i] = 0;
}
__global__ void hist_kernel(const int* __restrict__ tok) {
    int i = blockIdx.x * blockDim.x + threadIdx.x;
    atomicAdd(&g_cnt[tok[i]], 1);
}
__global__ void topk_gains_kernel(const float* __restrict__ tmr,
                                  const float* __restrict__ tmk,
                                  const float* __restrict__ tmv) {
    __shared__ long long skey[256];
    __shared__ int sel[5];
    int tid = threadIdx.x;
    for (int it = 0; it < 5; it++) {
        long long best = -1;
        for (int i = tid; i < VOCAB; i += 256) {
            bool ex = false;
            for (int j = 0; j < it; j++) if (sel[j] == i) ex = true;
            if (ex) continue;
            long long key = (((long long)g_cnt[i]) << 16) | (long long)(VOCAB - 1 - i);
            if (key > best) best = key;
        }
        skey[tid] = best;
        __syncthreads();
        for (int s = 128; s > 0; s >>= 1) {
            if (tid < s && skey[tid + s] > skey[tid]) skey[tid] = skey[tid + s];
            __syncthreads();
        }
        if (tid == 0) sel[it] = VOCAB - 1 - (int)(skey[0] & 0xFFFFLL);
        __syncthreads();
    }
    for (int d = tid; d < DMODEL; d += 256) {
        float g = (g_cnt[d] > 0) ? 0.6f : 1.0f;
        #pragma unroll
        for (int j = 0; j < 5; j++) if (sel[j] == d) g = 1.5f;
        g_m[0][d] = tmr[d] * g;
        g_m[1][d] = tmk[d] * g;
        g_m[2][d] = tmv[d] * g;
    }
}

// ---------------- prep: W hi x4; W lo only for Wk ----------------
__global__ void split_w_all(const float* __restrict__ W0, const float* __restrict__ W1,
                            const float* __restrict__ W2, const float* __restrict__ W3) {
    int i = blockIdx.x * 256 + threadIdx.x;
    const float* Ws[4] = {W0, W1, W2, W3};
    #pragma unroll
    for (int m = 0; m < 4; m++) {
        __half h, l;
        h_split(Ws[m][i], h, l);
        g_wh[m][i] = h;
        if (m == 1) g_wl[i] = l;
    }
}

// ---------------- prep: 3 mixed inputs (A-lo only for k path) ----------------
__global__ void prep_x012(const float* __restrict__ X) {
    int i = blockIdx.x * 256 + threadIdx.x;
    int t = i >> 10, d = i & (DMODEL - 1);
    float xv = X[i];
    float pv = ((t & (TSEQ - 1)) != 0) ? X[i - DMODEL] : 0.f;
    #pragma unroll
    for (int m = 0; m < 3; m++) {
        float mm = g_m[m][d];
        float a = mm * xv + (1.f - mm) * pv;
        __half h, l;
        h_split(a, h, l);
        g_ah[m][i] = h;
        if (m == 1) g_al1[i] = l;
    }
}

// ---------------- fp16 tensor-core GEMM, 2-stage cp.async pipeline -------------
// CTA 128x128, 8 warps (warp tile 64x32), K chunk 16, double-buffered smem.
// Terms: modes 0,2,3 -> 1 MMA (rn(A)*rn(W));  mode 1 -> 3 MMAs (spike accuracy).
// Epilogues: 0 -> g_gate=sigmoid(r) + g_qh/g_ql ; 1 -> spike -> g_kb ;
//            2 -> g_vf transposed ; 3 -> Cout + bias.
#define CH  16
#define SBF 24
#define STG (128 * SBF * 2)   // stage size in bytes
__global__ __launch_bounds__(256)
void gemm_all(int mode_base, const float* __restrict__ bias, float* __restrict__ Cout)
{
    const int mode = mode_base + blockIdx.z;
    const bool t3 = (mode == 1);
    const __half* __restrict__ Ah = g_ah[mode == 3 ? 0 : mode];
    const __half* __restrict__ Al = g_al1;
    const __half* __restrict__ Wh = g_wh[mode];
    const __half* __restrict__ Wl = g_wl;

    __shared__ __align__(16) __half sAh[2][128 * SBF], sAl[2][128 * SBF];
    __shared__ __align__(16) __half sWh[2][128 * SBF], sWl[2][128 * SBF];

    const int tid  = threadIdx.x;
    const int wid  = tid >> 5, lane = tid & 31;
    const int wr   = wid & 1,  wc   = wid >> 1;
    const int qrow = lane >> 2, qc = lane & 3;
    const int bm = blockIdx.y * 128, bn = blockIdx.x * 128;
    const int lr = tid >> 1, cg = (tid & 1) * 8;

    const __half* pAh = Ah + (size_t)(bm + lr) * DMODEL + cg;
    const __half* pAl = Al + (size_t)(bm + lr) * DMODEL + cg;
    const __half* pWh = Wh + (size_t)(bn + lr) * DMODEL + cg;
    const __half* pWl = Wl + (size_t)(bn + lr) * DMODEL + cg;
    const uint32_t dAh = smem_u32(sAh) + (lr * SBF + cg) * 2;
    const uint32_t dAl = smem_u32(sAl) + (lr * SBF + cg) * 2;
    const uint32_t dWh = smem_u32(sWh) + (lr * SBF + cg) * 2;
    const uint32_t dWl = smem_u32(sWl) + (lr * SBF + cg) * 2;

    float acc[4][4][4];
    #pragma unroll
    for (int mi = 0; mi < 4; mi++)
        #pragma unroll
        for (int ni = 0; ni < 4; ni++)
            #pragma unroll
            for (int e = 0; e < 4; e++) acc[mi][ni][e] = 0.f;

    CP16(dAh, pAh); CP16(dWh, pWh);
    if (t3) { CP16(dAl, pAl); CP16(dWl, pWl); }
    CPCOMMIT();

    for (int c = 0; c < DMODEL / CH; c++) {
        CPWAIT0();
        __syncthreads();
        if (c + 1 < DMODEL / CH) {
            const uint32_t so = ((c + 1) & 1) * STG;
            const int go = (c + 1) * CH;
            CP16(dAh + so, pAh + go); CP16(dWh + so, pWh + go);
            if (t3) { CP16(dAl + so, pAl + go); CP16(dWl + so, pWl + go); }
            CPCOMMIT();
        }
        const __half* cAh = sAh[c & 1];
        const __half* cAl = sAl[c & 1];
        const __half* cWh = sWh[c & 1];
        const __half* cWl = sWl[c & 1];

        const int k0 = 2 * qc;
        uint32_t bh[4][2], bl[4][2];
        #pragma unroll
        for (int ni = 0; ni < 4; ni++) {
            const int off = (wc * 32 + ni * 8 + qrow) * SBF + k0;
            bh[ni][0] = U32(cWh + off); bh[ni][1] = U32(cWh + off + 8);
            if (t3) { bl[ni][0] = U32(cWl + off); bl[ni][1] = U32(cWl + off + 8); }
        }
        #pragma unroll
        for (int mi = 0; mi < 4; mi++) {
            const int off = (wr * 64 + mi * 16 + qrow) * SBF + k0;
            uint32_t ah0 = U32(cAh + off),     ah1 = U32(cAh + off + 8 * SBF);
            uint32_t ah2 = U32(cAh + off + 8), ah3 = U32(cAh + off + 8 * SBF + 8);
            #pragma unroll
            for (int ni = 0; ni < 4; ni++) {
                if (t3) {
                    uint32_t al0 = U32(cAl + off),     al1 = U32(cAl + off + 8 * SBF);
                    uint32_t al2 = U32(cAl + off + 8), al3 = U32(cAl + off + 8 * SBF + 8);
                    MMA_F16(acc[mi][ni], al0, al1, al2, al3, bh[ni][0], bh[ni][1]);
                    MMA_F16(acc[mi][ni], ah0, ah1, ah2, ah3, bl[ni][0], bl[ni][1]);
                }
                MMA_F16(acc[mi][ni], ah0, ah1, ah2, ah3, bh[ni][0], bh[ni][1]);
            }
        }
    }

    #pragma unroll
    for (int mi = 0; mi < 4; mi++) {
        const int row0 = bm + wr * 64 + mi * 16 + qrow;
        #pragma unroll
        for (int ni = 0; ni < 4; ni++) {
            const int col = bn + wc * 32 + ni * 8 + 2 * qc;
            float d0 = acc[mi][ni][0], d1 = acc[mi][ni][1];
            float d2 = acc[mi][ni][2], d3 = acc[mi][ni][3];
            if (mode == 0) {
                *(float2*)(g_gate + (size_t)row0 * DMODEL + col) =
                    make_float2(1.f / (1.f + __expf(-d0)), 1.f / (1.f + __expf(-d1)));
                *(float2*)(g_gate + (size_t)(row0 + 8) * DMODEL + col) =
                    make_float2(1.f / (1.f + __expf(-d2)), 1.f / (1.f + __expf(-d3)));
                uint32_t h, l;
                split2h(d0, d1, h, l);
                *(uint32_t*)(g_qh + (size_t)row0 * DMODEL + col) = h;
                *(uint32_t*)(g_ql + (size_t)row0 * DMODEL + col) = l;
                split2h(d2, d3, h, l);
                *(uint32_t*)(g_qh + (size_t)(row0 + 8) * DMODEL + col) = h;
                *(uint32_t*)(g_ql + (size_t)(row0 + 8) * DMODEL + col) = l;
            } else if (mode == 1) {
                __half2 s;
                s.x = __float2half((d0 > 0.5f) ? 1.f : 0.f);
                s.y = __float2half((d1 > 0.5f) ? 1.f : 0.f);
                *(__half2*)(g_kb + (size_t)row0 * DMODEL + col) = s;
                s.x = __float2half((d2 > 0.5f) ? 1.f : 0.f);
                s.y = __float2half((d3 > 0.5f) ? 1.f : 0.f);
                *(__half2*)(g_kb + (size_t)(row0 + 8) * DMODEL + col) = s;
            } else if (mode == 2) {
                const int b  = row0 >> 11, tl = row0 & (TSEQ - 1);
                const int hh = col >> 6,  dd = col & (DHEAD - 1);
                const size_t base = ((size_t)(b * NHEAD + hh)) * DHEAD;
                g_vf[(base + dd) * TSEQ + tl]         = __float2half(d0);
                g_vf[(base + dd + 1) * TSEQ + tl]     = __float2half(d1);
                g_vf[(base + dd) * TSEQ + tl + 8]     = __float2half(d2);
                g_vf[(base + dd + 1) * TSEQ + tl + 8] = __float2half(d3);
            } else {
                float b0 = bias[col], b1 = bias[col + 1];
                *(float2*)(Cout + (size_t)row0 * DMODEL + col)       = make_float2(d0 + b0, d1 + b1);
                *(float2*)(Cout + (size_t)(row0 + 8) * DMODEL + col) = make_float2(d2 + b0, d3 + b1);
            }
        }
    }
}

// ---------------- flash attention: fp16, register P-reuse, cp.async ------------
// 256 thr / 8 warps, 128 q rows/block, one (b,h), 32-key tiles.
// QK: 2 MMAs (q hi/lo fp16; k binary = exact). PV: 1 MMA (single-fp16 P).
// Epilogue fuses receptance gating; writes final GEMM's single-fp16 A operand.
#define KS 72
#define VS 40
__global__ __launch_bounds__(256)
void attn_f16()
{
    __shared__ __align__(16) __half sKb[2][32 * KS];
    __shared__ __align__(16) __half sVf[2][64 * VS];

    const int tid = threadIdx.x, warp = tid >> 5, lane = tid & 31;
    const int qr = lane >> 2, qc = lane & 3;
    const int b = blockIdx.z, h = blockIdx.y;
    const int qb = blockIdx.x * 128 + warp * 16;

    const int kkey = tid >> 3, kdg = (tid & 7) * 8;
    const int vd = tid >> 2,   vkg = (tid & 3) * 8;
    const size_t vbase = ((size_t)(b * NHEAD + h)) * DHEAD * TSEQ;
    const __half* gK  = g_kb + (size_t)(b * TSEQ + kkey) * DMODEL + h * DHEAD + kdg;
    const __half* gVf = g_vf + vbase + (size_t)vd * TSEQ + vkg;
    const uint32_t sKa  = smem_u32(sKb) + (kkey * KS + kdg) * 2;
    const uint32_t sVfa = smem_u32(sVf) + (vd * VS + vkg) * 2;
    const uint32_t KBUF = 32 * KS * 2, VBUF = 64 * VS * 2;

    uint32_t qh[4][4], ql[4][4];
    {
        const size_t r0 = (size_t)(b * TSEQ + qb + qr) * DMODEL + h * DHEAD;
        const size_t r1 = r0 + (size_t)8 * DMODEL;
        #pragma unroll
        for (int kc = 0; kc < 4; kc++) {
            const int cc = kc * 16 + 2 * qc;
            qh[kc][0] = U32(g_qh + r0 + cc);     qh[kc][1] = U32(g_qh + r1 + cc);
            qh[kc][2] = U32(g_qh + r0 + cc + 8); qh[kc][3] = U32(g_qh + r1 + cc + 8);
            ql[kc][0] = U32(g_ql + r0 + cc);     ql[kc][1] = U32(g_ql + r1 + cc);
            ql[kc][2] = U32(g_ql + r0 + cc + 8); ql[kc][3] = U32(g_ql + r1 + cc + 8);
        }
    }

    float o[8][4];
    #pragma unroll
    for (int nd = 0; nd < 8; nd++)
        #pragma unroll
        for (int e = 0; e < 4; e++) o[nd][e] = 0.f;
    float m0 = -1e30f, m1 = -1e30f, l0 = 0.f, l1 = 0.f;

    CP16(sKa, gK);
    CP16(sVfa, gVf);
    CPCOMMIT();

    int buf = 0;
    for (int kt = 0; kt < TSEQ; kt += 32) {
        CPWAIT0();
        __syncthreads();
        if (kt + 32 < TSEQ) {
            const int nb = buf ^ 1;
            CP16(sKa + nb * KBUF, gK + (kt + 32) * DMODEL);
            CP16(sVfa + nb * VBUF, gVf + kt + 32);
            CPCOMMIT();
        }
        const __half* Kb = sKb[buf];
        const __half* Vf = sVf[buf];

        float s[4][4];
        #pragma unroll
        for (int nt = 0; nt < 4; nt++) {
            #pragma unroll
            for (int e = 0; e < 4; e++) s[nt][e] = 0.f;
            #pragma unroll
            for (int kc = 0; kc < 4; kc++) {
                const int off = (nt * 8 + qr) * KS + kc * 16 + 2 * qc;
                uint32_t b0 = U32(Kb + off), b1 = U32(Kb + off + 8);
                MMA_F16(s[nt], ql[kc][0], ql[kc][1], ql[kc][2], ql[kc][3], b0, b1);
                MMA_F16(s[nt], qh[kc][0], qh[kc][1], qh[kc][2], qh[kc][3], b0, b1);
            }
            #pragma unroll
            for (int e = 0; e < 4; e++) s[nt][e] *= 0.125f;
        }

        float t0 = -1e30f, t1 = -1e30f;
        #pragma unroll
        for (int nt = 0; nt < 4; nt++) {
            t0 = fmaxf(t0, fmaxf(s[nt][0], s[nt][1]));
            t1 = fmaxf(t1, fmaxf(s[nt][2], s[nt][3]));
        }
        t0 = fmaxf(t0, __shfl_xor_sync(0xffffffffu, t0, 1));
        t0 = fmaxf(t0, __shfl_xor_sync(0xffffffffu, t0, 2));
        t1 = fmaxf(t1, __shfl_xor_sync(0xffffffffu, t1, 1));
        t1 = fmaxf(t1, __shfl_xor_sync(0xffffffffu, t1, 2));
        float mn0 = fmaxf(m0, t0), mn1 = fmaxf(m1, t1);
        float corr0 = __expf(m0 - mn0), corr1 = __expf(m1 - mn1);
        float sum0 = 0.f, sum1 = 0.f;
        #pragma unroll
        for (int nt = 0; nt < 4; nt++) {
            s[nt][0] = __expf(s[nt][0] - mn0);
            s[nt][1] = __expf(s[nt][1] - mn0);
            s[nt][2] = __expf(s[nt][2] - mn1);
            s[nt][3] = __expf(s[nt][3] - mn1);
            sum0 += s[nt][0] + s[nt][1];
            sum1 += s[nt][2] + s[nt][3];
        }
        sum0 += __shfl_xor_sync(0xffffffffu, sum0, 1);
        sum0 += __shfl_xor_sync(0xffffffffu, sum0, 2);
        sum1 += __shfl_xor_sync(0xffffffffu, sum1, 1);
        sum1 += __shfl_xor_sync(0xffffffffu, sum1, 2);
        l0 = l0 * corr0 + sum0;
        l1 = l1 * corr1 + sum1;
        m0 = mn0; m1 = mn1;
        #pragma unroll
        for (int nd = 0; nd < 8; nd++) {
            o[nd][0] *= corr0; o[nd][1] *= corr0;
            o[nd][2] *= corr1; o[nd][3] *= corr1;
        }

        // ---- O += P V : single-fp16 P, 1 MMA per (kc, nd) ----
        #pragma unroll
        for (int kc = 0; kc < 2; kc++) {
            uint32_t a0 = pack2h(s[2*kc][0],     s[2*kc][1]);
            uint32_t a1 = pack2h(s[2*kc][2],     s[2*kc][3]);
            uint32_t a2 = pack2h(s[2*kc + 1][0], s[2*kc + 1][1]);
            uint32_t a3 = pack2h(s[2*kc + 1][2], s[2*kc + 1][3]);
            const int k0 = kc * 16 + 2 * qc;
            #pragma unroll
            for (int nd = 0; nd < 8; nd++) {
                const int off = (nd * 8 + qr) * VS + k0;
                uint32_t bh0 = U32(Vf + off), bh1 = U32(Vf + off + 8);
                MMA_F16(o[nd], a0, a1, a2, a3, bh0, bh1);
            }
        }
        buf ^= 1;
    }

    // ---- epilogue: normalize, gate -> final GEMM single-fp16 A operand ----
    const float inv0 = 1.f / l0, inv1 = 1.f / l1;
    const size_t r0 = (size_t)(b * TSEQ + qb + qr) * DMODEL + h * DHEAD;
    const size_t r1 = r0 + (size_t)8 * DMODEL;
    #pragma unroll
    for (int nd = 0; nd < 8; nd++) {
        const int cc = nd * 8 + 2 * qc;
        float2 gt0 = *(const float2*)(g_gate + r0 + cc);
        float2 gt1 = *(const float2*)(g_gate + r1 + cc);
        *(uint32_t*)(g_ah[0] + r0 + cc) =
            pack2h(o[nd][0] * inv0 * gt0.x, o[nd][1] * inv0 * gt0.y);
        *(uint32_t*)(g_ah[0] + r1 + cc) =
            pack2h(o[nd][2] * inv1 * gt1.x, o[nd][3] * inv1 * gt1.y);
    }
}

// ---------------- launch (only harness pointers cross the boundary) ----------
extern "C" void kernel_launch(void* const* d_in, const int* in_sizes, int n_in,
                              void* d_out, int out_size)
{
    const float* x   = (const float*)d_in[0];
    const int*   tok = (const int*)  d_in[1];
    const float* Wr  = (const float*)d_in[2];
    const float* Wk  = (const float*)d_in[3];
    const float* Wv  = (const float*)d_in[4];
    const float* Wo  = (const float*)d_in[5];
    const float* bo  = (const float*)d_in[6];
    const float* tmk = (const float*)d_in[7];
    const float* tmv = (const float*)d_in[8];
    const float* tmr = (const float*)d_in[9];
    float* out = (float*)d_out;

    zero_cnt_kernel<<<(VOCAB + 255) / 256, 256>>>();
    hist_kernel<<<BT / 256, 256>>>(tok);
    topk_gains_kernel<<<1, 256>>>(tmr, tmk, tmv);

    split_w_all<<<(DMODEL * DMODEL) / 256, 256>>>(Wr, Wk, Wv, Wo);
    prep_x012<<<(BT * DMODEL) / 256, 256>>>(x);

    gemm_all<<<dim3(DMODEL / 128, BT / 128, 3), 256>>>(0, nullptr, nullptr);

    attn_f16<<<dim3(TSEQ / 128, NHEAD, BATCH), 256>>>();

    gemm_all<<<dim3(DMODEL / 128, BT / 128, 1), 256>>>(3, bo, out);
}

// round 12
// speedup vs baseline: 5.0136x; 1.2963x over previous
#include <cuda_runtime.h>
#include <cuda_fp16.h>
#include <cstdint>
#include <math.h>

#define BATCH  2
#define TSEQ   2048
#define BT     (BATCH*TSEQ)   // 4096
#define DMODEL 1024
#define NHEAD  16
#define DHEAD  64
#define VOCAB  32000

// ---------------- scratch (device globals; referenced ONLY from device code) ----
__device__ __align__(16) int   g_cnt[VOCAB];
__device__ __align__(16) float g_m[3][DMODEL];
__device__ __align__(16) float g_gate[BT*DMODEL];                       // sigmoid(r)
__device__ __align__(16) __half g_ah[3][BT*DMODEL];                     // A hi (mode3 reuses [0])
__device__ __align__(16) __half g_al1[BT*DMODEL];                       // A lo (k-GEMM only)
__device__ __align__(16) __half g_wh[4][DMODEL*DMODEL];                 // W hi (all 4)
__device__ __align__(16) __half g_wl[DMODEL*DMODEL];                    // W lo (k-GEMM only)
__device__ __align__(16) __half g_qs[BT*DMODEL];                        // q*0.125 (fp16)
__device__ __align__(16) __half g_kb[BT*DMODEL];                        // k (binary)
__device__ __align__(16) __half g_vf[BATCH*NHEAD*DHEAD*TSEQ];           // V^T (single fp16)

// ---------------- helpers ----------------
__device__ __forceinline__ void h_split(float x, __half& h, __half& l) {
    h = __float2half_rn(x);
    l = __float2half_rn(x - __half2float(h));
}
__device__ __forceinline__ uint32_t pack2h(float x, float y) {
    __half2 hh = __floats2half2_rn(x, y);
    return *(uint32_t*)&hh;
}
__device__ __forceinline__ uint32_t smem_u32(const void* p) {
    uint32_t a;
    asm("{ .reg .u64 t; cvta.to.shared.u64 t, %1; cvt.u32.u64 %0, t; }" : "=r"(a) : "l"(p));
    return a;
}
#define U32(p) (*reinterpret_cast<const uint32_t*>(p))
#define CP16(dst, src) asm volatile("cp.async.cg.shared.global [%0], [%1], 16;" :: "r"(dst), "l"(src))
#define CPCOMMIT()     asm volatile("cp.async.commit_group;")
#define CPWAIT0()      asm volatile("cp.async.wait_group 0;")

#define MMA_F16(c, a0, a1, a2, a3, b0, b1)                                      \
    asm volatile(                                                               \
        "mma.sync.aligned.m16n8k16.row.col.f32.f16.f16.f32 "                    \
        "{%0,%1,%2,%3}, {%4,%5,%6,%7}, {%8,%9}, {%0,%1,%2,%3};"                 \
        : "+f"((c)[0]), "+f"((c)[1]), "+f"((c)[2]), "+f"((c)[3])                \
        : "r"(a0), "r"(a1), "r"(a2), "r"(a3), "r"(b0), "r"(b1))

// ---------------- kWTA: histogram + top-5 + gains ----------------
__global__ void zero_cnt_kernel() {
    int i = blockIdx.x * blockDim.x + threadIdx.x;
    if (i < VOCAB) g_cnt[i] = 0;
}
__global__ void hist_kernel(const int* __restrict__ tok) {
    int i = blockIdx.x * blockDim.x + threadIdx.x;
    atomicAdd(&g_cnt[tok[i]], 1);
}
__global__ void topk_gains_kernel(const float* __restrict__ tmr,
                                  const float* __restrict__ tmk,
                                  const float* __restrict__ tmv) {
    __shared__ long long skey[256];
    __shared__ int sel[5];
    int tid = threadIdx.x;
    for (int it = 0; it < 5; it++) {
        long long best = -1;
        for (int i = tid; i < VOCAB; i += 256) {
            bool ex = false;
            for (int j = 0; j < it; j++) if (sel[j] == i) ex = true;
            if (ex) continue;
            long long key = (((long long)g_cnt[i]) << 16) | (long long)(VOCAB - 1 - i);
            if (key > best) best = key;
        }
        skey[tid] = best;
        __syncthreads();
        for (int s = 128; s > 0; s >>= 1) {
            if (tid < s && skey[tid + s] > skey[tid]) skey[tid] = skey[tid + s];
            __syncthreads();
        }
        if (tid == 0) sel[it] = VOCAB - 1 - (int)(skey[0] & 0xFFFFLL);
        __syncthreads();
    }
    for (int d = tid; d < DMODEL; d += 256) {
        float g = (g_cnt[d] > 0) ? 0.6f : 1.0f;
        #pragma unroll
        for (int j = 0; j < 5; j++) if (sel[j] == d) g = 1.5f;
        g_m[0][d] = tmr[d] * g;
        g_m[1][d] = tmk[d] * g;
        g_m[2][d] = tmv[d] * g;
    }
}

// ---------------- prep: W hi x4; W lo only for Wk ----------------
__global__ void split_w_all(const float* __restrict__ W0, const float* __restrict__ W1,
                            const float* __restrict__ W2, const float* __restrict__ W3) {
    int i = blockIdx.x * 256 + threadIdx.x;
    const float* Ws[4] = {W0, W1, W2, W3};
    #pragma unroll
    for (int m = 0; m < 4; m++) {
        __half h, l;
        h_split(Ws[m][i], h, l);
        g_wh[m][i] = h;
        if (m == 1) g_wl[i] = l;
    }
}

// ---------------- prep: 3 mixed inputs (A-lo only for k path) ----------------
__global__ void prep_x012(const float* __restrict__ X) {
    int i = blockIdx.x * 256 + threadIdx.x;
    int t = i >> 10, d = i & (DMODEL - 1);
    float xv = X[i];
    float pv = ((t & (TSEQ - 1)) != 0) ? X[i - DMODEL] : 0.f;
    #pragma unroll
    for (int m = 0; m < 3; m++) {
        float mm = g_m[m][d];
        float a = mm * xv + (1.f - mm) * pv;
        __half h, l;
        h_split(a, h, l);
        g_ah[m][i] = h;
        if (m == 1) g_al1[i] = l;
    }
}

// ================= 1-term fp16 GEMM (modes 0/2/3), K-chunk 32 ==================
// CTA 128x128, 8 warps (64x32 warp tile), double-buffered cp.async, 32 chunks.
#define CH1  32
#define SB1  40
#define STG1 (128 * SB1 * 2)   // stage bytes
__global__ __launch_bounds__(256)
void gemm_1t(int modeA, int modeB, const float* __restrict__ bias, float* __restrict__ Cout)
{
    const int mode = blockIdx.z ? modeB : modeA;
    const __half* __restrict__ Ah = g_ah[mode == 3 ? 0 : mode];
    const __half* __restrict__ Wh = g_wh[mode];

    __shared__ __align__(16) __half sAh[2][128 * SB1], sWh[2][128 * SB1];

    const int tid  = threadIdx.x;
    const int wid  = tid >> 5, lane = tid & 31;
    const int wr   = wid & 1,  wc   = wid >> 1;
    const int qrow = lane >> 2, qc = lane & 3;
    const int bm = blockIdx.y * 128, bn = blockIdx.x * 128;
    const int lr = tid >> 1, cg = (tid & 1) * 16;

    const __half* pAh = Ah + (size_t)(bm + lr) * DMODEL + cg;
    const __half* pWh = Wh + (size_t)(bn + lr) * DMODEL + cg;
    const uint32_t dAh = smem_u32(sAh) + (lr * SB1 + cg) * 2;
    const uint32_t dWh = smem_u32(sWh) + (lr * SB1 + cg) * 2;

    float acc[4][4][4];
    #pragma unroll
    for (int mi = 0; mi < 4; mi++)
        #pragma unroll
        for (int ni = 0; ni < 4; ni++)
            #pragma unroll
            for (int e = 0; e < 4; e++) acc[mi][ni][e] = 0.f;

    CP16(dAh, pAh); CP16(dAh + 16, pAh + 8);
    CP16(dWh, pWh); CP16(dWh + 16, pWh + 8);
    CPCOMMIT();

    for (int c = 0; c < DMODEL / CH1; c++) {
        CPWAIT0();
        __syncthreads();
        if (c + 1 < DMODEL / CH1) {
            const uint32_t so = ((c + 1) & 1) * STG1;
            const int go = (c + 1) * CH1;
            CP16(dAh + so, pAh + go); CP16(dAh + so + 16, pAh + go + 8);
            CP16(dWh + so, pWh + go); CP16(dWh + so + 16, pWh + go + 8);
            CPCOMMIT();
        }
        const __half* cAh = sAh[c & 1];
        const __half* cWh = sWh[c & 1];

        #pragma unroll
        for (int ks = 0; ks < 2; ks++) {
            const int k0 = ks * 16 + 2 * qc;
            uint32_t bh[4][2];
            #pragma unroll
            for (int ni = 0; ni < 4; ni++) {
                const int off = (wc * 32 + ni * 8 + qrow) * SB1 + k0;
                bh[ni][0] = U32(cWh + off); bh[ni][1] = U32(cWh + off + 8);
            }
            #pragma unroll
            for (int mi = 0; mi < 4; mi++) {
                const int off = (wr * 64 + mi * 16 + qrow) * SB1 + k0;
                uint32_t a0 = U32(cAh + off),     a1 = U32(cAh + off + 8 * SB1);
                uint32_t a2 = U32(cAh + off + 8), a3 = U32(cAh + off + 8 * SB1 + 8);
                #pragma unroll
                for (int ni = 0; ni < 4; ni++)
                    MMA_F16(acc[mi][ni], a0, a1, a2, a3, bh[ni][0], bh[ni][1]);
            }
        }
    }

    #pragma unroll
    for (int mi = 0; mi < 4; mi++) {
        const int row0 = bm + wr * 64 + mi * 16 + qrow;
        #pragma unroll
        for (int ni = 0; ni < 4; ni++) {
            const int col = bn + wc * 32 + ni * 8 + 2 * qc;
            float d0 = acc[mi][ni][0], d1 = acc[mi][ni][1];
            float d2 = acc[mi][ni][2], d3 = acc[mi][ni][3];
            if (mode == 0) {
                *(float2*)(g_gate + (size_t)row0 * DMODEL + col) =
                    make_float2(1.f / (1.f + __expf(-d0)), 1.f / (1.f + __expf(-d1)));
                *(float2*)(g_gate + (size_t)(row0 + 8) * DMODEL + col) =
                    make_float2(1.f / (1.f + __expf(-d2)), 1.f / (1.f + __expf(-d3)));
                // q pre-scaled by 1/sqrt(Dh)=0.125 (exact power-of-2 in fp16)
                *(uint32_t*)(g_qs + (size_t)row0 * DMODEL + col)       = pack2h(d0 * 0.125f, d1 * 0.125f);
                *(uint32_t*)(g_qs + (size_t)(row0 + 8) * DMODEL + col) = pack2h(d2 * 0.125f, d3 * 0.125f);
            } else if (mode == 2) {
                const int b  = row0 >> 11, tl = row0 & (TSEQ - 1);
                const int hh = col >> 6,  dd = col & (DHEAD - 1);
                const size_t base = ((size_t)(b * NHEAD + hh)) * DHEAD;
                g_vf[(base + dd) * TSEQ + tl]         = __float2half(d0);
                g_vf[(base + dd + 1) * TSEQ + tl]     = __float2half(d1);
                g_vf[(base + dd) * TSEQ + tl + 8]     = __float2half(d2);
                g_vf[(base + dd + 1) * TSEQ + tl + 8] = __float2half(d3);
            } else {
                float b0 = bias[col], b1 = bias[col + 1];
                *(float2*)(Cout + (size_t)row0 * DMODEL + col)       = make_float2(d0 + b0, d1 + b1);
                *(float2*)(Cout + (size_t)(row0 + 8) * DMODEL + col) = make_float2(d2 + b0, d3 + b1);
            }
        }
    }
}

// ================= 3-term fp16 GEMM (mode 1: k, spike epilogue) ================
#define CH3  16
#define SB3  24
#define STG3 (128 * SB3 * 2)
__global__ __launch_bounds__(256)
void gemm_3t()
{
    const __half* __restrict__ Ah = g_ah[1];
    const __half* __restrict__ Al = g_al1;
    const __half* __restrict__ Wh = g_wh[1];
    const __half* __restrict__ Wl = g_wl;

    __shared__ __align__(16) __half sAh[2][128 * SB3], sAl[2][128 * SB3];
    __shared__ __align__(16) __half sWh[2][128 * SB3], sWl[2][128 * SB3];

    const int tid  = threadIdx.x;
    const int wid  = tid >> 5, lane = tid & 31;
    const int wr   = wid & 1,  wc   = wid >> 1;
    const int qrow = lane >> 2, qc = lane & 3;
    const int bm = blockIdx.y * 128, bn = blockIdx.x * 128;
    const int lr = tid >> 1, cg = (tid & 1) * 8;

    const __half* pAh = Ah + (size_t)(bm + lr) * DMODEL + cg;
    const __half* pAl = Al + (size_t)(bm + lr) * DMODEL + cg;
    const __half* pWh = Wh + (size_t)(bn + lr) * DMODEL + cg;
    const __half* pWl = Wl + (size_t)(bn + lr) * DMODEL + cg;
    const uint32_t dAh = smem_u32(sAh) + (lr * SB3 + cg) * 2;
    const uint32_t dAl = smem_u32(sAl) + (lr * SB3 + cg) * 2;
    const uint32_t dWh = smem_u32(sWh) + (lr * SB3 + cg) * 2;
    const uint32_t dWl = smem_u32(sWl) + (lr * SB3 + cg) * 2;

    float acc[4][4][4];
    #pragma unroll
    for (int mi = 0; mi < 4; mi++)
        #pragma unroll
        for (int ni = 0; ni < 4; ni++)
            #pragma unroll
            for (int e = 0; e < 4; e++) acc[mi][ni][e] = 0.f;

    CP16(dAh, pAh); CP16(dAl, pAl); CP16(dWh, pWh); CP16(dWl, pWl);
    CPCOMMIT();

    for (int c = 0; c < DMODEL / CH3; c++) {
        CPWAIT0();
        __syncthreads();
        if (c + 1 < DMODEL / CH3) {
            const uint32_t so = ((c + 1) & 1) * STG3;
            const int go = (c + 1) * CH3;
            CP16(dAh + so, pAh + go); CP16(dAl + so, pAl + go);
            CP16(dWh + so, pWh + go); CP16(dWl + so, pWl + go);
            CPCOMMIT();
        }
        const __half* cAh = sAh[c & 1];
        const __half* cAl = sAl[c & 1];
        const __half* cWh = sWh[c & 1];
        const __half* cWl = sWl[c & 1];

        const int k0 = 2 * qc;
        uint32_t bh[4][2], bl[4][2];
        #pragma unroll
        for (int ni = 0; ni < 4; ni++) {
            const int off = (wc * 32 + ni * 8 + qrow) * SB3 + k0;
            bh[ni][0] = U32(cWh + off); bh[ni][1] = U32(cWh + off + 8);
            bl[ni][0] = U32(cWl + off); bl[ni][1] = U32(cWl + off + 8);
        }
        #pragma unroll
        for (int mi = 0; mi < 4; mi++) {
            const int off = (wr * 64 + mi * 16 + qrow) * SB3 + k0;
            uint32_t ah0 = U32(cAh + off),     ah1 = U32(cAh + off + 8 * SB3);
            uint32_t ah2 = U32(cAh + off + 8), ah3 = U32(cAh + off + 8 * SB3 + 8);
            uint32_t al0 = U32(cAl + off),     al1 = U32(cAl + off + 8 * SB3);
            uint32_t al2 = U32(cAl + off + 8), al3 = U32(cAl + off + 8 * SB3 + 8);
            #pragma unroll
            for (int ni = 0; ni < 4; ni++) {
                MMA_F16(acc[mi][ni], al0, al1, al2, al3, bh[ni][0], bh[ni][1]);
                MMA_F16(acc[mi][ni], ah0, ah1, ah2, ah3, bl[ni][0], bl[ni][1]);
                MMA_F16(acc[mi][ni], ah0, ah1, ah2, ah3, bh[ni][0], bh[ni][1]);
            }
        }
    }

    #pragma unroll
    for (int mi = 0; mi < 4; mi++) {
        const int row0 = bm + wr * 64 + mi * 16 + qrow;
        #pragma unroll
        for (int ni = 0; ni < 4; ni++) {
            const int col = bn + wc * 32 + ni * 8 + 2 * qc;
            float d0 = acc[mi][ni][0], d1 = acc[mi][ni][1];
            float d2 = acc[mi][ni][2], d3 = acc[mi][ni][3];
            __half2 s;
            s.x = __float2half((d0 > 0.5f) ? 1.f : 0.f);
            s.y = __float2half((d1 > 0.5f) ? 1.f : 0.f);
            *(__half2*)(g_kb + (size_t)row0 * DMODEL + col) = s;
            s.x = __float2half((d2 > 0.5f) ? 1.f : 0.f);
            s.y = __float2half((d3 > 0.5f) ? 1.f : 0.f);
            *(__half2*)(g_kb + (size_t)(row0 + 8) * DMODEL + col) = s;
        }
    }
}

// ---------------- flash attention: fp16, 1-MMA QK, 1-MMA PV, cp.async ----------
// 256 thr / 8 warps, 128 q rows/block, one (b,h), 32-key tiles.
// q pre-scaled by 0.125; k binary; V single fp16; P single fp16.
#define KS 72
#define VS 40
__global__ __launch_bounds__(256)
void attn_f16()
{
    __shared__ __align__(16) __half sKb[2][32 * KS];
    __shared__ __align__(16) __half sVf[2][64 * VS];

    const int tid = threadIdx.x, warp = tid >> 5, lane = tid & 31;
    const int qr = lane >> 2, qc = lane & 3;
    const int b = blockIdx.z, h = blockIdx.y;
    const int qb = blockIdx.x * 128 + warp * 16;

    const int kkey = tid >> 3, kdg = (tid & 7) * 8;
    const int vd = tid >> 2,   vkg = (tid & 3) * 8;
    const size_t vbase = ((size_t)(b * NHEAD + h)) * DHEAD * TSEQ;
    const __half* gK  = g_kb + (size_t)(b * TSEQ + kkey) * DMODEL + h * DHEAD + kdg;
    const __half* gVf = g_vf + vbase + (size_t)vd * TSEQ + vkg;
    const uint32_t sKa  = smem_u32(sKb) + (kkey * KS + kdg) * 2;
    const uint32_t sVfa = smem_u32(sVf) + (vd * VS + vkg) * 2;
    const uint32_t KBUF = 32 * KS * 2, VBUF = 64 * VS * 2;

    uint32_t qf[4][4];
    {
        const size_t r0 = (size_t)(b * TSEQ + qb + qr) * DMODEL + h * DHEAD;
        const size_t r1 = r0 + (size_t)8 * DMODEL;
        #pragma unroll
        for (int kc = 0; kc < 4; kc++) {
            const int cc = kc * 16 + 2 * qc;
            qf[kc][0] = U32(g_qs + r0 + cc);     qf[kc][1] = U32(g_qs + r1 + cc);
            qf[kc][2] = U32(g_qs + r0 + cc + 8); qf[kc][3] = U32(g_qs + r1 + cc + 8);
        }
    }

    float o[8][4];
    #pragma unroll
    for (int nd = 0; nd < 8; nd++)
        #pragma unroll
        for (int e = 0; e < 4; e++) o[nd][e] = 0.f;
    float m0 = -1e30f, m1 = -1e30f, l0 = 0.f, l1 = 0.f;

    CP16(sKa, gK);
    CP16(sVfa, gVf);
    CPCOMMIT();

    int buf = 0;
    for (int kt = 0; kt < TSEQ; kt += 32) {
        CPWAIT0();
        __syncthreads();
        if (kt + 32 < TSEQ) {
            const int nb = buf ^ 1;
            CP16(sKa + nb * KBUF, gK + (kt + 32) * DMODEL);
            CP16(sVfa + nb * VBUF, gVf + kt + 32);
            CPCOMMIT();
        }
        const __half* Kb = sKb[buf];
        const __half* Vf = sVf[buf];

        float s[4][4];
        #pragma unroll
        for (int nt = 0; nt < 4; nt++) {
            #pragma unroll
            for (int e = 0; e < 4; e++) s[nt][e] = 0.f;
            #pragma unroll
            for (int kc = 0; kc < 4; kc++) {
                const int off = (nt * 8 + qr) * KS + kc * 16 + 2 * qc;
                uint32_t b0 = U32(Kb + off), b1 = U32(Kb + off + 8);
                MMA_F16(s[nt], qf[kc][0], qf[kc][1], qf[kc][2], qf[kc][3], b0, b1);
            }
        }

        float t0 = -1e30f, t1 = -1e30f;
        #pragma unroll
        for (int nt = 0; nt < 4; nt++) {
            t0 = fmaxf(t0, fmaxf(s[nt][0], s[nt][1]));
            t1 = fmaxf(t1, fmaxf(s[nt][2], s[nt][3]));
        }
        t0 = fmaxf(t0, __shfl_xor_sync(0xffffffffu, t0, 1));
        t0 = fmaxf(t0, __shfl_xor_sync(0xffffffffu, t0, 2));
        t1 = fmaxf(t1, __shfl_xor_sync(0xffffffffu, t1, 1));
        t1 = fmaxf(t1, __shfl_xor_sync(0xffffffffu, t1, 2));
        float mn0 = fmaxf(m0, t0), mn1 = fmaxf(m1, t1);
        float corr0 = __expf(m0 - mn0), corr1 = __expf(m1 - mn1);
        float sum0 = 0.f, sum1 = 0.f;
        #pragma unroll
        for (int nt = 0; nt < 4; nt++) {
            s[nt][0] = __expf(s[nt][0] - mn0);
            s[nt][1] = __expf(s[nt][1] - mn0);
            s[nt][2] = __expf(s[nt][2] - mn1);
            s[nt][3] = __expf(s[nt][3] - mn1);
            sum0 += s[nt][0] + s[nt][1];
            sum1 += s[nt][2] + s[nt][3];
        }
        sum0 += __shfl_xor_sync(0xffffffffu, sum0, 1);
        sum0 += __shfl_xor_sync(0xffffffffu, sum0, 2);
        sum1 += __shfl_xor_sync(0xffffffffu, sum1, 1);
        sum1 += __shfl_xor_sync(0xffffffffu, sum1, 2);
        l0 = l0 * corr0 + sum0;
        l1 = l1 * corr1 + sum1;
        m0 = mn0; m1 = mn1;
        #pragma unroll
        for (int nd = 0; nd < 8; nd++) {
            o[nd][0] *= corr0; o[nd][1] *= corr0;
            o[nd][2] *= corr1; o[nd][3] *= corr1;
        }

        #pragma unroll
        for (int kc = 0; kc < 2; kc++) {
            uint32_t a0 = pack2h(s[2*kc][0],     s[2*kc][1]);
            uint32_t a1 = pack2h(s[2*kc][2],     s[2*kc][3]);
            uint32_t a2 = pack2h(s[2*kc + 1][0], s[2*kc + 1][1]);
            uint32_t a3 = pack2h(s[2*kc + 1][2], s[2*kc + 1][3]);
            const int k0 = kc * 16 + 2 * qc;
            #pragma unroll
            for (int nd = 0; nd < 8; nd++) {
                const int off = (nd * 8 + qr) * VS + k0;
                uint32_t bh0 = U32(Vf + off), bh1 = U32(Vf + off + 8);
                MMA_F16(o[nd], a0, a1, a2, a3, bh0, bh1);
            }
        }
        buf ^= 1;
    }

    // ---- epilogue: normalize, gate -> final GEMM single-fp16 A operand ----
    const float inv0 = 1.f / l0, inv1 = 1.f / l1;
    const size_t r0 = (size_t)(b * TSEQ + qb + qr) * DMODEL + h * DHEAD;
    const size_t r1 = r0 + (size_t)8 * DMODEL;
    #pragma unroll
    for (int nd = 0; nd < 8; nd++) {
        const int cc = nd * 8 + 2 * qc;
        float2 gt0 = *(const float2*)(g_gate + r0 + cc);
        float2 gt1 = *(const float2*)(g_gate + r1 + cc);
        *(uint32_t*)(g_ah[0] + r0 + cc) =
            pack2h(o[nd][0] * inv0 * gt0.x, o[nd][1] * inv0 * gt0.y);
        *(uint32_t*)(g_ah[0] + r1 + cc) =
            pack2h(o[nd][2] * inv1 * gt1.x, o[nd][3] * inv1 * gt1.y);
    }
}

// ---------------- launch (only harness pointers cross the boundary) ----------
extern "C" void kernel_launch(void* const* d_in, const int* in_sizes, int n_in,
                              void* d_out, int out_size)
{
    const float* x   = (const float*)d_in[0];
    const int*   tok = (const int*)  d_in[1];
    const float* Wr  = (const float*)d_in[2];
    const float* Wk  = (const float*)d_in[3];
    const float* Wv  = (const float*)d_in[4];
    const float* Wo  = (const float*)d_in[5];
    const float* bo  = (const float*)d_in[6];
    const float* tmk = (const float*)d_in[7];
    const float* tmv = (const float*)d_in[8];
    const float* tmr = (const float*)d_in[9];
    float* out = (float*)d_out;

    zero_cnt_kernel<<<(VOCAB + 255) / 256, 256>>>();
    hist_kernel<<<BT / 256, 256>>>(tok);
    topk_gains_kernel<<<1, 256>>>(tmr, tmk, tmv);

    split_w_all<<<(DMODEL * DMODEL) / 256, 256>>>(Wr, Wk, Wv, Wo);
    prep_x012<<<(BT * DMODEL) / 256, 256>>>(x);

    gemm_1t<<<dim3(DMODEL / 128, BT / 128, 2), 256>>>(0, 2, nullptr, nullptr);  // r, v
    gemm_3t<<<dim3(DMODEL / 128, BT / 128), 256>>>();                           // k (spike)

    attn_f16<<<dim3(TSEQ / 128, NHEAD, BATCH), 256>>>();

    gemm_1t<<<dim3(DMODEL / 128, BT / 128, 1), 256>>>(3, 3, bo, out);           // output
}

// round 13
// speedup vs baseline: 5.2980x; 1.0567x over previous
#include <cuda_runtime.h>
#include <cuda_fp16.h>
#include <cstdint>
#include <math.h>

#define BATCH  2
#define TSEQ   2048
#define BT     (BATCH*TSEQ)   // 4096
#define DMODEL 1024
#define NHEAD  16
#define DHEAD  64
#define VOCAB  32000

// ---------------- scratch (device globals; referenced ONLY from device code) ----
__device__ __align__(16) int   g_cnt[VOCAB];
__device__ __align__(16) float g_m[3][DMODEL];
__device__ __align__(16) float g_gate[BT*DMODEL];                       // sigmoid(r)
__device__ __align__(16) __half g_ah[3][BT*DMODEL];                     // A hi (mode3 reuses [0])
__device__ __align__(16) __half g_al1[BT*DMODEL];                       // A lo (k-GEMM only)
__device__ __align__(16) __half g_wh[4][DMODEL*DMODEL];                 // W hi (all 4)
__device__ __align__(16) __half g_wl[DMODEL*DMODEL];                    // W lo (k-GEMM only)
__device__ __align__(16) __half g_qs[BT*DMODEL];                        // q*0.125 (fp16)
__device__ __align__(16) __half g_kb[BT*DMODEL];                        // k (binary)
__device__ __align__(16) __half g_vf[BATCH*NHEAD*DHEAD*TSEQ];           // V^T (single fp16)

// ---------------- helpers ----------------
__device__ __forceinline__ void h_split(float x, __half& h, __half& l) {
    h = __float2half_rn(x);
    l = __float2half_rn(x - __half2float(h));
}
__device__ __forceinline__ uint32_t pack2h(float x, float y) {
    __half2 hh = __floats2half2_rn(x, y);
    return *(uint32_t*)&hh;
}
__device__ __forceinline__ uint32_t smem_u32(const void* p) {
    uint32_t a;
    asm("{ .reg .u64 t; cvta.to.shared.u64 t, %1; cvt.u32.u64 %0, t; }" : "=r"(a) : "l"(p));
    return a;
}
// exp(s - 4) = 2^(s*log2e - 4*log2e); single FMA feeding EX2
__device__ __forceinline__ float exps4(float s) {
    return exp2f(fmaf(s, 1.44269504f, -5.77078016f));
}
#define U32(p) (*reinterpret_cast<const uint32_t*>(p))
#define CP16(dst, src) asm volatile("cp.async.cg.shared.global [%0], [%1], 16;" :: "r"(dst), "l"(src))
#define CPCOMMIT()     asm volatile("cp.async.commit_group;")
#define CPWAIT0()      asm volatile("cp.async.wait_group 0;")

#define MMA_F16(c, a0, a1, a2, a3, b0, b1)                                      \
    asm volatile(                                                               \
        "mma.sync.aligned.m16n8k16.row.col.f32.f16.f16.f32 "                    \
        "{%0,%1,%2,%3}, {%4,%5,%6,%7}, {%8,%9}, {%0,%1,%2,%3};"                 \
        : "+f"((c)[0]), "+f"((c)[1]), "+f"((c)[2]), "+f"((c)[3])                \
        : "r"(a0), "r"(a1), "r"(a2), "r"(a3), "r"(b0), "r"(b1))

// ---------------- kWTA: histogram + top-5 + gains ----------------
__global__ void zero_cnt_kernel() {
    int i = blockIdx.x * blockDim.x + threadIdx.x;
    if (i < VOCAB) g_cnt[i] = 0;
}
__global__ void hist_kernel(const int* __restrict__ tok) {
    int i = blockIdx.x * blockDim.x + threadIdx.x;
    atomicAdd(&g_cnt[tok[i]], 1);
}
__global__ void topk_gains_kernel(const float* __restrict__ tmr,
                                  const float* __restrict__ tmk,
                                  const float* __restrict__ tmv) {
    __shared__ long long skey[256];
    __shared__ int sel[5];
    int tid = threadIdx.x;
    for (int it = 0; it < 5; it++) {
        long long best = -1;
        for (int i = tid; i < VOCAB; i += 256) {
            bool ex = false;
            for (int j = 0; j < it; j++) if (sel[j] == i) ex = true;
            if (ex) continue;
            long long key = (((long long)g_cnt[i]) << 16) | (long long)(VOCAB - 1 - i);
            if (key > best) best = key;
        }
        skey[tid] = best;
        __syncthreads();
        for (int s = 128; s > 0; s >>= 1) {
            if (tid < s && skey[tid + s] > skey[tid]) skey[tid] = skey[tid + s];
            __syncthreads();
        }
        if (tid == 0) sel[it] = VOCAB - 1 - (int)(skey[0] & 0xFFFFLL);
        __syncthreads();
    }
    for (int d = tid; d < DMODEL; d += 256) {
        float g = (g_cnt[d] > 0) ? 0.6f : 1.0f;
        #pragma unroll
        for (int j = 0; j < 5; j++) if (sel[j] == d) g = 1.5f;
        g_m[0][d] = tmr[d] * g;
        g_m[1][d] = tmk[d] * g;
        g_m[2][d] = tmv[d] * g;
    }
}

// ---------------- prep: W hi x4; W lo only for Wk ----------------
__global__ void split_w_all(const float* __restrict__ W0, const float* __restrict__ W1,
                            const float* __restrict__ W2, const float* __restrict__ W3) {
    int i = blockIdx.x * 256 + threadIdx.x;
    const float* Ws[4] = {W0, W1, W2, W3};
    #pragma unroll
    for (int m = 0; m < 4; m++) {
        __half h, l;
        h_split(Ws[m][i], h, l);
        g_wh[m][i] = h;
        if (m == 1) g_wl[i] = l;
    }
}

// ---------------- prep: 3 mixed inputs (A-lo only for k path) ----------------
__global__ void prep_x012(const float* __restrict__ X) {
    int i = blockIdx.x * 256 + threadIdx.x;
    int t = i >> 10, d = i & (DMODEL - 1);
    float xv = X[i];
    float pv = ((t & (TSEQ - 1)) != 0) ? X[i - DMODEL] : 0.f;
    #pragma unroll
    for (int m = 0; m < 3; m++) {
        float mm = g_m[m][d];
        float a = mm * xv + (1.f - mm) * pv;
        __half h, l;
        h_split(a, h, l);
        g_ah[m][i] = h;
        if (m == 1) g_al1[i] = l;
    }
}

// ================= 1-term fp16 GEMM (modes 0/2/3), K-chunk 32 ==================
#define CH1  32
#define SB1  40
#define STG1 (128 * SB1 * 2)
__global__ __launch_bounds__(256)
void gemm_1t(int modeA, int modeB, const float* __restrict__ bias, float* __restrict__ Cout)
{
    const int mode = blockIdx.z ? modeB : modeA;
    const __half* __restrict__ Ah = g_ah[mode == 3 ? 0 : mode];
    const __half* __restrict__ Wh = g_wh[mode];

    __shared__ __align__(16) __half sAh[2][128 * SB1], sWh[2][128 * SB1];

    const int tid  = threadIdx.x;
    const int wid  = tid >> 5, lane = tid & 31;
    const int wr   = wid & 1,  wc   = wid >> 1;
    const int qrow = lane >> 2, qc = lane & 3;
    const int bm = blockIdx.y * 128, bn = blockIdx.x * 128;
    const int lr = tid >> 1, cg = (tid & 1) * 16;

    const __half* pAh = Ah + (size_t)(bm + lr) * DMODEL + cg;
    const __half* pWh = Wh + (size_t)(bn + lr) * DMODEL + cg;
    const uint32_t dAh = smem_u32(sAh) + (lr * SB1 + cg) * 2;
    const uint32_t dWh = smem_u32(sWh) + (lr * SB1 + cg) * 2;

    float acc[4][4][4];
    #pragma unroll
    for (int mi = 0; mi < 4; mi++)
        #pragma unroll
        for (int ni = 0; ni < 4; ni++)
            #pragma unroll
            for (int e = 0; e < 4; e++) acc[mi][ni][e] = 0.f;

    CP16(dAh, pAh); CP16(dAh + 16, pAh + 8);
    CP16(dWh, pWh); CP16(dWh + 16, pWh + 8);
    CPCOMMIT();

    for (int c = 0; c < DMODEL / CH1; c++) {
        CPWAIT0();
        __syncthreads();
        if (c + 1 < DMODEL / CH1) {
            const uint32_t so = ((c + 1) & 1) * STG1;
            const int go = (c + 1) * CH1;
            CP16(dAh + so, pAh + go); CP16(dAh + so + 16, pAh + go + 8);
            CP16(dWh + so, pWh + go); CP16(dWh + so + 16, pWh + go + 8);
            CPCOMMIT();
        }
        const __half* cAh = sAh[c & 1];
        const __half* cWh = sWh[c & 1];

        #pragma unroll
        for (int ks = 0; ks < 2; ks++) {
            const int k0 = ks * 16 + 2 * qc;
            uint32_t bh[4][2];
            #pragma unroll
            for (int ni = 0; ni < 4; ni++) {
                const int off = (wc * 32 + ni * 8 + qrow) * SB1 + k0;
                bh[ni][0] = U32(cWh + off); bh[ni][1] = U32(cWh + off + 8);
            }
            #pragma unroll
            for (int mi = 0; mi < 4; mi++) {
                const int off = (wr * 64 + mi * 16 + qrow) * SB1 + k0;
                uint32_t a0 = U32(cAh + off),     a1 = U32(cAh + off + 8 * SB1);
                uint32_t a2 = U32(cAh + off + 8), a3 = U32(cAh + off + 8 * SB1 + 8);
                #pragma unroll
                for (int ni = 0; ni < 4; ni++)
                    MMA_F16(acc[mi][ni], a0, a1, a2, a3, bh[ni][0], bh[ni][1]);
            }
        }
    }

    #pragma unroll
    for (int mi = 0; mi < 4; mi++) {
        const int row0 = bm + wr * 64 + mi * 16 + qrow;
        #pragma unroll
        for (int ni = 0; ni < 4; ni++) {
            const int col = bn + wc * 32 + ni * 8 + 2 * qc;
            float d0 = acc[mi][ni][0], d1 = acc[mi][ni][1];
            float d2 = acc[mi][ni][2], d3 = acc[mi][ni][3];
            if (mode == 0) {
                *(float2*)(g_gate + (size_t)row0 * DMODEL + col) =
                    make_float2(1.f / (1.f + __expf(-d0)), 1.f / (1.f + __expf(-d1)));
                *(float2*)(g_gate + (size_t)(row0 + 8) * DMODEL + col) =
                    make_float2(1.f / (1.f + __expf(-d2)), 1.f / (1.f + __expf(-d3)));
                *(uint32_t*)(g_qs + (size_t)row0 * DMODEL + col)       = pack2h(d0 * 0.125f, d1 * 0.125f);
                *(uint32_t*)(g_qs + (size_t)(row0 + 8) * DMODEL + col) = pack2h(d2 * 0.125f, d3 * 0.125f);
            } else if (mode == 2) {
                const int b  = row0 >> 11, tl = row0 & (TSEQ - 1);
                const int hh = col >> 6,  dd = col & (DHEAD - 1);
                const size_t base = ((size_t)(b * NHEAD + hh)) * DHEAD;
                g_vf[(base + dd) * TSEQ + tl]         = __float2half(d0);
                g_vf[(base + dd + 1) * TSEQ + tl]     = __float2half(d1);
                g_vf[(base + dd) * TSEQ + tl + 8]     = __float2half(d2);
                g_vf[(base + dd + 1) * TSEQ + tl + 8] = __float2half(d3);
            } else {
                float b0 = bias[col], b1 = bias[col + 1];
                *(float2*)(Cout + (size_t)row0 * DMODEL + col)       = make_float2(d0 + b0, d1 + b1);
                *(float2*)(Cout + (size_t)(row0 + 8) * DMODEL + col) = make_float2(d2 + b0, d3 + b1);
            }
        }
    }
}

// ================= 3-term fp16 GEMM (mode 1: k, spike epilogue) ================
#define CH3  16
#define SB3  24
#define STG3 (128 * SB3 * 2)
__global__ __launch_bounds__(256)
void gemm_3t()
{
    const __half* __restrict__ Ah = g_ah[1];
    const __half* __restrict__ Al = g_al1;
    const __half* __restrict__ Wh = g_wh[1];
    const __half* __restrict__ Wl = g_wl;

    __shared__ __align__(16) __half sAh[2][128 * SB3], sAl[2][128 * SB3];
    __shared__ __align__(16) __half sWh[2][128 * SB3], sWl[2][128 * SB3];

    const int tid  = threadIdx.x;
    const int wid  = tid >> 5, lane = tid & 31;
    const int wr   = wid & 1,  wc   = wid >> 1;
    const int qrow = lane >> 2, qc = lane & 3;
    const int bm = blockIdx.y * 128, bn = blockIdx.x * 128;
    const int lr = tid >> 1, cg = (tid & 1) * 8;

    const __half* pAh = Ah + (size_t)(bm + lr) * DMODEL + cg;
    const __half* pAl = Al + (size_t)(bm + lr) * DMODEL + cg;
    const __half* pWh = Wh + (size_t)(bn + lr) * DMODEL + cg;
    const __half* pWl = Wl + (size_t)(bn + lr) * DMODEL + cg;
    const uint32_t dAh = smem_u32(sAh) + (lr * SB3 + cg) * 2;
    const uint32_t dAl = smem_u32(sAl) + (lr * SB3 + cg) * 2;
    const uint32_t dWh = smem_u32(sWh) + (lr * SB3 + cg) * 2;
    const uint32_t dWl = smem_u32(sWl) + (lr * SB3 + cg) * 2;

    float acc[4][4][4];
    #pragma unroll
    for (int mi = 0; mi < 4; mi++)
        #pragma unroll
        for (int ni = 0; ni < 4; ni++)
            #pragma unroll
            for (int e = 0; e < 4; e++) acc[mi][ni][e] = 0.f;

    CP16(dAh, pAh); CP16(dAl, pAl); CP16(dWh, pWh); CP16(dWl, pWl);
    CPCOMMIT();

    for (int c = 0; c < DMODEL / CH3; c++) {
        CPWAIT0();
        __syncthreads();
        if (c + 1 < DMODEL / CH3) {
            const uint32_t so = ((c + 1) & 1) * STG3;
            const int go = (c + 1) * CH3;
            CP16(dAh + so, pAh + go); CP16(dAl + so, pAl + go);
            CP16(dWh + so, pWh + go); CP16(dWl + so, pWl + go);
            CPCOMMIT();
        }
        const __half* cAh = sAh[c & 1];
        const __half* cAl = sAl[c & 1];
        const __half* cWh = sWh[c & 1];
        const __half* cWl = sWl[c & 1];

        const int k0 = 2 * qc;
        uint32_t bh[4][2], bl[4][2];
        #pragma unroll
        for (int ni = 0; ni < 4; ni++) {
            const int off = (wc * 32 + ni * 8 + qrow) * SB3 + k0;
            bh[ni][0] = U32(cWh + off); bh[ni][1] = U32(cWh + off + 8);
            bl[ni][0] = U32(cWl + off); bl[ni][1] = U32(cWl + off + 8);
        }
        #pragma unroll
        for (int mi = 0; mi < 4; mi++) {
            const int off = (wr * 64 + mi * 16 + qrow) * SB3 + k0;
            uint32_t ah0 = U32(cAh + off),     ah1 = U32(cAh + off + 8 * SB3);
            uint32_t ah2 = U32(cAh + off + 8), ah3 = U32(cAh + off + 8 * SB3 + 8);
            uint32_t al0 = U32(cAl + off),     al1 = U32(cAl + off + 8 * SB3);
            uint32_t al2 = U32(cAl + off + 8), al3 = U32(cAl + off + 8 * SB3 + 8);
            #pragma unroll
            for (int ni = 0; ni < 4; ni++) {
                MMA_F16(acc[mi][ni], al0, al1, al2, al3, bh[ni][0], bh[ni][1]);
                MMA_F16(acc[mi][ni], ah0, ah1, ah2, ah3, bl[ni][0], bl[ni][1]);
                MMA_F16(acc[mi][ni], ah0, ah1, ah2, ah3, bh[ni][0], bh[ni][1]);
            }
        }
    }

    #pragma unroll
    for (int mi = 0; mi < 4; mi++) {
        const int row0 = bm + wr * 64 + mi * 16 + qrow;
        #pragma unroll
        for (int ni = 0; ni < 4; ni++) {
            const int col = bn + wc * 32 + ni * 8 + 2 * qc;
            float d0 = acc[mi][ni][0], d1 = acc[mi][ni][1];
            float d2 = acc[mi][ni][2], d3 = acc[mi][ni][3];
            __half2 s;
            s.x = __float2half((d0 > 0.5f) ? 1.f : 0.f);
            s.y = __float2half((d1 > 0.5f) ? 1.f : 0.f);
            *(__half2*)(g_kb + (size_t)row0 * DMODEL + col) = s;
            s.x = __float2half((d2 > 0.5f) ? 1.f : 0.f);
            s.y = __float2half((d3 > 0.5f) ? 1.f : 0.f);
            *(__half2*)(g_kb + (size_t)(row0 + 8) * DMODEL + col) = s;
        }
    }
}

// ---------------- flash attention: NO online softmax (bounded scores) ----------
// p = exp(s - 4) accumulated directly; l reduced once after the loop.
// 256 thr / 8 warps, 128 q rows/block, one (b,h), 32-key tiles, cp.async x2.
#define KS 72
#define VS 40
__global__ __launch_bounds__(256)
void attn_f16()
{
    __shared__ __align__(16) __half sKb[2][32 * KS];
    __shared__ __align__(16) __half sVf[2][64 * VS];

    const int tid = threadIdx.x, warp = tid >> 5, lane = tid & 31;
    const int qr = lane >> 2, qc = lane & 3;
    const int b = blockIdx.z, h = blockIdx.y;
    const int qb = blockIdx.x * 128 + warp * 16;

    const int kkey = tid >> 3, kdg = (tid & 7) * 8;
    const int vd = tid >> 2,   vkg = (tid & 3) * 8;
    const size_t vbase = ((size_t)(b * NHEAD + h)) * DHEAD * TSEQ;
    const __half* gK  = g_kb + (size_t)(b * TSEQ + kkey) * DMODEL + h * DHEAD + kdg;
    const __half* gVf = g_vf + vbase + (size_t)vd * TSEQ + vkg;
    const uint32_t sKa  = smem_u32(sKb) + (kkey * KS + kdg) * 2;
    const uint32_t sVfa = smem_u32(sVf) + (vd * VS + vkg) * 2;
    const uint32_t KBUF = 32 * KS * 2, VBUF = 64 * VS * 2;

    uint32_t qf[4][4];
    {
        const size_t r0 = (size_t)(b * TSEQ + qb + qr) * DMODEL + h * DHEAD;
        const size_t r1 = r0 + (size_t)8 * DMODEL;
        #pragma unroll
        for (int kc = 0; kc < 4; kc++) {
            const int cc = kc * 16 + 2 * qc;
            qf[kc][0] = U32(g_qs + r0 + cc);     qf[kc][1] = U32(g_qs + r1 + cc);
            qf[kc][2] = U32(g_qs + r0 + cc + 8); qf[kc][3] = U32(g_qs + r1 + cc + 8);
        }
    }

    float o[8][4];
    #pragma unroll
    for (int nd = 0; nd < 8; nd++)
        #pragma unroll
        for (int e = 0; e < 4; e++) o[nd][e] = 0.f;
    float l0 = 0.f, l1 = 0.f;      // per-thread partial row sums

    CP16(sKa, gK);
    CP16(sVfa, gVf);
    CPCOMMIT();

    int buf = 0;
    for (int kt = 0; kt < TSEQ; kt += 32) {
        CPWAIT0();
        __syncthreads();
        if (kt + 32 < TSEQ) {
            const int nb = buf ^ 1;
            CP16(sKa + nb * KBUF, gK + (kt + 32) * DMODEL);
            CP16(sVfa + nb * VBUF, gVf + kt + 32);
            CPCOMMIT();
        }
        const __half* Kb = sKb[buf];
        const __half* Vf = sVf[buf];

        // ---- S = Q K^T (q pre-scaled; k binary) ----
        float s[4][4];
        #pragma unroll
        for (int nt = 0; nt < 4; nt++) {
            #pragma unroll
            for (int e = 0; e < 4; e++) s[nt][e] = 0.f;
            #pragma unroll
            for (int kc = 0; kc < 4; kc++) {
                const int off = (nt * 8 + qr) * KS + kc * 16 + 2 * qc;
                uint32_t b0 = U32(Kb + off), b1 = U32(Kb + off + 8);
                MMA_F16(s[nt], qf[kc][0], qf[kc][1], qf[kc][2], qf[kc][3], b0, b1);
            }
        }

        // ---- p = exp(s - 4); accumulate row sums (no max, no rescale) ----
        #pragma unroll
        for (int nt = 0; nt < 4; nt++) {
            s[nt][0] = exps4(s[nt][0]);
            s[nt][1] = exps4(s[nt][1]);
            s[nt][2] = exps4(s[nt][2]);
            s[nt][3] = exps4(s[nt][3]);
            l0 += s[nt][0] + s[nt][1];
            l1 += s[nt][2] + s[nt][3];
        }

        // ---- O += P V (single-fp16 P) ----
        #pragma unroll
        for (int kc = 0; kc < 2; kc++) {
            uint32_t a0 = pack2h(s[2*kc][0],     s[2*kc][1]);
            uint32_t a1 = pack2h(s[2*kc][2],     s[2*kc][3]);
            uint32_t a2 = pack2h(s[2*kc + 1][0], s[2*kc + 1][1]);
            uint32_t a3 = pack2h(s[2*kc + 1][2], s[2*kc + 1][3]);
            const int k0 = kc * 16 + 2 * qc;
            #pragma unroll
            for (int nd = 0; nd < 8; nd++) {
                const int off = (nd * 8 + qr) * VS + k0;
                uint32_t bh0 = U32(Vf + off), bh1 = U32(Vf + off + 8);
                MMA_F16(o[nd], a0, a1, a2, a3, bh0, bh1);
            }
        }
        buf ^= 1;
    }

    // ---- one reduction across the quad (lanes sharing a row) ----
    l0 += __shfl_xor_sync(0xffffffffu, l0, 1);
    l0 += __shfl_xor_sync(0xffffffffu, l0, 2);
    l1 += __shfl_xor_sync(0xffffffffu, l1, 1);
    l1 += __shfl_xor_sync(0xffffffffu, l1, 2);

    // ---- epilogue: normalize, gate -> final GEMM single-fp16 A operand ----
    const float inv0 = 1.f / l0, inv1 = 1.f / l1;
    const size_t r0 = (size_t)(b * TSEQ + qb + qr) * DMODEL + h * DHEAD;
    const size_t r1 = r0 + (size_t)8 * DMODEL;
    #pragma unroll
    for (int nd = 0; nd < 8; nd++) {
        const int cc = nd * 8 + 2 * qc;
        float2 gt0 = *(const float2*)(g_gate + r0 + cc);
        float2 gt1 = *(const float2*)(g_gate + r1 + cc);
        *(uint32_t*)(g_ah[0] + r0 + cc) =
            pack2h(o[nd][0] * inv0 * gt0.x, o[nd][1] * inv0 * gt0.y);
        *(uint32_t*)(g_ah[0] + r1 + cc) =
            pack2h(o[nd][2] * inv1 * gt1.x, o[nd][3] * inv1 * gt1.y);
    }
}

// ---------------- launch (only harness pointers cross the boundary) ----------
extern "C" void kernel_launch(void* const* d_in, const int* in_sizes, int n_in,
                              void* d_out, int out_size)
{
    const float* x   = (const float*)d_in[0];
    const int*   tok = (const int*)  d_in[1];
    const float* Wr  = (const float*)d_in[2];
    const float* Wk  = (const float*)d_in[3];
    const float* Wv  = (const float*)d_in[4];
    const float* Wo  = (const float*)d_in[5];
    const float* bo  = (const float*)d_in[6];
    const float* tmk = (const float*)d_in[7];
    const float* tmv = (const float*)d_in[8];
    const float* tmr = (const float*)d_in[9];
    float* out = (float*)d_out;

    zero_cnt_kernel<<<(VOCAB + 255) / 256, 256>>>();
    hist_kernel<<<BT / 256, 256>>>(tok);
    topk_gains_kernel<<<1, 256>>>(tmr, tmk, tmv);

    split_w_all<<<(DMODEL * DMODEL) / 256, 256>>>(Wr, Wk, Wv, Wo);
    prep_x012<<<(BT * DMODEL) / 256, 256>>>(x);

    gemm_1t<<<dim3(DMODEL / 128, BT / 128, 2), 256>>>(0, 2, nullptr, nullptr);  // r, v
    gemm_3t<<<dim3(DMODEL / 128, BT / 128), 256>>>();                           // k (spike)

    attn_f16<<<dim3(TSEQ / 128, NHEAD, BATCH), 256>>>();

    gemm_1t<<<dim3(DMODEL / 128, BT / 128, 1), 256>>>(3, 3, bo, out);           // output
}